// round 1
// baseline (speedup 1.0000x reference)
#include <cuda_runtime.h>
#include <cuda_bf16.h>
#include <math.h>

// ---------------- problem dims ----------------
#define T    2048
#define XD   2048
#define QD   256     // X_D / REDUCE
#define MN   64      // M_N
#define MD   256     // M_D
#define DCD  64      // DECAY_D
#define FFD  2816    // FF_D
#define CH   64      // CHUNK

// ---------------- scratch (device globals; allocation-free) ----------------
__device__ float B_xn  [(size_t)T*XD];
__device__ float B_q   [(size_t)T*QD];
__device__ float B_k   [(size_t)T*QD];
__device__ float B_qhi [(size_t)T*QD];
__device__ float B_klo [(size_t)T*QD];
__device__ float B_khi [(size_t)T*QD];
__device__ float B_v   [(size_t)T*XD];
__device__ float B_A   [(size_t)T*2*CH];
__device__ float B_y   [(size_t)T*XD];
__device__ float B_gate[(size_t)T*XD];
__device__ float B_acc [(size_t)T*XD];
__device__ float B_memF[(size_t)T*MN];
__device__ float B_memV[(size_t)T*MD];
__device__ float B_memQ[(size_t)T*MD];
__device__ float B_gam [(size_t)MN*MD];
__device__ float B_bg  [(size_t)MN*MD];
__device__ float B_wkT [(size_t)MD*MD];
__device__ float B_qk2 [(size_t)T*MD];
__device__ float B_lq  [(size_t)T*MN];
__device__ float B_mems[(size_t)T*MN*MD];   // 134 MB
__device__ float B_memY[(size_t)T*MD];
__device__ float B_x1  [(size_t)T*XD];
__device__ float B_x2n [(size_t)T*XD];
__device__ float B_h1  [(size_t)T*FFD];
__device__ float B_h2  [(size_t)T*FFD];

__device__ __forceinline__ float sigf(float x) { return 1.f / (1.f + expf(-x)); }

// ---------------- generic GEMM: C[M,N] = A[M,K] @ B[N,K]^T ----------------
#define BM 128
#define BN 128
#define BKK 16

enum { EPI_NONE = 0, EPI_SIGMOID, EPI_GATE, EPI_GATE_ADD2, EPI_SILU_MUL, EPI_ADD };

template <int EPI>
__global__ __launch_bounds__(256) void gemm_tn(
    const float* __restrict__ A, const float* __restrict__ B, float* __restrict__ D,
    const float* __restrict__ G, const float* __restrict__ R1, const float* __restrict__ R2,
    int M, int N, int K)
{
    __shared__ float As[BKK][BM + 4];
    __shared__ float Bs[BKK][BN + 4];

    const int tid = threadIdx.x;
    const int m0 = blockIdx.y * BM;
    const int n0 = blockIdx.x * BN;
    const int tx = tid & 15;       // 0..15 -> 8 cols each
    const int ty = tid >> 4;       // 0..15 -> 8 rows each

    float acc[8][8];
#pragma unroll
    for (int i = 0; i < 8; i++)
#pragma unroll
        for (int j = 0; j < 8; j++) acc[i][j] = 0.f;

    for (int k0 = 0; k0 < K; k0 += BKK) {
        // load A tile: 128 rows x 16 k  (512 float4, 2 per thread)
#pragma unroll
        for (int l = 0; l < 2; l++) {
            int qi  = tid + l * 256;
            int row = qi >> 2;
            int kk  = (qi & 3) * 4;
            float4 av = *(const float4*)&A[(size_t)(m0 + row) * K + k0 + kk];
            As[kk + 0][row] = av.x; As[kk + 1][row] = av.y;
            As[kk + 2][row] = av.z; As[kk + 3][row] = av.w;
        }
        // load B tile: 128 rows (N-dim) x 16 k, guarded on N
#pragma unroll
        for (int l = 0; l < 2; l++) {
            int qi  = tid + l * 256;
            int row = qi >> 2;
            int kk  = (qi & 3) * 4;
            float4 bv = make_float4(0.f, 0.f, 0.f, 0.f);
            if (n0 + row < N) bv = *(const float4*)&B[(size_t)(n0 + row) * K + k0 + kk];
            Bs[kk + 0][row] = bv.x; Bs[kk + 1][row] = bv.y;
            Bs[kk + 2][row] = bv.z; Bs[kk + 3][row] = bv.w;
        }
        __syncthreads();

#pragma unroll
        for (int kk = 0; kk < BKK; kk++) {
            float a[8], b[8];
#pragma unroll
            for (int i = 0; i < 8; i++) a[i] = As[kk][ty * 8 + i];
#pragma unroll
            for (int j = 0; j < 8; j++) b[j] = Bs[kk][tx * 8 + j];
#pragma unroll
            for (int i = 0; i < 8; i++)
#pragma unroll
                for (int j = 0; j < 8; j++) acc[i][j] += a[i] * b[j];
        }
        __syncthreads();
    }

#pragma unroll
    for (int i = 0; i < 8; i++) {
        int row = m0 + ty * 8 + i;
#pragma unroll
        for (int j = 0; j < 8; j++) {
            int col = n0 + tx * 8 + j;
            if (col < N) {
                size_t idx = (size_t)row * N + col;
                float c = acc[i][j];
                if (EPI == EPI_SIGMOID)      c = sigf(c);
                else if (EPI == EPI_GATE)    c = c * sigf(G[idx]);
                else if (EPI == EPI_GATE_ADD2) c = c * sigf(G[idx]) + R1[idx] + R2[idx];
                else if (EPI == EPI_SILU_MUL) { float g = G[idx]; c = c * (g * sigf(g)); }
                else if (EPI == EPI_ADD)     c = c + R1[idx];
                D[idx] = c;
            }
        }
    }
}

// ---------------- scale_norm: o = x * g / (||x||_2 + 1e-8), row-wise over 2048 ----------------
__global__ __launch_bounds__(256) void scale_norm_k(
    const float* __restrict__ x, float* __restrict__ o, const float* __restrict__ g)
{
    int t = blockIdx.x;
    const float4* xr = (const float4*)(x + (size_t)t * XD);
    float4 v0 = xr[threadIdx.x];
    float4 v1 = xr[threadIdx.x + 256];
    float s = v0.x*v0.x + v0.y*v0.y + v0.z*v0.z + v0.w*v0.w
            + v1.x*v1.x + v1.y*v1.y + v1.z*v1.z + v1.w*v1.w;
    for (int off = 16; off; off >>= 1) s += __shfl_xor_sync(0xffffffffu, s, off);
    __shared__ float red[8];
    int w = threadIdx.x >> 5, lane = threadIdx.x & 31;
    if (lane == 0) red[w] = s;
    __syncthreads();
    float tot = red[0] + red[1] + red[2] + red[3] + red[4] + red[5] + red[6] + red[7];
    float sc = g[0] / (sqrtf(tot) + 1e-8f);
    float4* orow = (float4*)(o + (size_t)t * XD);
    v0.x *= sc; v0.y *= sc; v0.z *= sc; v0.w *= sc;
    v1.x *= sc; v1.y *= sc; v1.z *= sc; v1.w *= sc;
    orow[threadIdx.x] = v0;
    orow[threadIdx.x + 256] = v1;
}

// ---------------- RoPE: qhi (pos=64+r), klo (pos=r), khi (pos=64+r) ----------------
__global__ __launch_bounds__(128) void rope_all(
    const float* __restrict__ q, const float* __restrict__ k,
    float* __restrict__ qhi, float* __restrict__ klo, float* __restrict__ khi)
{
    int t = blockIdx.x, j = threadIdx.x;           // j = pair index 0..127
    int r = t & 63;
    float freq = powf(10000.f, -(float)j / 128.f);
    float slo, clo, shi, chi;
    sincosf((float)r * freq, &slo, &clo);
    sincosf((float)(64 + r) * freq, &shi, &chi);
    size_t base = (size_t)t * QD + 2 * j;
    float qe = q[base], qo = q[base + 1];
    qhi[base]     = qe * chi - qo * shi;
    qhi[base + 1] = qo * chi + qe * shi;
    float ke = k[base], ko = k[base + 1];
    klo[base]     = ke * clo - ko * slo;
    klo[base + 1] = ko * clo + ke * slo;
    khi[base]     = ke * chi - ko * shi;
    khi[base + 1] = ko * chi + ke * shi;
}

// ---------------- attention scores + softmax: A[t, 0..127] ----------------
__global__ __launch_bounds__(256) void attn_score(
    const float* __restrict__ qr, const float* __restrict__ klo,
    const float* __restrict__ khi, float* __restrict__ Aout)
{
    int w = threadIdx.x >> 5, lane = threadIdx.x & 31;
    int t = blockIdx.x * 8 + w;
    int c = t >> 6, r = t & 63;
    float qreg[8];
#pragma unroll
    for (int i = 0; i < 8; i++) qreg[i] = qr[(size_t)t * QD + i * 32 + lane];

    __shared__ float s_s[8][128];
    for (int m = 0; m < 128; m++) {
        float sc;
        if (c == 0 && m < 64) {
            sc = 0.f;   // zero keys from "previous chunk" of chunk 0 (reference keeps them)
        } else {
            const float* kp = (m < 64)
                ? &klo[(size_t)((c - 1) * 64 + m) * QD]
                : &khi[(size_t)(c * 64 + (m - 64)) * QD];
            float d = 0.f;
#pragma unroll
            for (int i = 0; i < 8; i++) d += qreg[i] * kp[i * 32 + lane];
            for (int off = 16; off; off >>= 1) d += __shfl_xor_sync(0xffffffffu, d, off);
            sc = d * (1.f / 16.f);   // / sqrt(256)
        }
        if (m > r + 64) sc = -1e30f; // causal mask
        if (lane == 0) s_s[w][m] = sc;
    }
    __syncwarp();
    float a0 = s_s[w][lane], a1 = s_s[w][lane + 32], a2 = s_s[w][lane + 64], a3 = s_s[w][lane + 96];
    float mx = fmaxf(fmaxf(a0, a1), fmaxf(a2, a3));
    for (int off = 16; off; off >>= 1) mx = fmaxf(mx, __shfl_xor_sync(0xffffffffu, mx, off));
    float e0 = expf(a0 - mx), e1 = expf(a1 - mx), e2 = expf(a2 - mx), e3 = expf(a3 - mx);
    float sm = e0 + e1 + e2 + e3;
    for (int off = 16; off; off >>= 1) sm += __shfl_xor_sync(0xffffffffu, sm, off);
    float inv = 1.f / sm;
    size_t ob = (size_t)t * 128;
    Aout[ob + lane]      = e0 * inv;
    Aout[ob + lane + 32] = e1 * inv;
    Aout[ob + lane + 64] = e2 * inv;
    Aout[ob + lane + 96] = e3 * inv;
}

// ---------------- y = A @ v2 (per chunk), v2 rows = v[(c-1)*64 + m] ----------------
__global__ __launch_bounds__(256) void attn_av(
    const float* __restrict__ Aat, const float* __restrict__ v, float* __restrict__ y)
{
    int c = blockIdx.z, rg = blockIdx.y, ct = blockIdx.x;
    int col = ct * 256 + threadIdx.x;
    __shared__ float As[16][128];
    for (int idx = threadIdx.x; idx < 16 * 128; idx += 256) {
        int rr = idx >> 7, mm = idx & 127;
        As[rr][mm] = Aat[(size_t)(c * 64 + rg * 16 + rr) * 128 + mm];
    }
    __syncthreads();
    float acc[16];
#pragma unroll
    for (int r = 0; r < 16; r++) acc[r] = 0.f;
    int mstart = (c == 0) ? 64 : 0;
    for (int m = mstart; m < 128; m++) {
        float vv = v[(size_t)((c - 1) * 64 + m) * XD + col];
#pragma unroll
        for (int r = 0; r < 16; r++) acc[r] += As[r][m] * vv;
    }
#pragma unroll
    for (int r = 0; r < 16; r++)
        y[(size_t)(c * 64 + rg * 16 + r) * XD + col] = acc[r];
}

// ---------------- mem: gamma / beta*gamma precompute ----------------
__global__ void mem_prep(const float* __restrict__ beta, const float* __restrict__ decay,
                         float* __restrict__ gam, float* __restrict__ bg)
{
    int n = blockIdx.x, d = threadIdx.x;
    float g = (d < MD - DCD) ? 1.f : sigf(decay[n * DCD + (d - (MD - DCD))]);
    gam[n * MD + d] = g;
    bg[n * MD + d] = g * sigf(beta[n * MD + d]);
}

// ---------------- mem: sequential scan (16384 independent recurrences) ----------------
__global__ __launch_bounds__(256) void mem_scan(
    const float* __restrict__ F, const float* __restrict__ V,
    const float* __restrict__ gam, const float* __restrict__ bg, float* __restrict__ mems)
{
    int n = blockIdx.x, d = threadIdx.x;
    float ga = gam[n * MD + d], b = bg[n * MD + d];
    float m = 0.f;
    float fn = F[n], vn = V[d];
    for (int t = 0; t < T; t++) {
        float f = fn, vv = vn;
        if (t + 1 < T) { fn = F[(t + 1) * MN + n]; vn = V[(size_t)(t + 1) * MD + d]; }
        m = (ga - f * b) * m + f * vv;
        mems[((size_t)t * MN + n) * MD + d] = m;
    }
}

// ---------------- transpose 256x256 (Wk -> WkT so qk2 = q@Wk via A@B^T) ----------------
__global__ void transpose256(const float* __restrict__ W, float* __restrict__ WT)
{
    int rk = blockIdx.x, cd = threadIdx.x;
    WT[cd * MD + rk] = W[rk * MD + cd];
}

// ---------------- mem readout: softmax over slots + weighted sum ----------------
__global__ __launch_bounds__(256) void mem_readout(
    const float* __restrict__ mems, const float* __restrict__ qk2,
    const float* __restrict__ lq, float* __restrict__ yout)
{
    int t = blockIdx.x;
    int tid = threadIdx.x, w = tid >> 5, lane = tid & 31;
    __shared__ float qs[MD];
    __shared__ float as[MN];
    qs[tid] = qk2[(size_t)t * MD + tid];
    __syncthreads();
    const float* mb = mems + (size_t)t * MN * MD;
#pragma unroll
    for (int mi = 0; mi < 8; mi++) {
        int m = w * 8 + mi;
        const float* mp = mb + m * MD;
        float d = 0.f;
#pragma unroll
        for (int i = 0; i < 8; i++) d += mp[i * 32 + lane] * qs[i * 32 + lane];
        for (int off = 16; off; off >>= 1) d += __shfl_xor_sync(0xffffffffu, d, off);
        if (lane == 0) as[m] = (d + lq[t * MN + m]) * (1.f / 16.f);  // / sqrt(256)
    }
    __syncthreads();
    if (w == 0) {
        float a0 = as[lane], a1 = as[lane + 32];
        float mx = fmaxf(a0, a1);
        for (int off = 16; off; off >>= 1) mx = fmaxf(mx, __shfl_xor_sync(0xffffffffu, mx, off));
        float e0 = expf(a0 - mx), e1 = expf(a1 - mx);
        float sm = e0 + e1;
        for (int off = 16; off; off >>= 1) sm += __shfl_xor_sync(0xffffffffu, sm, off);
        float inv = 1.f / sm;
        as[lane] = e0 * inv;
        as[lane + 32] = e1 * inv;
    }
    __syncthreads();
    float acc = 0.f;
    for (int m = 0; m < MN; m++) acc += as[m] * mb[m * MD + tid];
    yout[(size_t)t * MD + tid] = acc;
}

// ---------------- launcher ----------------
static float* sym(const void* s) { void* p = nullptr; cudaGetSymbolAddress(&p, s); return (float*)p; }

extern "C" void kernel_launch(void* const* d_in, const int* in_sizes, int n_in,
                              void* d_out, int out_size)
{
    const float* xs      = (const float*)d_in[0];
    const float* attn_q  = (const float*)d_in[1];
    const float* attn_k  = (const float*)d_in[2];
    const float* attn_v  = (const float*)d_in[3];
    const float* attn_o  = (const float*)d_in[4];
    const float* attn_r  = (const float*)d_in[5];
    const float* mem_f   = (const float*)d_in[6];
    const float* mem_q   = (const float*)d_in[7];
    const float* mem_k   = (const float*)d_in[8];
    const float* mem_v   = (const float*)d_in[9];
    const float* mem_o   = (const float*)d_in[10];
    const float* mem_r   = (const float*)d_in[11];
    const float* mem_beta= (const float*)d_in[12];
    const float* mem_dec = (const float*)d_in[13];
    const float* mem_l   = (const float*)d_in[14];
    const float* ff_in1  = (const float*)d_in[15];
    const float* ff_in2  = (const float*)d_in[16];
    const float* ff_out  = (const float*)d_in[17];
    const float* sn1     = (const float*)d_in[18];
    const float* sn2     = (const float*)d_in[19];
    float* out = (float*)d_out;

    float* xn   = sym(B_xn);   float* q_   = sym(B_q);    float* k_   = sym(B_k);
    float* qhi  = sym(B_qhi);  float* klo  = sym(B_klo);  float* khi  = sym(B_khi);
    float* v_   = sym(B_v);    float* A_   = sym(B_A);    float* y_   = sym(B_y);
    float* gate = sym(B_gate); float* accb = sym(B_acc);
    float* memF = sym(B_memF); float* memV = sym(B_memV); float* memQ = sym(B_memQ);
    float* gam  = sym(B_gam);  float* bg   = sym(B_bg);   float* wkT  = sym(B_wkT);
    float* qk2  = sym(B_qk2);  float* lq   = sym(B_lq);   float* mems = sym(B_mems);
    float* memY = sym(B_memY); float* x1   = sym(B_x1);   float* x2n  = sym(B_x2n);
    float* h1   = sym(B_h1);   float* h2   = sym(B_h2);

    const dim3 blk(256);
    // 1. xn = scale_norm(xs, sn1)
    scale_norm_k<<<T, blk>>>(xs, xn, sn1);
    // 2-5. attn projections + gate
    gemm_tn<EPI_NONE><<<dim3(2, 16), blk>>>(xn, attn_q, q_, nullptr, nullptr, nullptr, T, QD, XD);
    gemm_tn<EPI_NONE><<<dim3(2, 16), blk>>>(q_, attn_k, k_, nullptr, nullptr, nullptr, T, QD, QD);
    gemm_tn<EPI_NONE><<<dim3(16, 16), blk>>>(xn, attn_v, v_, nullptr, nullptr, nullptr, T, XD, XD);
    gemm_tn<EPI_NONE><<<dim3(16, 16), blk>>>(xn, attn_r, gate, nullptr, nullptr, nullptr, T, XD, XD);
    // 6. attention core
    rope_all<<<T, 128>>>(q_, k_, qhi, klo, khi);
    attn_score<<<T / 8, blk>>>(qhi, klo, khi, A_);
    attn_av<<<dim3(8, 4, 32), blk>>>(A_, v_, y_);
    // 7. attn out = (y @ Wo^T) * sigmoid(gate)
    gemm_tn<EPI_GATE><<<dim3(16, 16), blk>>>(y_, attn_o, accb, gate, nullptr, nullptr, T, XD, XD);
    // 8-11. mem projections (f is sigmoid'ed in epilogue) + mem gate (reuses `gate`)
    gemm_tn<EPI_SIGMOID><<<dim3(1, 16), blk>>>(xn, mem_f, memF, nullptr, nullptr, nullptr, T, MN, XD);
    gemm_tn<EPI_NONE><<<dim3(2, 16), blk>>>(xn, mem_v, memV, nullptr, nullptr, nullptr, T, MD, XD);
    gemm_tn<EPI_NONE><<<dim3(2, 16), blk>>>(xn, mem_q, memQ, nullptr, nullptr, nullptr, T, MD, XD);
    gemm_tn<EPI_NONE><<<dim3(16, 16), blk>>>(xn, mem_r, gate, nullptr, nullptr, nullptr, T, XD, XD);
    // 12-13. scan
    mem_prep<<<MN, MD>>>(mem_beta, mem_dec, gam, bg);
    mem_scan<<<MN, MD>>>(memF, memV, gam, bg, mems);
    // 14. readout: qk2 = q@Wk (via WkT), lq = q@l^T, then softmax-weighted sum over slots
    transpose256<<<MD, MD>>>(mem_k, wkT);
    gemm_tn<EPI_NONE><<<dim3(2, 16), blk>>>(memQ, wkT, qk2, nullptr, nullptr, nullptr, T, MD, MD);
    gemm_tn<EPI_NONE><<<dim3(1, 16), blk>>>(memQ, mem_l, lq, nullptr, nullptr, nullptr, T, MN, MD);
    mem_readout<<<T, blk>>>(mems, qk2, lq, memY);
    // 15. x1 = (memY @ mem_o^T)*sigmoid(gate) + attn_out + xs
    gemm_tn<EPI_GATE_ADD2><<<dim3(16, 16), blk>>>(memY, mem_o, x1, gate, accb, xs, T, XD, MD);
    // 16-19. FF block
    scale_norm_k<<<T, blk>>>(x1, x2n, sn2);
    gemm_tn<EPI_NONE><<<dim3(22, 16), blk>>>(x2n, ff_in1, h1, nullptr, nullptr, nullptr, T, FFD, XD);
    gemm_tn<EPI_SILU_MUL><<<dim3(22, 16), blk>>>(x2n, ff_in2, h2, h1, nullptr, nullptr, T, FFD, XD);
    gemm_tn<EPI_ADD><<<dim3(16, 16), blk>>>(h2, ff_out, out, nullptr, x1, nullptr, T, XD, FFD);
}

// round 3
// speedup vs baseline: 1.2575x; 1.2575x over previous
#include <cuda_runtime.h>
#include <cuda_bf16.h>
#include <math.h>
#include <stdint.h>

// ---------------- problem dims ----------------
#define T    2048
#define XD   2048
#define QD   256     // X_D / REDUCE
#define MN   64      // M_N
#define MD   256     // M_D
#define DCD  64      // DECAY_D
#define FFD  2816    // FF_D
#define CH   64      // CHUNK

// ---------------- scratch (device globals; allocation-free) ----------------
__device__ float B_xn  [(size_t)T*XD];
__device__ float B_q   [(size_t)T*QD];
__device__ float B_k   [(size_t)T*QD];
__device__ float B_qhi [(size_t)T*QD];
__device__ float B_klo [(size_t)T*QD];
__device__ float B_khi [(size_t)T*QD];
__device__ float B_v   [(size_t)T*XD];
__device__ float B_A   [(size_t)T*2*CH];
__device__ float B_y   [(size_t)T*XD];
__device__ float B_gate[(size_t)T*XD];
__device__ float B_acc [(size_t)T*XD];
__device__ float B_memF[(size_t)T*MN];
__device__ float B_memV[(size_t)T*MD];
__device__ float B_memQ[(size_t)T*MD];
__device__ float B_gam [(size_t)MN*MD];
__device__ float B_bg  [(size_t)MN*MD];
__device__ float B_wkT [(size_t)MD*MD];
__device__ float B_qk2 [(size_t)T*MD];
__device__ float B_lq  [(size_t)T*MN];
__device__ float B_mems[(size_t)T*MN*MD];   // 134 MB
__device__ float B_memY[(size_t)T*MD];
__device__ float B_x1  [(size_t)T*XD];
__device__ float B_x2n [(size_t)T*XD];
__device__ float B_h1  [(size_t)T*FFD];
__device__ float B_h2  [(size_t)T*FFD];

__device__ __forceinline__ float sigf(float x) { return 1.f / (1.f + expf(-x)); }

enum { EPI_NONE = 0, EPI_SIGMOID, EPI_GATE, EPI_GATE_ADD2, EPI_SILU_MUL, EPI_ADD };

// =====================================================================
//  3xTF32 tensor-core GEMM:  C[M,N] = A[M,K] @ B[N,K]^T  (~fp32 accuracy)
//  block: 256 threads (8 warps), tile 128x128, BK=16, double-buffered cp.async
//  warp grid 2(m) x 4(n), each warp computes 64x32 via m16n8k8 tf32 mma
//  each operand split big+small (cvt.rna.tf32); 3 MMAs per product term
// =====================================================================
#define SMSTRIDE 20   // 16 + 4 pad -> conflict-free for frag access pattern

__device__ __forceinline__ uint32_t f2tf(float x)
{
    uint32_t r;
    asm("cvt.rna.tf32.f32 %0, %1;" : "=r"(r) : "f"(x));
    return r;
}

__device__ __forceinline__ void mma8(float* c, uint32_t a0, uint32_t a1, uint32_t a2, uint32_t a3,
                                     uint32_t b0, uint32_t b1)
{
    asm volatile(
        "mma.sync.aligned.m16n8k8.row.col.f32.tf32.tf32.f32 "
        "{%0,%1,%2,%3}, {%4,%5,%6,%7}, {%8,%9}, {%0,%1,%2,%3};"
        : "+f"(c[0]), "+f"(c[1]), "+f"(c[2]), "+f"(c[3])
        : "r"(a0), "r"(a1), "r"(a2), "r"(a3), "r"(b0), "r"(b1));
}

template <int EPI>
__device__ __forceinline__ float epi_apply(float c, size_t idx,
                                           const float* __restrict__ G,
                                           const float* __restrict__ R1,
                                           const float* __restrict__ R2)
{
    if (EPI == EPI_SIGMOID)        c = sigf(c);
    else if (EPI == EPI_GATE)      c = c * sigf(G[idx]);
    else if (EPI == EPI_GATE_ADD2) c = c * sigf(G[idx]) + R1[idx] + R2[idx];
    else if (EPI == EPI_SILU_MUL)  { float g = G[idx]; c = c * (g * sigf(g)); }
    else if (EPI == EPI_ADD)       c = c + R1[idx];
    return c;
}

template <int EPI>
__global__ __launch_bounds__(256) void gemm_mma(
    const float* __restrict__ A, const float* __restrict__ B, float* __restrict__ D,
    const float* __restrict__ G, const float* __restrict__ R1, const float* __restrict__ R2,
    int M, int N, int K)
{
    __shared__ float As[2][128 * SMSTRIDE];
    __shared__ float Bs[2][128 * SMSTRIDE];

    const int tid  = threadIdx.x;
    const int wid  = tid >> 5, lane = tid & 31;
    const int wm   = wid & 1, wn = wid >> 1;      // 2(m) x 4(n) warp grid
    const int g    = lane >> 2, tg = lane & 3;
    const int m0   = blockIdx.y * 128;
    const int n0   = blockIdx.x * 128;

    float acc[4][4][4];
#pragma unroll
    for (int mt = 0; mt < 4; mt++)
#pragma unroll
        for (int nt = 0; nt < 4; nt++)
#pragma unroll
            for (int e = 0; e < 4; e++) acc[mt][nt][e] = 0.f;

    const int KT = K / 16;

    const uint32_t asBase = (uint32_t)__cvta_generic_to_shared(&As[0][0]);
    const uint32_t bsBase = (uint32_t)__cvta_generic_to_shared(&Bs[0][0]);
    const uint32_t stageBytes = 128 * SMSTRIDE * 4;

    // per-thread gmem row pointer: row = tid>>1, 8-float half = tid&1
    const int ldRow  = tid >> 1;
    const int ldCol  = (tid & 1) * 8;
    const float* agRow = A + (size_t)(m0 + ldRow) * K + ldCol;
    const float* bgRow = B + (size_t)(n0 + ldRow) * K + ldCol;
    const uint32_t asDst = asBase + (ldRow * SMSTRIDE + ldCol) * 4;
    const uint32_t bsDst = bsBase + (ldRow * SMSTRIDE + ldCol) * 4;

#define LOAD_STAGE(buf, kt)                                                            \
    {                                                                                  \
        int k0_ = (kt) * 16;                                                           \
        uint32_t da = asDst + (buf) * stageBytes;                                      \
        uint32_t db = bsDst + (buf) * stageBytes;                                      \
        const float* ga = agRow + k0_;                                                 \
        const float* gb = bgRow + k0_;                                                 \
        asm volatile("cp.async.ca.shared.global [%0], [%1], 16;" :: "r"(da),      "l"(ga));     \
        asm volatile("cp.async.ca.shared.global [%0], [%1], 16;" :: "r"(da + 16), "l"(ga + 4)); \
        asm volatile("cp.async.ca.shared.global [%0], [%1], 16;" :: "r"(db),      "l"(gb));     \
        asm volatile("cp.async.ca.shared.global [%0], [%1], 16;" :: "r"(db + 16), "l"(gb + 4)); \
    }

    LOAD_STAGE(0, 0);
    asm volatile("cp.async.commit_group;");

    for (int kt = 0; kt < KT; kt++) {
        if (kt + 1 < KT) LOAD_STAGE((kt + 1) & 1, kt + 1);
        asm volatile("cp.async.commit_group;");
        asm volatile("cp.async.wait_group 1;");
        __syncthreads();

        const float* as = &As[kt & 1][0];
        const float* bs = &Bs[kt & 1][0];

#pragma unroll
        for (int ks = 0; ks < 2; ks++) {
            const int kb = ks * 8;
            uint32_t bb[4][2], bsm[4][2];
#pragma unroll
            for (int nt = 0; nt < 4; nt++) {
                int n = wn * 32 + nt * 8 + g;
                float v0 = bs[n * SMSTRIDE + kb + tg];
                float v1 = bs[n * SMSTRIDE + kb + tg + 4];
                bb[nt][0]  = f2tf(v0);
                bb[nt][1]  = f2tf(v1);
                bsm[nt][0] = f2tf(v0 - __uint_as_float(bb[nt][0]));
                bsm[nt][1] = f2tf(v1 - __uint_as_float(bb[nt][1]));
            }
#pragma unroll
            for (int mt = 0; mt < 4; mt++) {
                int m = wm * 64 + mt * 16;
                float v0 = as[(m + g)     * SMSTRIDE + kb + tg];
                float v1 = as[(m + g + 8) * SMSTRIDE + kb + tg];
                float v2 = as[(m + g)     * SMSTRIDE + kb + tg + 4];
                float v3 = as[(m + g + 8) * SMSTRIDE + kb + tg + 4];
                uint32_t ab0 = f2tf(v0), ab1 = f2tf(v1), ab2 = f2tf(v2), ab3 = f2tf(v3);
                uint32_t as0 = f2tf(v0 - __uint_as_float(ab0));
                uint32_t as1 = f2tf(v1 - __uint_as_float(ab1));
                uint32_t as2 = f2tf(v2 - __uint_as_float(ab2));
                uint32_t as3 = f2tf(v3 - __uint_as_float(ab3));
#pragma unroll
                for (int nt = 0; nt < 4; nt++) {
                    mma8(acc[mt][nt], as0, as1, as2, as3, bb[nt][0],  bb[nt][1]);   // a_small * b_big
                    mma8(acc[mt][nt], ab0, ab1, ab2, ab3, bsm[nt][0], bsm[nt][1]);  // a_big * b_small
                    mma8(acc[mt][nt], ab0, ab1, ab2, ab3, bb[nt][0],  bb[nt][1]);   // a_big * b_big
                }
            }
        }
        __syncthreads();
    }
#undef LOAD_STAGE

    // epilogue
#pragma unroll
    for (int mt = 0; mt < 4; mt++) {
        int r0 = m0 + wm * 64 + mt * 16 + g;
#pragma unroll
        for (int nt = 0; nt < 4; nt++) {
            int col = n0 + wn * 32 + nt * 8 + tg * 2;
            size_t i0 = (size_t)r0 * N + col;
            size_t i1 = i0 + (size_t)8 * N;
            float2 o0, o1;
            o0.x = epi_apply<EPI>(acc[mt][nt][0], i0,     G, R1, R2);
            o0.y = epi_apply<EPI>(acc[mt][nt][1], i0 + 1, G, R1, R2);
            o1.x = epi_apply<EPI>(acc[mt][nt][2], i1,     G, R1, R2);
            o1.y = epi_apply<EPI>(acc[mt][nt][3], i1 + 1, G, R1, R2);
            *(float2*)&D[i0] = o0;
            *(float2*)&D[i1] = o1;
        }
    }
}

// ---------------- legacy FFMA GEMM (kept for tiny-N cases) ----------------
#define BM 128
#define BN 128
#define BKK 16

template <int EPI>
__global__ __launch_bounds__(256) void gemm_tn(
    const float* __restrict__ A, const float* __restrict__ B, float* __restrict__ D,
    const float* __restrict__ G, const float* __restrict__ R1, const float* __restrict__ R2,
    int M, int N, int K)
{
    __shared__ float As[BKK][BM + 4];
    __shared__ float Bs[BKK][BN + 4];

    const int tid = threadIdx.x;
    const int m0 = blockIdx.y * BM;
    const int n0 = blockIdx.x * BN;
    const int tx = tid & 15;
    const int ty = tid >> 4;

    float acc[8][8];
#pragma unroll
    for (int i = 0; i < 8; i++)
#pragma unroll
        for (int j = 0; j < 8; j++) acc[i][j] = 0.f;

    for (int k0 = 0; k0 < K; k0 += BKK) {
#pragma unroll
        for (int l = 0; l < 2; l++) {
            int qi  = tid + l * 256;
            int row = qi >> 2;
            int kk  = (qi & 3) * 4;
            float4 av = *(const float4*)&A[(size_t)(m0 + row) * K + k0 + kk];
            As[kk + 0][row] = av.x; As[kk + 1][row] = av.y;
            As[kk + 2][row] = av.z; As[kk + 3][row] = av.w;
        }
#pragma unroll
        for (int l = 0; l < 2; l++) {
            int qi  = tid + l * 256;
            int row = qi >> 2;
            int kk  = (qi & 3) * 4;
            float4 bv = make_float4(0.f, 0.f, 0.f, 0.f);
            if (n0 + row < N) bv = *(const float4*)&B[(size_t)(n0 + row) * K + k0 + kk];
            Bs[kk + 0][row] = bv.x; Bs[kk + 1][row] = bv.y;
            Bs[kk + 2][row] = bv.z; Bs[kk + 3][row] = bv.w;
        }
        __syncthreads();

#pragma unroll
        for (int kk = 0; kk < BKK; kk++) {
            float a[8], b[8];
#pragma unroll
            for (int i = 0; i < 8; i++) a[i] = As[kk][ty * 8 + i];
#pragma unroll
            for (int j = 0; j < 8; j++) b[j] = Bs[kk][tx * 8 + j];
#pragma unroll
            for (int i = 0; i < 8; i++)
#pragma unroll
                for (int j = 0; j < 8; j++) acc[i][j] += a[i] * b[j];
        }
        __syncthreads();
    }

#pragma unroll
    for (int i = 0; i < 8; i++) {
        int row = m0 + ty * 8 + i;
#pragma unroll
        for (int j = 0; j < 8; j++) {
            int col = n0 + tx * 8 + j;
            if (col < N) {
                size_t idx = (size_t)row * N + col;
                D[idx] = epi_apply<EPI>(acc[i][j], idx, G, R1, R2);
            }
        }
    }
}

// ---------------- scale_norm ----------------
__global__ __launch_bounds__(256) void scale_norm_k(
    const float* __restrict__ x, float* __restrict__ o, const float* __restrict__ g)
{
    int t = blockIdx.x;
    const float4* xr = (const float4*)(x + (size_t)t * XD);
    float4 v0 = xr[threadIdx.x];
    float4 v1 = xr[threadIdx.x + 256];
    float s = v0.x*v0.x + v0.y*v0.y + v0.z*v0.z + v0.w*v0.w
            + v1.x*v1.x + v1.y*v1.y + v1.z*v1.z + v1.w*v1.w;
    for (int off = 16; off; off >>= 1) s += __shfl_xor_sync(0xffffffffu, s, off);
    __shared__ float red[8];
    int w = threadIdx.x >> 5, lane = threadIdx.x & 31;
    if (lane == 0) red[w] = s;
    __syncthreads();
    float tot = red[0] + red[1] + red[2] + red[3] + red[4] + red[5] + red[6] + red[7];
    float sc = g[0] / (sqrtf(tot) + 1e-8f);
    float4* orow = (float4*)(o + (size_t)t * XD);
    v0.x *= sc; v0.y *= sc; v0.z *= sc; v0.w *= sc;
    v1.x *= sc; v1.y *= sc; v1.z *= sc; v1.w *= sc;
    orow[threadIdx.x] = v0;
    orow[threadIdx.x + 256] = v1;
}

// ---------------- RoPE ----------------
__global__ __launch_bounds__(128) void rope_all(
    const float* __restrict__ q, const float* __restrict__ k,
    float* __restrict__ qhi, float* __restrict__ klo, float* __restrict__ khi)
{
    int t = blockIdx.x, j = threadIdx.x;
    int r = t & 63;
    float freq = powf(10000.f, -(float)j / 128.f);
    float slo, clo, shi, chi;
    sincosf((float)r * freq, &slo, &clo);
    sincosf((float)(64 + r) * freq, &shi, &chi);
    size_t base = (size_t)t * QD + 2 * j;
    float qe = q[base], qo = q[base + 1];
    qhi[base]     = qe * chi - qo * shi;
    qhi[base + 1] = qo * chi + qe * shi;
    float ke = k[base], ko = k[base + 1];
    klo[base]     = ke * clo - ko * slo;
    klo[base + 1] = ko * clo + ke * slo;
    khi[base]     = ke * chi - ko * shi;
    khi[base + 1] = ko * chi + ke * shi;
}

// ---------------- attention scores + softmax ----------------
__global__ __launch_bounds__(256) void attn_score(
    const float* __restrict__ qr, const float* __restrict__ klo,
    const float* __restrict__ khi, float* __restrict__ Aout)
{
    int w = threadIdx.x >> 5, lane = threadIdx.x & 31;
    int t = blockIdx.x * 8 + w;
    int c = t >> 6, r = t & 63;
    float qreg[8];
#pragma unroll
    for (int i = 0; i < 8; i++) qreg[i] = qr[(size_t)t * QD + i * 32 + lane];

    __shared__ float s_s[8][128];
    for (int m = 0; m < 128; m++) {
        float sc;
        if (c == 0 && m < 64) {
            sc = 0.f;
        } else {
            const float* kp = (m < 64)
                ? &klo[(size_t)((c - 1) * 64 + m) * QD]
                : &khi[(size_t)(c * 64 + (m - 64)) * QD];
            float d = 0.f;
#pragma unroll
            for (int i = 0; i < 8; i++) d += qreg[i] * kp[i * 32 + lane];
            for (int off = 16; off; off >>= 1) d += __shfl_xor_sync(0xffffffffu, d, off);
            sc = d * (1.f / 16.f);
        }
        if (m > r + 64) sc = -1e30f;
        if (lane == 0) s_s[w][m] = sc;
    }
    __syncwarp();
    float a0 = s_s[w][lane], a1 = s_s[w][lane + 32], a2 = s_s[w][lane + 64], a3 = s_s[w][lane + 96];
    float mx = fmaxf(fmaxf(a0, a1), fmaxf(a2, a3));
    for (int off = 16; off; off >>= 1) mx = fmaxf(mx, __shfl_xor_sync(0xffffffffu, mx, off));
    float e0 = expf(a0 - mx), e1 = expf(a1 - mx), e2 = expf(a2 - mx), e3 = expf(a3 - mx);
    float sm = e0 + e1 + e2 + e3;
    for (int off = 16; off; off >>= 1) sm += __shfl_xor_sync(0xffffffffu, sm, off);
    float inv = 1.f / sm;
    size_t ob = (size_t)t * 128;
    Aout[ob + lane]      = e0 * inv;
    Aout[ob + lane + 32] = e1 * inv;
    Aout[ob + lane + 64] = e2 * inv;
    Aout[ob + lane + 96] = e3 * inv;
}

// ---------------- y = A @ v2 ----------------
__global__ __launch_bounds__(256) void attn_av(
    const float* __restrict__ Aat, const float* __restrict__ v, float* __restrict__ y)
{
    int c = blockIdx.z, rg = blockIdx.y, ct = blockIdx.x;
    int col = ct * 256 + threadIdx.x;
    __shared__ float As[16][128];
    for (int idx = threadIdx.x; idx < 16 * 128; idx += 256) {
        int rr = idx >> 7, mm = idx & 127;
        As[rr][mm] = Aat[(size_t)(c * 64 + rg * 16 + rr) * 128 + mm];
    }
    __syncthreads();
    float acc[16];
#pragma unroll
    for (int r = 0; r < 16; r++) acc[r] = 0.f;
    int mstart = (c == 0) ? 64 : 0;
    for (int m = mstart; m < 128; m++) {
        float vv = v[(size_t)((c - 1) * 64 + m) * XD + col];
#pragma unroll
        for (int r = 0; r < 16; r++) acc[r] += As[r][m] * vv;
    }
#pragma unroll
    for (int r = 0; r < 16; r++)
        y[(size_t)(c * 64 + rg * 16 + r) * XD + col] = acc[r];
}

// ---------------- mem prep ----------------
__global__ void mem_prep(const float* __restrict__ beta, const float* __restrict__ decay,
                         float* __restrict__ gam, float* __restrict__ bg)
{
    int n = blockIdx.x, d = threadIdx.x;
    float g = (d < MD - DCD) ? 1.f : sigf(decay[n * DCD + (d - (MD - DCD))]);
    gam[n * MD + d] = g;
    bg[n * MD + d] = g * sigf(beta[n * MD + d]);
}

// ---------------- mem scan ----------------
__global__ __launch_bounds__(256) void mem_scan(
    const float* __restrict__ F, const float* __restrict__ V,
    const float* __restrict__ gam, const float* __restrict__ bg, float* __restrict__ mems)
{
    int n = blockIdx.x, d = threadIdx.x;
    float ga = gam[n * MD + d], b = bg[n * MD + d];
    float m = 0.f;
    float fn = F[n], vn = V[d];
    for (int t = 0; t < T; t++) {
        float f = fn, vv = vn;
        if (t + 1 < T) { fn = F[(t + 1) * MN + n]; vn = V[(size_t)(t + 1) * MD + d]; }
        m = (ga - f * b) * m + f * vv;
        mems[((size_t)t * MN + n) * MD + d] = m;
    }
}

// ---------------- transpose 256x256 ----------------
__global__ void transpose256(const float* __restrict__ W, float* __restrict__ WT)
{
    int rk = blockIdx.x, cd = threadIdx.x;
    WT[cd * MD + rk] = W[rk * MD + cd];
}

// ---------------- mem readout ----------------
__global__ __launch_bounds__(256) void mem_readout(
    const float* __restrict__ mems, const float* __restrict__ qk2,
    const float* __restrict__ lq, float* __restrict__ yout)
{
    int t = blockIdx.x;
    int tid = threadIdx.x, w = tid >> 5, lane = tid & 31;
    __shared__ float qs[MD];
    __shared__ float as[MN];
    qs[tid] = qk2[(size_t)t * MD + tid];
    __syncthreads();
    const float* mb = mems + (size_t)t * MN * MD;
#pragma unroll
    for (int mi = 0; mi < 8; mi++) {
        int m = w * 8 + mi;
        const float* mp = mb + m * MD;
        float d = 0.f;
#pragma unroll
        for (int i = 0; i < 8; i++) d += mp[i * 32 + lane] * qs[i * 32 + lane];
        for (int off = 16; off; off >>= 1) d += __shfl_xor_sync(0xffffffffu, d, off);
        if (lane == 0) as[m] = (d + lq[t * MN + m]) * (1.f / 16.f);
    }
    __syncthreads();
    if (w == 0) {
        float a0 = as[lane], a1 = as[lane + 32];
        float mx = fmaxf(a0, a1);
        for (int off = 16; off; off >>= 1) mx = fmaxf(mx, __shfl_xor_sync(0xffffffffu, mx, off));
        float e0 = expf(a0 - mx), e1 = expf(a1 - mx);
        float sm = e0 + e1;
        for (int off = 16; off; off >>= 1) sm += __shfl_xor_sync(0xffffffffu, sm, off);
        float inv = 1.f / sm;
        as[lane] = e0 * inv;
        as[lane + 32] = e1 * inv;
    }
    __syncthreads();
    float acc = 0.f;
    for (int m = 0; m < MN; m++) acc += as[m] * mb[m * MD + tid];
    yout[(size_t)t * MD + tid] = acc;
}

// ---------------- launcher ----------------
static float* sym(const void* s) { void* p = nullptr; cudaGetSymbolAddress(&p, s); return (float*)p; }

extern "C" void kernel_launch(void* const* d_in, const int* in_sizes, int n_in,
                              void* d_out, int out_size)
{
    const float* xs      = (const float*)d_in[0];
    const float* attn_q  = (const float*)d_in[1];
    const float* attn_k  = (const float*)d_in[2];
    const float* attn_v  = (const float*)d_in[3];
    const float* attn_o  = (const float*)d_in[4];
    const float* attn_r  = (const float*)d_in[5];
    const float* mem_f   = (const float*)d_in[6];
    const float* mem_q   = (const float*)d_in[7];
    const float* mem_k   = (const float*)d_in[8];
    const float* mem_v   = (const float*)d_in[9];
    const float* mem_o   = (const float*)d_in[10];
    const float* mem_r   = (const float*)d_in[11];
    const float* mem_beta= (const float*)d_in[12];
    const float* mem_dec = (const float*)d_in[13];
    const float* mem_l   = (const float*)d_in[14];
    const float* ff_in1  = (const float*)d_in[15];
    const float* ff_in2  = (const float*)d_in[16];
    const float* ff_out  = (const float*)d_in[17];
    const float* sn1     = (const float*)d_in[18];
    const float* sn2     = (const float*)d_in[19];
    float* out = (float*)d_out;

    float* xn   = sym(B_xn);   float* q_   = sym(B_q);    float* k_   = sym(B_k);
    float* qhi  = sym(B_qhi);  float* klo  = sym(B_klo);  float* khi  = sym(B_khi);
    float* v_   = sym(B_v);    float* A_   = sym(B_A);    float* y_   = sym(B_y);
    float* gate = sym(B_gate); float* accb = sym(B_acc);
    float* memF = sym(B_memF); float* memV = sym(B_memV); float* memQ = sym(B_memQ);
    float* gam  = sym(B_gam);  float* bg   = sym(B_bg);   float* wkT  = sym(B_wkT);
    float* qk2  = sym(B_qk2);  float* lq   = sym(B_lq);   float* mems = sym(B_mems);
    float* memY = sym(B_memY); float* x1   = sym(B_x1);   float* x2n  = sym(B_x2n);
    float* h1   = sym(B_h1);   float* h2   = sym(B_h2);

    const dim3 blk256(256);

    // 1. xn = scale_norm(xs, sn1)
    scale_norm_k<<<T, blk256>>>(xs, xn, sn1);
    // 2-5. attn projections + gate (3xTF32 tensor path)
    gemm_mma<EPI_NONE><<<dim3(2, 16),  blk256>>>(xn, attn_q, q_, nullptr, nullptr, nullptr, T, QD, XD);
    gemm_mma<EPI_NONE><<<dim3(2, 16),  blk256>>>(q_, attn_k, k_, nullptr, nullptr, nullptr, T, QD, QD);
    gemm_mma<EPI_NONE><<<dim3(16, 16), blk256>>>(xn, attn_v, v_, nullptr, nullptr, nullptr, T, XD, XD);
    gemm_mma<EPI_NONE><<<dim3(16, 16), blk256>>>(xn, attn_r, gate, nullptr, nullptr, nullptr, T, XD, XD);
    // 6. attention core
    rope_all<<<T, 128>>>(q_, k_, qhi, klo, khi);
    attn_score<<<T / 8, blk256>>>(qhi, klo, khi, A_);
    attn_av<<<dim3(8, 4, 32), blk256>>>(A_, v_, y_);
    // 7. attn out = (y @ Wo^T) * sigmoid(gate)
    gemm_mma<EPI_GATE><<<dim3(16, 16), blk256>>>(y_, attn_o, accb, gate, nullptr, nullptr, T, XD, XD);
    // 8-11. mem projections + mem gate
    gemm_tn<EPI_SIGMOID><<<dim3(1, 16), blk256>>>(xn, mem_f, memF, nullptr, nullptr, nullptr, T, MN, XD);
    gemm_mma<EPI_NONE><<<dim3(2, 16),  blk256>>>(xn, mem_v, memV, nullptr, nullptr, nullptr, T, MD, XD);
    gemm_mma<EPI_NONE><<<dim3(2, 16),  blk256>>>(xn, mem_q, memQ, nullptr, nullptr, nullptr, T, MD, XD);
    gemm_mma<EPI_NONE><<<dim3(16, 16), blk256>>>(xn, mem_r, gate, nullptr, nullptr, nullptr, T, XD, XD);
    // 12-13. scan
    mem_prep<<<MN, MD>>>(mem_beta, mem_dec, gam, bg);
    mem_scan<<<MN, MD>>>(memF, memV, gam, bg, mems);
    // 14. readout
    transpose256<<<MD, MD>>>(mem_k, wkT);
    gemm_mma<EPI_NONE><<<dim3(2, 16), blk256>>>(memQ, wkT, qk2, nullptr, nullptr, nullptr, T, MD, MD);
    gemm_tn<EPI_NONE><<<dim3(1, 16), blk256>>>(memQ, mem_l, lq, nullptr, nullptr, nullptr, T, MN, MD);
    mem_readout<<<T, blk256>>>(mems, qk2, lq, memY);
    // 15. x1 = (memY @ mem_o^T)*sigmoid(gate) + attn_out + xs
    gemm_mma<EPI_GATE_ADD2><<<dim3(16, 16), blk256>>>(memY, mem_o, x1, gate, accb, xs, T, XD, MD);
    // 16-19. FF block
    scale_norm_k<<<T, blk256>>>(x1, x2n, sn2);
    gemm_mma<EPI_NONE><<<dim3(22, 16), blk256>>>(x2n, ff_in1, h1, nullptr, nullptr, nullptr, T, FFD, XD);
    gemm_mma<EPI_SILU_MUL><<<dim3(22, 16), blk256>>>(x2n, ff_in2, h2, h1, nullptr, nullptr, T, FFD, XD);
    gemm_mma<EPI_ADD><<<dim3(16, 16), blk256>>>(h2, ff_out, out, nullptr, x1, nullptr, T, XD, FFD);
}

// round 6
// speedup vs baseline: 1.6069x; 1.2779x over previous
#include <cuda_runtime.h>
#include <cuda_bf16.h>
#include <math.h>
#include <stdint.h>

// ---------------- problem dims ----------------
#define T    2048
#define XD   2048
#define QD   256     // X_D / REDUCE
#define MN   64      // M_N
#define MD   256     // M_D
#define DCD  64      // DECAY_D
#define FFD  2816    // FF_D
#define CH   64      // CHUNK

// ---------------- scratch (device globals; allocation-free) ----------------
__device__ float B_xn  [(size_t)T*XD];
__device__ float B_q   [(size_t)T*QD];
__device__ float B_k   [(size_t)T*QD];
__device__ float B_qhi [(size_t)T*QD];
__device__ float B_klo [(size_t)T*QD];
__device__ float B_khi [(size_t)T*QD];
__device__ float B_v   [(size_t)T*XD];
__device__ float B_A   [(size_t)T*2*CH];
__device__ float B_y   [(size_t)T*XD];
__device__ float B_gate[(size_t)T*XD];
__device__ float B_acc [(size_t)T*XD];
__device__ float B_memF[(size_t)T*MN];
__device__ float B_memV[(size_t)T*MD];
__device__ float B_memQ[(size_t)T*MD];
__device__ float B_gam [(size_t)MN*MD];
__device__ float B_bg  [(size_t)MN*MD];
__device__ float B_wkT [(size_t)MD*MD];
__device__ float B_qk2 [(size_t)T*MD];
__device__ float B_lq  [(size_t)T*MN];
__device__ float B_mems[(size_t)T*MN*MD];   // 134 MB
__device__ float B_memY[(size_t)T*MD];
__device__ float B_x1  [(size_t)T*XD];
__device__ float B_x2n [(size_t)T*XD];
__device__ float B_h1  [(size_t)T*FFD];
__device__ float B_h2  [(size_t)T*FFD];

__device__ __forceinline__ float sigf(float x) { return 1.f / (1.f + expf(-x)); }

enum { EPI_NONE = 0, EPI_SIGMOID, EPI_GATE, EPI_GATE_ADD2, EPI_SILU_MUL, EPI_ADD };

// =====================================================================
//  bf16-split tensor-core GEMM:  C[M,N] = A[M,K] @ B[N,K]^T (~1e-5 accuracy)
//  Each fp32 operand split v = hi(bf16) + lo(bf16); 3 MMAs per product:
//  lo*hi + hi*lo + hi*hi  (dropped lo*lo ~ 2^-18).
//  block: 256 threads (8 warps), tile 128x128, BK=16, double-buffered cp.async
//  warp grid 2(m) x 4(n), each warp computes 64x32 via m16n8k16 bf16 mma.
//  Term-ordered so consecutive MMAs hit different accumulators.
// =====================================================================
#define SMSTRIDE 20   // 16 + 4 pad

// hi = bf16x2(v0,v1) packed (v0 low half), lo = bf16x2 of residuals
__device__ __forceinline__ void split2(float v0, float v1, uint32_t& hi, uint32_t& lo)
{
    asm("cvt.rn.bf16x2.f32 %0, %1, %2;" : "=r"(hi) : "f"(v1), "f"(v0));
    float h0 = __uint_as_float(hi << 16);
    float h1 = __uint_as_float(hi & 0xffff0000u);
    asm("cvt.rn.bf16x2.f32 %0, %1, %2;" : "=r"(lo) : "f"(v1 - h1), "f"(v0 - h0));
}

__device__ __forceinline__ void mma16(float* c, uint32_t a0, uint32_t a1, uint32_t a2, uint32_t a3,
                                      uint32_t b0, uint32_t b1)
{
    asm volatile(
        "mma.sync.aligned.m16n8k16.row.col.f32.bf16.bf16.f32 "
        "{%0,%1,%2,%3}, {%4,%5,%6,%7}, {%8,%9}, {%0,%1,%2,%3};"
        : "+f"(c[0]), "+f"(c[1]), "+f"(c[2]), "+f"(c[3])
        : "r"(a0), "r"(a1), "r"(a2), "r"(a3), "r"(b0), "r"(b1));
}

template <int EPI>
__device__ __forceinline__ float epi_apply(float c, size_t idx,
                                           const float* __restrict__ G,
                                           const float* __restrict__ R1,
                                           const float* __restrict__ R2)
{
    if (EPI == EPI_SIGMOID)        c = sigf(c);
    else if (EPI == EPI_GATE)      c = c * sigf(G[idx]);
    else if (EPI == EPI_GATE_ADD2) c = c * sigf(G[idx]) + R1[idx] + R2[idx];
    else if (EPI == EPI_SILU_MUL)  { float g = G[idx]; c = c * (g * sigf(g)); }
    else if (EPI == EPI_ADD)       c = c + R1[idx];
    return c;
}

template <int EPI>
__global__ __launch_bounds__(256) void gemm_mma(
    const float* __restrict__ A, const float* __restrict__ B, float* __restrict__ D,
    const float* __restrict__ G, const float* __restrict__ R1, const float* __restrict__ R2,
    int M, int N, int K)
{
    __shared__ float As[2][128 * SMSTRIDE];
    __shared__ float Bs[2][128 * SMSTRIDE];

    const int tid  = threadIdx.x;
    const int wid  = tid >> 5, lane = tid & 31;
    const int wm   = wid & 1, wn = wid >> 1;      // 2(m) x 4(n) warp grid
    const int g    = lane >> 2, tg = lane & 3;
    const int m0   = blockIdx.y * 128;
    const int n0   = blockIdx.x * 128;

    float acc[4][4][4];
#pragma unroll
    for (int mt = 0; mt < 4; mt++)
#pragma unroll
        for (int nt = 0; nt < 4; nt++)
#pragma unroll
            for (int e = 0; e < 4; e++) acc[mt][nt][e] = 0.f;

    const int KT = K / 16;

    const uint32_t asBase = (uint32_t)__cvta_generic_to_shared(&As[0][0]);
    const uint32_t bsBase = (uint32_t)__cvta_generic_to_shared(&Bs[0][0]);
    const uint32_t stageBytes = 128 * SMSTRIDE * 4;

    // per-thread gmem row pointer: row = tid>>1, 8-float half = tid&1
    const int ldRow  = tid >> 1;
    const int ldCol  = (tid & 1) * 8;
    const float* agRow = A + (size_t)(m0 + ldRow) * K + ldCol;
    const float* bgRow = B + (size_t)(n0 + ldRow) * K + ldCol;
    const uint32_t asDst = asBase + (ldRow * SMSTRIDE + ldCol) * 4;
    const uint32_t bsDst = bsBase + (ldRow * SMSTRIDE + ldCol) * 4;

#define LOAD_STAGE(buf, kt)                                                            \
    {                                                                                  \
        int k0_ = (kt) * 16;                                                           \
        uint32_t da = asDst + (buf) * stageBytes;                                      \
        uint32_t db = bsDst + (buf) * stageBytes;                                      \
        const float* ga = agRow + k0_;                                                 \
        const float* gb = bgRow + k0_;                                                 \
        asm volatile("cp.async.ca.shared.global [%0], [%1], 16;" :: "r"(da),      "l"(ga));     \
        asm volatile("cp.async.ca.shared.global [%0], [%1], 16;" :: "r"(da + 16), "l"(ga + 4)); \
        asm volatile("cp.async.ca.shared.global [%0], [%1], 16;" :: "r"(db),      "l"(gb));     \
        asm volatile("cp.async.ca.shared.global [%0], [%1], 16;" :: "r"(db + 16), "l"(gb + 4)); \
    }

    LOAD_STAGE(0, 0);
    asm volatile("cp.async.commit_group;");

    for (int kt = 0; kt < KT; kt++) {
        if (kt + 1 < KT) LOAD_STAGE((kt + 1) & 1, kt + 1);
        asm volatile("cp.async.commit_group;");
        asm volatile("cp.async.wait_group 1;");
        __syncthreads();

        const float* as = &As[kt & 1][0];
        const float* bs = &Bs[kt & 1][0];

        // B fragments for this warp's 4 n-tiles (k16 = whole stage)
        uint32_t bhi[4][2], blo[4][2];
#pragma unroll
        for (int nt = 0; nt < 4; nt++) {
            int n = wn * 32 + nt * 8 + g;
            float2 w0 = *(const float2*)&bs[n * SMSTRIDE + 2 * tg];
            float2 w1 = *(const float2*)&bs[n * SMSTRIDE + 2 * tg + 8];
            split2(w0.x, w0.y, bhi[nt][0], blo[nt][0]);
            split2(w1.x, w1.y, bhi[nt][1], blo[nt][1]);
        }

#pragma unroll
        for (int mt = 0; mt < 4; mt++) {
            int m = wm * 64 + mt * 16;
            float2 v00 = *(const float2*)&as[(m + g)     * SMSTRIDE + 2 * tg];
            float2 v10 = *(const float2*)&as[(m + g + 8) * SMSTRIDE + 2 * tg];
            float2 v02 = *(const float2*)&as[(m + g)     * SMSTRIDE + 2 * tg + 8];
            float2 v12 = *(const float2*)&as[(m + g + 8) * SMSTRIDE + 2 * tg + 8];
            uint32_t ahi[4], alo[4];
            split2(v00.x, v00.y, ahi[0], alo[0]);
            split2(v10.x, v10.y, ahi[1], alo[1]);
            split2(v02.x, v02.y, ahi[2], alo[2]);
            split2(v12.x, v12.y, ahi[3], alo[3]);
            // term-major order: consecutive MMAs target different accumulators
#pragma unroll
            for (int nt = 0; nt < 4; nt++)
                mma16(acc[mt][nt], alo[0], alo[1], alo[2], alo[3], bhi[nt][0], bhi[nt][1]);
#pragma unroll
            for (int nt = 0; nt < 4; nt++)
                mma16(acc[mt][nt], ahi[0], ahi[1], ahi[2], ahi[3], blo[nt][0], blo[nt][1]);
#pragma unroll
            for (int nt = 0; nt < 4; nt++)
                mma16(acc[mt][nt], ahi[0], ahi[1], ahi[2], ahi[3], bhi[nt][0], bhi[nt][1]);
        }
        __syncthreads();
    }
#undef LOAD_STAGE

    // epilogue
#pragma unroll
    for (int mt = 0; mt < 4; mt++) {
        int r0 = m0 + wm * 64 + mt * 16 + g;
#pragma unroll
        for (int nt = 0; nt < 4; nt++) {
            int col = n0 + wn * 32 + nt * 8 + tg * 2;
            size_t i0 = (size_t)r0 * N + col;
            size_t i1 = i0 + (size_t)8 * N;
            float2 o0, o1;
            o0.x = epi_apply<EPI>(acc[mt][nt][0], i0,     G, R1, R2);
            o0.y = epi_apply<EPI>(acc[mt][nt][1], i0 + 1, G, R1, R2);
            o1.x = epi_apply<EPI>(acc[mt][nt][2], i1,     G, R1, R2);
            o1.y = epi_apply<EPI>(acc[mt][nt][3], i1 + 1, G, R1, R2);
            *(float2*)&D[i0] = o0;
            *(float2*)&D[i1] = o1;
        }
    }
}

// ---------------- legacy FFMA GEMM (kept for tiny-N cases) ----------------
#define BM 128
#define BN 128
#define BKK 16

template <int EPI>
__global__ __launch_bounds__(256) void gemm_tn(
    const float* __restrict__ A, const float* __restrict__ B, float* __restrict__ D,
    const float* __restrict__ G, const float* __restrict__ R1, const float* __restrict__ R2,
    int M, int N, int K)
{
    __shared__ float As[BKK][BM + 4];
    __shared__ float Bs[BKK][BN + 4];

    const int tid = threadIdx.x;
    const int m0 = blockIdx.y * BM;
    const int n0 = blockIdx.x * BN;
    const int tx = tid & 15;
    const int ty = tid >> 4;

    float acc[8][8];
#pragma unroll
    for (int i = 0; i < 8; i++)
#pragma unroll
        for (int j = 0; j < 8; j++) acc[i][j] = 0.f;

    for (int k0 = 0; k0 < K; k0 += BKK) {
#pragma unroll
        for (int l = 0; l < 2; l++) {
            int qi  = tid + l * 256;
            int row = qi >> 2;
            int kk  = (qi & 3) * 4;
            float4 av = *(const float4*)&A[(size_t)(m0 + row) * K + k0 + kk];
            As[kk + 0][row] = av.x; As[kk + 1][row] = av.y;
            As[kk + 2][row] = av.z; As[kk + 3][row] = av.w;
        }
#pragma unroll
        for (int l = 0; l < 2; l++) {
            int qi  = tid + l * 256;
            int row = qi >> 2;
            int kk  = (qi & 3) * 4;
            float4 bv = make_float4(0.f, 0.f, 0.f, 0.f);
            if (n0 + row < N) bv = *(const float4*)&B[(size_t)(n0 + row) * K + k0 + kk];
            Bs[kk + 0][row] = bv.x; Bs[kk + 1][row] = bv.y;
            Bs[kk + 2][row] = bv.z; Bs[kk + 3][row] = bv.w;
        }
        __syncthreads();

#pragma unroll
        for (int kk = 0; kk < BKK; kk++) {
            float a[8], b[8];
#pragma unroll
            for (int i = 0; i < 8; i++) a[i] = As[kk][ty * 8 + i];
#pragma unroll
            for (int j = 0; j < 8; j++) b[j] = Bs[kk][tx * 8 + j];
#pragma unroll
            for (int i = 0; i < 8; i++)
#pragma unroll
                for (int j = 0; j < 8; j++) acc[i][j] += a[i] * b[j];
        }
        __syncthreads();
    }

#pragma unroll
    for (int i = 0; i < 8; i++) {
        int row = m0 + ty * 8 + i;
#pragma unroll
        for (int j = 0; j < 8; j++) {
            int col = n0 + tx * 8 + j;
            if (col < N) {
                size_t idx = (size_t)row * N + col;
                D[idx] = epi_apply<EPI>(acc[i][j], idx, G, R1, R2);
            }
        }
    }
}

// ---------------- scale_norm ----------------
__global__ __launch_bounds__(256) void scale_norm_k(
    const float* __restrict__ x, float* __restrict__ o, const float* __restrict__ g)
{
    int t = blockIdx.x;
    const float4* xr = (const float4*)(x + (size_t)t * XD);
    float4 v0 = xr[threadIdx.x];
    float4 v1 = xr[threadIdx.x + 256];
    float s = v0.x*v0.x + v0.y*v0.y + v0.z*v0.z + v0.w*v0.w
            + v1.x*v1.x + v1.y*v1.y + v1.z*v1.z + v1.w*v1.w;
    for (int off = 16; off; off >>= 1) s += __shfl_xor_sync(0xffffffffu, s, off);
    __shared__ float red[8];
    int w = threadIdx.x >> 5, lane = threadIdx.x & 31;
    if (lane == 0) red[w] = s;
    __syncthreads();
    float tot = red[0] + red[1] + red[2] + red[3] + red[4] + red[5] + red[6] + red[7];
    float sc = g[0] / (sqrtf(tot) + 1e-8f);
    float4* orow = (float4*)(o + (size_t)t * XD);
    v0.x *= sc; v0.y *= sc; v0.z *= sc; v0.w *= sc;
    v1.x *= sc; v1.y *= sc; v1.z *= sc; v1.w *= sc;
    orow[threadIdx.x] = v0;
    orow[threadIdx.x + 256] = v1;
}

// ---------------- RoPE ----------------
__global__ __launch_bounds__(128) void rope_all(
    const float* __restrict__ q, const float* __restrict__ k,
    float* __restrict__ qhi, float* __restrict__ klo, float* __restrict__ khi)
{
    int t = blockIdx.x, j = threadIdx.x;
    int r = t & 63;
    float freq = powf(10000.f, -(float)j / 128.f);
    float slo, clo, shi, chi;
    sincosf((float)r * freq, &slo, &clo);
    sincosf((float)(64 + r) * freq, &shi, &chi);
    size_t base = (size_t)t * QD + 2 * j;
    float qe = q[base], qo = q[base + 1];
    qhi[base]     = qe * chi - qo * shi;
    qhi[base + 1] = qo * chi + qe * shi;
    float ke = k[base], ko = k[base + 1];
    klo[base]     = ke * clo - ko * slo;
    klo[base + 1] = ko * clo + ke * slo;
    khi[base]     = ke * chi - ko * shi;
    khi[base + 1] = ko * chi + ke * shi;
}

// ---------------- attention scores + softmax ----------------
__global__ __launch_bounds__(256) void attn_score(
    const float* __restrict__ qr, const float* __restrict__ klo,
    const float* __restrict__ khi, float* __restrict__ Aout)
{
    int w = threadIdx.x >> 5, lane = threadIdx.x & 31;
    int t = blockIdx.x * 8 + w;
    int c = t >> 6, r = t & 63;
    float qreg[8];
#pragma unroll
    for (int i = 0; i < 8; i++) qreg[i] = qr[(size_t)t * QD + i * 32 + lane];

    __shared__ float s_s[8][128];
    for (int m = 0; m < 128; m++) {
        float sc;
        if (c == 0 && m < 64) {
            sc = 0.f;
        } else {
            const float* kp = (m < 64)
                ? &klo[(size_t)((c - 1) * 64 + m) * QD]
                : &khi[(size_t)(c * 64 + (m - 64)) * QD];
            float d = 0.f;
#pragma unroll
            for (int i = 0; i < 8; i++) d += qreg[i] * kp[i * 32 + lane];
            for (int off = 16; off; off >>= 1) d += __shfl_xor_sync(0xffffffffu, d, off);
            sc = d * (1.f / 16.f);
        }
        if (m > r + 64) sc = -1e30f;
        if (lane == 0) s_s[w][m] = sc;
    }
    __syncwarp();
    float a0 = s_s[w][lane], a1 = s_s[w][lane + 32], a2 = s_s[w][lane + 64], a3 = s_s[w][lane + 96];
    float mx = fmaxf(fmaxf(a0, a1), fmaxf(a2, a3));
    for (int off = 16; off; off >>= 1) mx = fmaxf(mx, __shfl_xor_sync(0xffffffffu, mx, off));
    float e0 = expf(a0 - mx), e1 = expf(a1 - mx), e2 = expf(a2 - mx), e3 = expf(a3 - mx);
    float sm = e0 + e1 + e2 + e3;
    for (int off = 16; off; off >>= 1) sm += __shfl_xor_sync(0xffffffffu, sm, off);
    float inv = 1.f / sm;
    size_t ob = (size_t)t * 128;
    Aout[ob + lane]      = e0 * inv;
    Aout[ob + lane + 32] = e1 * inv;
    Aout[ob + lane + 64] = e2 * inv;
    Aout[ob + lane + 96] = e3 * inv;
}

// ---------------- y = A @ v2 ----------------
__global__ __launch_bounds__(256) void attn_av(
    const float* __restrict__ Aat, const float* __restrict__ v, float* __restrict__ y)
{
    int c = blockIdx.z, rg = blockIdx.y, ct = blockIdx.x;
    int col = ct * 256 + threadIdx.x;
    __shared__ float As[16][128];
    for (int idx = threadIdx.x; idx < 16 * 128; idx += 256) {
        int rr = idx >> 7, mm = idx & 127;
        As[rr][mm] = Aat[(size_t)(c * 64 + rg * 16 + rr) * 128 + mm];
    }
    __syncthreads();
    float acc[16];
#pragma unroll
    for (int r = 0; r < 16; r++) acc[r] = 0.f;
    int mstart = (c == 0) ? 64 : 0;
    for (int m = mstart; m < 128; m++) {
        float vv = v[(size_t)((c - 1) * 64 + m) * XD + col];
#pragma unroll
        for (int r = 0; r < 16; r++) acc[r] += As[r][m] * vv;
    }
#pragma unroll
    for (int r = 0; r < 16; r++)
        y[(size_t)(c * 64 + rg * 16 + r) * XD + col] = acc[r];
}

// ---------------- mem prep ----------------
__global__ void mem_prep(const float* __restrict__ beta, const float* __restrict__ decay,
                         float* __restrict__ gam, float* __restrict__ bg)
{
    int n = blockIdx.x, d = threadIdx.x;
    float g = (d < MD - DCD) ? 1.f : sigf(decay[n * DCD + (d - (MD - DCD))]);
    gam[n * MD + d] = g;
    bg[n * MD + d] = g * sigf(beta[n * MD + d]);
}

// ---------------- mem scan ----------------
__global__ __launch_bounds__(256) void mem_scan(
    const float* __restrict__ F, const float* __restrict__ V,
    const float* __restrict__ gam, const float* __restrict__ bg, float* __restrict__ mems)
{
    int n = blockIdx.x, d = threadIdx.x;
    float ga = gam[n * MD + d], b = bg[n * MD + d];
    float m = 0.f;
    float fn = F[n], vn = V[d];
    for (int t = 0; t < T; t++) {
        float f = fn, vv = vn;
        if (t + 1 < T) { fn = F[(t + 1) * MN + n]; vn = V[(size_t)(t + 1) * MD + d]; }
        m = (ga - f * b) * m + f * vv;
        mems[((size_t)t * MN + n) * MD + d] = m;
    }
}

// ---------------- transpose 256x256 ----------------
__global__ void transpose256(const float* __restrict__ W, float* __restrict__ WT)
{
    int rk = blockIdx.x, cd = threadIdx.x;
    WT[cd * MD + rk] = W[rk * MD + cd];
}

// ---------------- mem readout ----------------
__global__ __launch_bounds__(256) void mem_readout(
    const float* __restrict__ mems, const float* __restrict__ qk2,
    const float* __restrict__ lq, float* __restrict__ yout)
{
    int t = blockIdx.x;
    int tid = threadIdx.x, w = tid >> 5, lane = tid & 31;
    __shared__ float qs[MD];
    __shared__ float as[MN];
    qs[tid] = qk2[(size_t)t * MD + tid];
    __syncthreads();
    const float* mb = mems + (size_t)t * MN * MD;
#pragma unroll
    for (int mi = 0; mi < 8; mi++) {
        int m = w * 8 + mi;
        const float* mp = mb + m * MD;
        float d = 0.f;
#pragma unroll
        for (int i = 0; i < 8; i++) d += mp[i * 32 + lane] * qs[i * 32 + lane];
        for (int off = 16; off; off >>= 1) d += __shfl_xor_sync(0xffffffffu, d, off);
        if (lane == 0) as[m] = (d + lq[t * MN + m]) * (1.f / 16.f);
    }
    __syncthreads();
    if (w == 0) {
        float a0 = as[lane], a1 = as[lane + 32];
        float mx = fmaxf(a0, a1);
        for (int off = 16; off; off >>= 1) mx = fmaxf(mx, __shfl_xor_sync(0xffffffffu, mx, off));
        float e0 = expf(a0 - mx), e1 = expf(a1 - mx);
        float sm = e0 + e1;
        for (int off = 16; off; off >>= 1) sm += __shfl_xor_sync(0xffffffffu, sm, off);
        float inv = 1.f / sm;
        as[lane] = e0 * inv;
        as[lane + 32] = e1 * inv;
    }
    __syncthreads();
    float acc = 0.f;
    for (int m = 0; m < MN; m++) acc += as[m] * mb[m * MD + tid];
    yout[(size_t)t * MD + tid] = acc;
}

// ---------------- launcher ----------------
static float* sym(const void* s) { void* p = nullptr; cudaGetSymbolAddress(&p, s); return (float*)p; }

extern "C" void kernel_launch(void* const* d_in, const int* in_sizes, int n_in,
                              void* d_out, int out_size)
{
    const float* xs      = (const float*)d_in[0];
    const float* attn_q  = (const float*)d_in[1];
    const float* attn_k  = (const float*)d_in[2];
    const float* attn_v  = (const float*)d_in[3];
    const float* attn_o  = (const float*)d_in[4];
    const float* attn_r  = (const float*)d_in[5];
    const float* mem_f   = (const float*)d_in[6];
    const float* mem_q   = (const float*)d_in[7];
    const float* mem_k   = (const float*)d_in[8];
    const float* mem_v   = (const float*)d_in[9];
    const float* mem_o   = (const float*)d_in[10];
    const float* mem_r   = (const float*)d_in[11];
    const float* mem_beta= (const float*)d_in[12];
    const float* mem_dec = (const float*)d_in[13];
    const float* mem_l   = (const float*)d_in[14];
    const float* ff_in1  = (const float*)d_in[15];
    const float* ff_in2  = (const float*)d_in[16];
    const float* ff_out  = (const float*)d_in[17];
    const float* sn1     = (const float*)d_in[18];
    const float* sn2     = (const float*)d_in[19];
    float* out = (float*)d_out;

    float* xn   = sym(B_xn);   float* q_   = sym(B_q);    float* k_   = sym(B_k);
    float* qhi  = sym(B_qhi);  float* klo  = sym(B_klo);  float* khi  = sym(B_khi);
    float* v_   = sym(B_v);    float* A_   = sym(B_A);    float* y_   = sym(B_y);
    float* gate = sym(B_gate); float* accb = sym(B_acc);
    float* memF = sym(B_memF); float* memV = sym(B_memV); float* memQ = sym(B_memQ);
    float* gam  = sym(B_gam);  float* bg   = sym(B_bg);   float* wkT  = sym(B_wkT);
    float* qk2  = sym(B_qk2);  float* lq   = sym(B_lq);   float* mems = sym(B_mems);
    float* memY = sym(B_memY); float* x1   = sym(B_x1);   float* x2n  = sym(B_x2n);
    float* h1   = sym(B_h1);   float* h2   = sym(B_h2);

    const dim3 blk256(256);

    // 1. xn = scale_norm(xs, sn1)
    scale_norm_k<<<T, blk256>>>(xs, xn, sn1);
    // 2-5. attn projections + gate (bf16-split tensor path)
    gemm_mma<EPI_NONE><<<dim3(2, 16),  blk256>>>(xn, attn_q, q_, nullptr, nullptr, nullptr, T, QD, XD);
    gemm_mma<EPI_NONE><<<dim3(2, 16),  blk256>>>(q_, attn_k, k_, nullptr, nullptr, nullptr, T, QD, QD);
    gemm_mma<EPI_NONE><<<dim3(16, 16), blk256>>>(xn, attn_v, v_, nullptr, nullptr, nullptr, T, XD, XD);
    gemm_mma<EPI_NONE><<<dim3(16, 16), blk256>>>(xn, attn_r, gate, nullptr, nullptr, nullptr, T, XD, XD);
    // 6. attention core
    rope_all<<<T, 128>>>(q_, k_, qhi, klo, khi);
    attn_score<<<T / 8, blk256>>>(qhi, klo, khi, A_);
    attn_av<<<dim3(8, 4, 32), blk256>>>(A_, v_, y_);
    // 7. attn out = (y @ Wo^T) * sigmoid(gate)
    gemm_mma<EPI_GATE><<<dim3(16, 16), blk256>>>(y_, attn_o, accb, gate, nullptr, nullptr, T, XD, XD);
    // 8-11. mem projections + mem gate
    gemm_tn<EPI_SIGMOID><<<dim3(1, 16), blk256>>>(xn, mem_f, memF, nullptr, nullptr, nullptr, T, MN, XD);
    gemm_mma<EPI_NONE><<<dim3(2, 16),  blk256>>>(xn, mem_v, memV, nullptr, nullptr, nullptr, T, MD, XD);
    gemm_mma<EPI_NONE><<<dim3(2, 16),  blk256>>>(xn, mem_q, memQ, nullptr, nullptr, nullptr, T, MD, XD);
    gemm_mma<EPI_NONE><<<dim3(16, 16), blk256>>>(xn, mem_r, gate, nullptr, nullptr, nullptr, T, XD, XD);
    // 12-13. scan
    mem_prep<<<MN, MD>>>(mem_beta, mem_dec, gam, bg);
    mem_scan<<<MN, MD>>>(memF, memV, gam, bg, mems);
    // 14. readout
    transpose256<<<MD, MD>>>(mem_k, wkT);
    gemm_mma<EPI_NONE><<<dim3(2, 16), blk256>>>(memQ, wkT, qk2, nullptr, nullptr, nullptr, T, MD, MD);
    gemm_tn<EPI_NONE><<<dim3(1, 16), blk256>>>(memQ, mem_l, lq, nullptr, nullptr, nullptr, T, MN, MD);
    mem_readout<<<T, blk256>>>(mems, qk2, lq, memY);
    // 15. x1 = (memY @ mem_o^T)*sigmoid(gate) + attn_out + xs
    gemm_mma<EPI_GATE_ADD2><<<dim3(16, 16), blk256>>>(memY, mem_o, x1, gate, accb, xs, T, XD, MD);
    // 16-19. FF block
    scale_norm_k<<<T, blk256>>>(x1, x2n, sn2);
    gemm_mma<EPI_NONE><<<dim3(22, 16), blk256>>>(x2n, ff_in1, h1, nullptr, nullptr, nullptr, T, FFD, XD);
    gemm_mma<EPI_SILU_MUL><<<dim3(22, 16), blk256>>>(x2n, ff_in2, h2, h1, nullptr, nullptr, T, FFD, XD);
    gemm_mma<EPI_ADD><<<dim3(16, 16), blk256>>>(h2, ff_out, out, nullptr, x1, nullptr, T, XD, FFD);
}

// round 7
// speedup vs baseline: 1.6656x; 1.0365x over previous
#include <cuda_runtime.h>
#include <cuda_bf16.h>
#include <math.h>
#include <stdint.h>

// ---------------- problem dims ----------------
#define T    2048
#define XD   2048
#define QD   256     // X_D / REDUCE
#define MN   64      // M_N
#define MD   256     // M_D
#define DCD  64      // DECAY_D
#define FFD  2816    // FF_D
#define CH   64      // CHUNK

// ---------------- fp32 scratch ----------------
__device__ float B_xn  [(size_t)T*XD];
__device__ float B_q   [(size_t)T*QD];
__device__ float B_k   [(size_t)T*QD];
__device__ float B_qhi [(size_t)T*QD];
__device__ float B_klo [(size_t)T*QD];
__device__ float B_khi [(size_t)T*QD];
__device__ float B_v   [(size_t)T*XD];
__device__ float B_A   [(size_t)T*2*CH];
__device__ float B_y   [(size_t)T*XD];
__device__ float B_gate[(size_t)T*XD];
__device__ float B_acc [(size_t)T*XD];
__device__ float B_memF[(size_t)T*MN];
__device__ float B_memV[(size_t)T*MD];
__device__ float B_memQ[(size_t)T*MD];
__device__ float B_gam [(size_t)MN*MD];
__device__ float B_bg  [(size_t)MN*MD];
__device__ float B_wkT [(size_t)MD*MD];
__device__ float B_qk2 [(size_t)T*MD];
__device__ float B_lq  [(size_t)T*MN];
__device__ float B_mems[(size_t)T*MN*MD];   // 134 MB
__device__ float B_memY[(size_t)T*MD];
__device__ float B_x1  [(size_t)T*XD];
__device__ float B_x2n [(size_t)T*XD];
__device__ float B_h1  [(size_t)T*FFD];
__device__ float B_h2  [(size_t)T*FFD];

// ---------------- bf16 split scratch: A-side [hi|lo|hi], B-side [hi|hi|lo] ----------------
__device__ __nv_bfloat16 C_xn3  [(size_t)T*3*XD];
__device__ __nv_bfloat16 C_q3   [(size_t)T*3*QD];
__device__ __nv_bfloat16 C_y3   [(size_t)T*3*XD];
__device__ __nv_bfloat16 C_memQ3[(size_t)T*3*MD];
__device__ __nv_bfloat16 C_memY3[(size_t)T*3*MD];
__device__ __nv_bfloat16 C_x2n3 [(size_t)T*3*XD];
__device__ __nv_bfloat16 C_h23  [(size_t)T*3*FFD];
__device__ __nv_bfloat16 W_aq3  [(size_t)QD*3*XD];
__device__ __nv_bfloat16 W_ak3  [(size_t)QD*3*QD];
__device__ __nv_bfloat16 W_av3  [(size_t)XD*3*XD];
__device__ __nv_bfloat16 W_ao3  [(size_t)XD*3*XD];
__device__ __nv_bfloat16 W_ar3  [(size_t)XD*3*XD];
__device__ __nv_bfloat16 W_mv3  [(size_t)MD*3*XD];
__device__ __nv_bfloat16 W_mq3  [(size_t)MD*3*XD];
__device__ __nv_bfloat16 W_mr3  [(size_t)XD*3*XD];
__device__ __nv_bfloat16 W_wk3  [(size_t)MD*3*MD];
__device__ __nv_bfloat16 W_mo3  [(size_t)XD*3*MD];
__device__ __nv_bfloat16 W_f13  [(size_t)FFD*3*XD];
__device__ __nv_bfloat16 W_f23  [(size_t)FFD*3*XD];
__device__ __nv_bfloat16 W_fo3  [(size_t)XD*3*FFD];

__device__ __forceinline__ float sigf(float x) { return 1.f / (1.f + expf(-x)); }

enum { EPI_NONE = 0, EPI_SIGMOID, EPI_GATE, EPI_GATE_ADD2, EPI_SILU_MUL, EPI_ADD };

// hi = bf16x2(v0,v1) packed (v0 low half), lo = bf16x2 of residuals
__device__ __forceinline__ void split2(float v0, float v1, uint32_t& hi, uint32_t& lo)
{
    asm("cvt.rn.bf16x2.f32 %0, %1, %2;" : "=r"(hi) : "f"(v1), "f"(v0));
    float h0 = __uint_as_float(hi << 16);
    float h1 = __uint_as_float(hi & 0xffff0000u);
    asm("cvt.rn.bf16x2.f32 %0, %1, %2;" : "=r"(lo) : "f"(v1 - h1), "f"(v0 - h0));
}

// ---------------- split-conversion kernels (grid sized exactly: M*K/2 threads) ----------------
__global__ __launch_bounds__(256) void cvtA_k(const float* __restrict__ src,
                                              __nv_bfloat16* __restrict__ dst, int Khalf)
{
    size_t i = (size_t)blockIdx.x * 256 + threadIdx.x;
    size_t row = i / Khalf;
    int   cp  = (int)(i - row * Khalf);
    float2 v = ((const float2*)src)[i];
    uint32_t hi, lo; split2(v.x, v.y, hi, lo);
    uint32_t* dr = (uint32_t*)(dst + row * 6 * (size_t)Khalf);
    dr[cp]             = hi;   // seg0 hi
    dr[Khalf + cp]     = lo;   // seg1 lo
    dr[2 * Khalf + cp] = hi;   // seg2 hi
}

__global__ __launch_bounds__(256) void cvtB_k(const float* __restrict__ src,
                                              __nv_bfloat16* __restrict__ dst, int Khalf)
{
    size_t i = (size_t)blockIdx.x * 256 + threadIdx.x;
    size_t row = i / Khalf;
    int   cp  = (int)(i - row * Khalf);
    float2 v = ((const float2*)src)[i];
    uint32_t hi, lo; split2(v.x, v.y, hi, lo);
    uint32_t* dr = (uint32_t*)(dst + row * 6 * (size_t)Khalf);
    dr[cp]             = hi;   // seg0 hi
    dr[Khalf + cp]     = hi;   // seg1 hi
    dr[2 * Khalf + cp] = lo;   // seg2 lo
}

// =====================================================================
//  pure-bf16 tensor-core GEMM over packed K3 = 3K operands
//  C[M,N] = A3[M,K3] @ B3[N,K3]^T   (exact 3-term compensated product)
//  256 threads / 8 warps, tile 128x128, BK=32 bf16, double-buffered cp.async
//  warp grid 2(m) x 4(n): 64x32 per warp via m16n8k16; ldmatrix.x4 frags
// =====================================================================
#define AST 40   // bf16 smem row stride (80 B) -> conflict-free ldmatrix
#define STG (128 * AST)

template <int EPI>
__device__ __forceinline__ float epi_apply(float c, size_t idx,
                                           const float* __restrict__ G,
                                           const float* __restrict__ R1,
                                           const float* __restrict__ R2)
{
    if (EPI == EPI_SIGMOID)        c = sigf(c);
    else if (EPI == EPI_GATE)      c = c * sigf(G[idx]);
    else if (EPI == EPI_GATE_ADD2) c = c * sigf(G[idx]) + R1[idx] + R2[idx];
    else if (EPI == EPI_SILU_MUL)  { float g = G[idx]; c = c * (g * sigf(g)); }
    else if (EPI == EPI_ADD)       c = c + R1[idx];
    return c;
}

__device__ __forceinline__ void mma16(float* c, uint32_t a0, uint32_t a1, uint32_t a2, uint32_t a3,
                                      uint32_t b0, uint32_t b1)
{
    asm volatile(
        "mma.sync.aligned.m16n8k16.row.col.f32.bf16.bf16.f32 "
        "{%0,%1,%2,%3}, {%4,%5,%6,%7}, {%8,%9}, {%0,%1,%2,%3};"
        : "+f"(c[0]), "+f"(c[1]), "+f"(c[2]), "+f"(c[3])
        : "r"(a0), "r"(a1), "r"(a2), "r"(a3), "r"(b0), "r"(b1));
}

__device__ __forceinline__ void ldsm4(uint32_t addr, uint32_t& r0, uint32_t& r1,
                                      uint32_t& r2, uint32_t& r3)
{
    asm volatile("ldmatrix.sync.aligned.m8n8.x4.shared.b16 {%0,%1,%2,%3}, [%4];"
                 : "=r"(r0), "=r"(r1), "=r"(r2), "=r"(r3) : "r"(addr));
}

template <int EPI>
__global__ __launch_bounds__(256) void gemm_bf16(
    const __nv_bfloat16* __restrict__ A, const __nv_bfloat16* __restrict__ B,
    float* __restrict__ D,
    const float* __restrict__ G, const float* __restrict__ R1, const float* __restrict__ R2,
    int M, int N, int K3)
{
    __shared__ __nv_bfloat16 As[2][STG];
    __shared__ __nv_bfloat16 Bs[2][STG];

    const int tid  = threadIdx.x;
    const int wid  = tid >> 5, lane = tid & 31;
    const int wm   = wid & 1, wn = wid >> 1;   // 2(m) x 4(n)
    const int g    = lane >> 2, tg = lane & 3;
    const int m0   = blockIdx.y * 128;
    const int n0   = blockIdx.x * 128;

    float acc[4][4][4];
#pragma unroll
    for (int mt = 0; mt < 4; mt++)
#pragma unroll
        for (int nt = 0; nt < 4; nt++)
#pragma unroll
            for (int e = 0; e < 4; e++) acc[mt][nt][e] = 0.f;

    const int KT = K3 / 32;

    const uint32_t asBase = (uint32_t)__cvta_generic_to_shared(&As[0][0]);
    const uint32_t bsBase = (uint32_t)__cvta_generic_to_shared(&Bs[0][0]);
    const uint32_t stageBytes = STG * 2;

    // cp.async: thread t -> row = t>>1, 16 bf16 starting at (t&1)*16
    const int ldRow = tid >> 1;
    const int ldOff = (tid & 1) * 16;
    const __nv_bfloat16* agRow = A + (size_t)(m0 + ldRow) * K3 + ldOff;
    const __nv_bfloat16* bgRow = B + (size_t)(n0 + ldRow) * K3 + ldOff;
    const uint32_t asDst = asBase + (ldRow * AST + ldOff) * 2;
    const uint32_t bsDst = bsBase + (ldRow * AST + ldOff) * 2;

    // ldmatrix lane mapping (x4: tiles [r0-7,k0-7],[r8-15,k0-7],[r0-7,k8-15],[r8-15,k8-15])
    const int lmT   = lane >> 3;
    const int lmRow = (lmT & 1) * 8 + (lane & 7);
    const int lmCol = (lmT >> 1) * 8;

#define LOAD3(buf, kt)                                                                      \
    {                                                                                       \
        const __nv_bfloat16* ga = agRow + (kt) * 32;                                        \
        const __nv_bfloat16* gb = bgRow + (kt) * 32;                                        \
        uint32_t da = asDst + (buf) * stageBytes;                                           \
        uint32_t db = bsDst + (buf) * stageBytes;                                           \
        asm volatile("cp.async.ca.shared.global [%0], [%1], 16;" :: "r"(da),      "l"(ga));     \
        asm volatile("cp.async.ca.shared.global [%0], [%1], 16;" :: "r"(da + 16), "l"(ga + 8)); \
        asm volatile("cp.async.ca.shared.global [%0], [%1], 16;" :: "r"(db),      "l"(gb));     \
        asm volatile("cp.async.ca.shared.global [%0], [%1], 16;" :: "r"(db + 16), "l"(gb + 8)); \
    }

    LOAD3(0, 0);
    asm volatile("cp.async.commit_group;");

    for (int kt = 0; kt < KT; kt++) {
        if (kt + 1 < KT) LOAD3((kt + 1) & 1, kt + 1);
        asm volatile("cp.async.commit_group;");
        asm volatile("cp.async.wait_group 1;");
        __syncthreads();

        const uint32_t aBuf = asBase + (kt & 1) * stageBytes;
        const uint32_t bBuf = bsBase + (kt & 1) * stageBytes;

#pragma unroll
        for (int ks = 0; ks < 2; ks++) {
            const int kb = ks * 16;
            // B fragments: two x4 loads cover n 0-15 and 16-31 of this warp
            uint32_t bf[4][2];
#pragma unroll
            for (int h = 0; h < 2; h++) {
                uint32_t addr = bBuf + ((wn * 32 + h * 16 + lmRow) * AST + kb + lmCol) * 2;
                ldsm4(addr, bf[2 * h][0], bf[2 * h + 1][0], bf[2 * h][1], bf[2 * h + 1][1]);
            }
            // A fragments: one x4 per mt
            uint32_t af[4][4];
#pragma unroll
            for (int mt = 0; mt < 4; mt++) {
                uint32_t addr = aBuf + ((wm * 64 + mt * 16 + lmRow) * AST + kb + lmCol) * 2;
                ldsm4(addr, af[mt][0], af[mt][1], af[mt][2], af[mt][3]);
            }
#pragma unroll
            for (int mt = 0; mt < 4; mt++)
#pragma unroll
                for (int nt = 0; nt < 4; nt++)
                    mma16(acc[mt][nt], af[mt][0], af[mt][1], af[mt][2], af[mt][3],
                          bf[nt][0], bf[nt][1]);
        }
        __syncthreads();
    }
#undef LOAD3

    // epilogue
#pragma unroll
    for (int mt = 0; mt < 4; mt++) {
        int r0 = m0 + wm * 64 + mt * 16 + g;
#pragma unroll
        for (int nt = 0; nt < 4; nt++) {
            int col = n0 + wn * 32 + nt * 8 + tg * 2;
            size_t i0 = (size_t)r0 * N + col;
            size_t i1 = i0 + (size_t)8 * N;
            float2 o0, o1;
            o0.x = epi_apply<EPI>(acc[mt][nt][0], i0,     G, R1, R2);
            o0.y = epi_apply<EPI>(acc[mt][nt][1], i0 + 1, G, R1, R2);
            o1.x = epi_apply<EPI>(acc[mt][nt][2], i1,     G, R1, R2);
            o1.y = epi_apply<EPI>(acc[mt][nt][3], i1 + 1, G, R1, R2);
            *(float2*)&D[i0] = o0;
            *(float2*)&D[i1] = o1;
        }
    }
}

// ---------------- legacy FFMA GEMM (tiny-N cases: N=64) ----------------
#define BM 128
#define BN 128
#define BKK 16

template <int EPI>
__global__ __launch_bounds__(256) void gemm_tn(
    const float* __restrict__ A, const float* __restrict__ B, float* __restrict__ D,
    const float* __restrict__ G, const float* __restrict__ R1, const float* __restrict__ R2,
    int M, int N, int K)
{
    __shared__ float As[BKK][BM + 4];
    __shared__ float Bs[BKK][BN + 4];

    const int tid = threadIdx.x;
    const int m0 = blockIdx.y * BM;
    const int n0 = blockIdx.x * BN;
    const int tx = tid & 15;
    const int ty = tid >> 4;

    float acc[8][8];
#pragma unroll
    for (int i = 0; i < 8; i++)
#pragma unroll
        for (int j = 0; j < 8; j++) acc[i][j] = 0.f;

    for (int k0 = 0; k0 < K; k0 += BKK) {
#pragma unroll
        for (int l = 0; l < 2; l++) {
            int qi  = tid + l * 256;
            int row = qi >> 2;
            int kk  = (qi & 3) * 4;
            float4 av = *(const float4*)&A[(size_t)(m0 + row) * K + k0 + kk];
            As[kk + 0][row] = av.x; As[kk + 1][row] = av.y;
            As[kk + 2][row] = av.z; As[kk + 3][row] = av.w;
        }
#pragma unroll
        for (int l = 0; l < 2; l++) {
            int qi  = tid + l * 256;
            int row = qi >> 2;
            int kk  = (qi & 3) * 4;
            float4 bv = make_float4(0.f, 0.f, 0.f, 0.f);
            if (n0 + row < N) bv = *(const float4*)&B[(size_t)(n0 + row) * K + k0 + kk];
            Bs[kk + 0][row] = bv.x; Bs[kk + 1][row] = bv.y;
            Bs[kk + 2][row] = bv.z; Bs[kk + 3][row] = bv.w;
        }
        __syncthreads();

#pragma unroll
        for (int kk = 0; kk < BKK; kk++) {
            float a[8], b[8];
#pragma unroll
            for (int i = 0; i < 8; i++) a[i] = As[kk][ty * 8 + i];
#pragma unroll
            for (int j = 0; j < 8; j++) b[j] = Bs[kk][tx * 8 + j];
#pragma unroll
            for (int i = 0; i < 8; i++)
#pragma unroll
                for (int j = 0; j < 8; j++) acc[i][j] += a[i] * b[j];
        }
        __syncthreads();
    }

#pragma unroll
    for (int i = 0; i < 8; i++) {
        int row = m0 + ty * 8 + i;
#pragma unroll
        for (int j = 0; j < 8; j++) {
            int col = n0 + tx * 8 + j;
            if (col < N) {
                size_t idx = (size_t)row * N + col;
                D[idx] = epi_apply<EPI>(acc[i][j], idx, G, R1, R2);
            }
        }
    }
}

// ---------------- scale_norm ----------------
__global__ __launch_bounds__(256) void scale_norm_k(
    const float* __restrict__ x, float* __restrict__ o, const float* __restrict__ g)
{
    int t = blockIdx.x;
    const float4* xr = (const float4*)(x + (size_t)t * XD);
    float4 v0 = xr[threadIdx.x];
    float4 v1 = xr[threadIdx.x + 256];
    float s = v0.x*v0.x + v0.y*v0.y + v0.z*v0.z + v0.w*v0.w
            + v1.x*v1.x + v1.y*v1.y + v1.z*v1.z + v1.w*v1.w;
    for (int off = 16; off; off >>= 1) s += __shfl_xor_sync(0xffffffffu, s, off);
    __shared__ float red[8];
    int w = threadIdx.x >> 5, lane = threadIdx.x & 31;
    if (lane == 0) red[w] = s;
    __syncthreads();
    float tot = red[0] + red[1] + red[2] + red[3] + red[4] + red[5] + red[6] + red[7];
    float sc = g[0] / (sqrtf(tot) + 1e-8f);
    float4* orow = (float4*)(o + (size_t)t * XD);
    v0.x *= sc; v0.y *= sc; v0.z *= sc; v0.w *= sc;
    v1.x *= sc; v1.y *= sc; v1.z *= sc; v1.w *= sc;
    orow[threadIdx.x] = v0;
    orow[threadIdx.x + 256] = v1;
}

// ---------------- RoPE ----------------
__global__ __launch_bounds__(128) void rope_all(
    const float* __restrict__ q, const float* __restrict__ k,
    float* __restrict__ qhi, float* __restrict__ klo, float* __restrict__ khi)
{
    int t = blockIdx.x, j = threadIdx.x;
    int r = t & 63;
    float freq = powf(10000.f, -(float)j / 128.f);
    float slo, clo, shi, chi;
    sincosf((float)r * freq, &slo, &clo);
    sincosf((float)(64 + r) * freq, &shi, &chi);
    size_t base = (size_t)t * QD + 2 * j;
    float qe = q[base], qo = q[base + 1];
    qhi[base]     = qe * chi - qo * shi;
    qhi[base + 1] = qo * chi + qe * shi;
    float ke = k[base], ko = k[base + 1];
    klo[base]     = ke * clo - ko * slo;
    klo[base + 1] = ko * clo + ke * slo;
    khi[base]     = ke * chi - ko * shi;
    khi[base + 1] = ko * chi + ke * shi;
}

// ---------------- attention scores + softmax ----------------
__global__ __launch_bounds__(256) void attn_score(
    const float* __restrict__ qr, const float* __restrict__ klo,
    const float* __restrict__ khi, float* __restrict__ Aout)
{
    int w = threadIdx.x >> 5, lane = threadIdx.x & 31;
    int t = blockIdx.x * 8 + w;
    int c = t >> 6, r = t & 63;
    float qreg[8];
#pragma unroll
    for (int i = 0; i < 8; i++) qreg[i] = qr[(size_t)t * QD + i * 32 + lane];

    __shared__ float s_s[8][128];
    for (int m = 0; m < 128; m++) {
        float sc;
        if (c == 0 && m < 64) {
            sc = 0.f;
        } else {
            const float* kp = (m < 64)
                ? &klo[(size_t)((c - 1) * 64 + m) * QD]
                : &khi[(size_t)(c * 64 + (m - 64)) * QD];
            float d = 0.f;
#pragma unroll
            for (int i = 0; i < 8; i++) d += qreg[i] * kp[i * 32 + lane];
            for (int off = 16; off; off >>= 1) d += __shfl_xor_sync(0xffffffffu, d, off);
            sc = d * (1.f / 16.f);
        }
        if (m > r + 64) sc = -1e30f;
        if (lane == 0) s_s[w][m] = sc;
    }
    __syncwarp();
    float a0 = s_s[w][lane], a1 = s_s[w][lane + 32], a2 = s_s[w][lane + 64], a3 = s_s[w][lane + 96];
    float mx = fmaxf(fmaxf(a0, a1), fmaxf(a2, a3));
    for (int off = 16; off; off >>= 1) mx = fmaxf(mx, __shfl_xor_sync(0xffffffffu, mx, off));
    float e0 = expf(a0 - mx), e1 = expf(a1 - mx), e2 = expf(a2 - mx), e3 = expf(a3 - mx);
    float sm = e0 + e1 + e2 + e3;
    for (int off = 16; off; off >>= 1) sm += __shfl_xor_sync(0xffffffffu, sm, off);
    float inv = 1.f / sm;
    size_t ob = (size_t)t * 128;
    Aout[ob + lane]      = e0 * inv;
    Aout[ob + lane + 32] = e1 * inv;
    Aout[ob + lane + 64] = e2 * inv;
    Aout[ob + lane + 96] = e3 * inv;
}

// ---------------- y = A @ v2 ----------------
__global__ __launch_bounds__(256) void attn_av(
    const float* __restrict__ Aat, const float* __restrict__ v, float* __restrict__ y)
{
    int c = blockIdx.z, rg = blockIdx.y, ct = blockIdx.x;
    int col = ct * 256 + threadIdx.x;
    __shared__ float As[16][128];
    for (int idx = threadIdx.x; idx < 16 * 128; idx += 256) {
        int rr = idx >> 7, mm = idx & 127;
        As[rr][mm] = Aat[(size_t)(c * 64 + rg * 16 + rr) * 128 + mm];
    }
    __syncthreads();
    float acc[16];
#pragma unroll
    for (int r = 0; r < 16; r++) acc[r] = 0.f;
    int mstart = (c == 0) ? 64 : 0;
    for (int m = mstart; m < 128; m++) {
        float vv = v[(size_t)((c - 1) * 64 + m) * XD + col];
#pragma unroll
        for (int r = 0; r < 16; r++) acc[r] += As[r][m] * vv;
    }
#pragma unroll
    for (int r = 0; r < 16; r++)
        y[(size_t)(c * 64 + rg * 16 + r) * XD + col] = acc[r];
}

// ---------------- mem prep ----------------
__global__ void mem_prep(const float* __restrict__ beta, const float* __restrict__ decay,
                         float* __restrict__ gam, float* __restrict__ bg)
{
    int n = blockIdx.x, d = threadIdx.x;
    float g = (d < MD - DCD) ? 1.f : sigf(decay[n * DCD + (d - (MD - DCD))]);
    gam[n * MD + d] = g;
    bg[n * MD + d] = g * sigf(beta[n * MD + d]);
}

// ---------------- mem scan ----------------
__global__ __launch_bounds__(256) void mem_scan(
    const float* __restrict__ F, const float* __restrict__ V,
    const float* __restrict__ gam, const float* __restrict__ bg, float* __restrict__ mems)
{
    int n = blockIdx.x, d = threadIdx.x;
    float ga = gam[n * MD + d], b = bg[n * MD + d];
    float m = 0.f;
    float fn = F[n], vn = V[d];
    for (int t = 0; t < T; t++) {
        float f = fn, vv = vn;
        if (t + 1 < T) { fn = F[(t + 1) * MN + n]; vn = V[(size_t)(t + 1) * MD + d]; }
        m = (ga - f * b) * m + f * vv;
        mems[((size_t)t * MN + n) * MD + d] = m;
    }
}

// ---------------- transpose 256x256 ----------------
__global__ void transpose256(const float* __restrict__ W, float* __restrict__ WT)
{
    int rk = blockIdx.x, cd = threadIdx.x;
    WT[cd * MD + rk] = W[rk * MD + cd];
}

// ---------------- mem readout ----------------
__global__ __launch_bounds__(256) void mem_readout(
    const float* __restrict__ mems, const float* __restrict__ qk2,
    const float* __restrict__ lq, float* __restrict__ yout)
{
    int t = blockIdx.x;
    int tid = threadIdx.x, w = tid >> 5, lane = tid & 31;
    __shared__ float qs[MD];
    __shared__ float as[MN];
    qs[tid] = qk2[(size_t)t * MD + tid];
    __syncthreads();
    const float* mb = mems + (size_t)t * MN * MD;
#pragma unroll
    for (int mi = 0; mi < 8; mi++) {
        int m = w * 8 + mi;
        const float* mp = mb + m * MD;
        float d = 0.f;
#pragma unroll
        for (int i = 0; i < 8; i++) d += mp[i * 32 + lane] * qs[i * 32 + lane];
        for (int off = 16; off; off >>= 1) d += __shfl_xor_sync(0xffffffffu, d, off);
        if (lane == 0) as[m] = (d + lq[t * MN + m]) * (1.f / 16.f);
    }
    __syncthreads();
    if (w == 0) {
        float a0 = as[lane], a1 = as[lane + 32];
        float mx = fmaxf(a0, a1);
        for (int off = 16; off; off >>= 1) mx = fmaxf(mx, __shfl_xor_sync(0xffffffffu, mx, off));
        float e0 = expf(a0 - mx), e1 = expf(a1 - mx);
        float sm = e0 + e1;
        for (int off = 16; off; off >>= 1) sm += __shfl_xor_sync(0xffffffffu, sm, off);
        float inv = 1.f / sm;
        as[lane] = e0 * inv;
        as[lane + 32] = e1 * inv;
    }
    __syncthreads();
    float acc = 0.f;
    for (int m = 0; m < MN; m++) acc += as[m] * mb[m * MD + tid];
    yout[(size_t)t * MD + tid] = acc;
}

// ---------------- launcher ----------------
static float* sym(const void* s) { void* p = nullptr; cudaGetSymbolAddress(&p, s); return (float*)p; }
static __nv_bfloat16* symb(const void* s) { void* p = nullptr; cudaGetSymbolAddress(&p, s); return (__nv_bfloat16*)p; }

extern "C" void kernel_launch(void* const* d_in, const int* in_sizes, int n_in,
                              void* d_out, int out_size)
{
    const float* xs      = (const float*)d_in[0];
    const float* attn_q  = (const float*)d_in[1];
    const float* attn_k  = (const float*)d_in[2];
    const float* attn_v  = (const float*)d_in[3];
    const float* attn_o  = (const float*)d_in[4];
    const float* attn_r  = (const float*)d_in[5];
    const float* mem_f   = (const float*)d_in[6];
    const float* mem_q   = (const float*)d_in[7];
    const float* mem_k   = (const float*)d_in[8];
    const float* mem_v   = (const float*)d_in[9];
    const float* mem_o   = (const float*)d_in[10];
    const float* mem_r   = (const float*)d_in[11];
    const float* mem_beta= (const float*)d_in[12];
    const float* mem_dec = (const float*)d_in[13];
    const float* mem_l   = (const float*)d_in[14];
    const float* ff_in1  = (const float*)d_in[15];
    const float* ff_in2  = (const float*)d_in[16];
    const float* ff_out  = (const float*)d_in[17];
    const float* sn1     = (const float*)d_in[18];
    const float* sn2     = (const float*)d_in[19];
    float* out = (float*)d_out;

    float* xn   = sym(B_xn);   float* q_   = sym(B_q);    float* k_   = sym(B_k);
    float* qhi  = sym(B_qhi);  float* klo  = sym(B_klo);  float* khi  = sym(B_khi);
    float* v_   = sym(B_v);    float* A_   = sym(B_A);    float* y_   = sym(B_y);
    float* gate = sym(B_gate); float* accb = sym(B_acc);
    float* memF = sym(B_memF); float* memV = sym(B_memV); float* memQ = sym(B_memQ);
    float* gam  = sym(B_gam);  float* bg   = sym(B_bg);   float* wkT  = sym(B_wkT);
    float* qk2  = sym(B_qk2);  float* lq   = sym(B_lq);   float* mems = sym(B_mems);
    float* memY = sym(B_memY); float* x1   = sym(B_x1);   float* x2n  = sym(B_x2n);
    float* h1   = sym(B_h1);   float* h2   = sym(B_h2);

    __nv_bfloat16* xn3  = symb(C_xn3);  __nv_bfloat16* q3   = symb(C_q3);
    __nv_bfloat16* y3   = symb(C_y3);   __nv_bfloat16* memQ3= symb(C_memQ3);
    __nv_bfloat16* memY3= symb(C_memY3);__nv_bfloat16* x2n3 = symb(C_x2n3);
    __nv_bfloat16* h23  = symb(C_h23);
    __nv_bfloat16* aq3  = symb(W_aq3);  __nv_bfloat16* ak3  = symb(W_ak3);
    __nv_bfloat16* av3  = symb(W_av3);  __nv_bfloat16* ao3  = symb(W_ao3);
    __nv_bfloat16* ar3  = symb(W_ar3);  __nv_bfloat16* mv3  = symb(W_mv3);
    __nv_bfloat16* mq3  = symb(W_mq3);  __nv_bfloat16* mr3  = symb(W_mr3);
    __nv_bfloat16* wk3  = symb(W_wk3);  __nv_bfloat16* mo3  = symb(W_mo3);
    __nv_bfloat16* f13  = symb(W_f13);  __nv_bfloat16* f23  = symb(W_f23);
    __nv_bfloat16* fo3  = symb(W_fo3);

    const dim3 blk256(256);
#define CVTA(src, dst, M_, K_) cvtA_k<<<(unsigned)((size_t)(M_) * (K_) / 2 / 256), blk256>>>(src, dst, (K_) / 2)
#define CVTB(src, dst, M_, K_) cvtB_k<<<(unsigned)((size_t)(M_) * (K_) / 2 / 256), blk256>>>(src, dst, (K_) / 2)

    // weight conversions (independent of activations)
    CVTB(attn_q, aq3, QD, XD);
    CVTB(attn_k, ak3, QD, QD);
    CVTB(attn_v, av3, XD, XD);
    CVTB(attn_o, ao3, XD, XD);
    CVTB(attn_r, ar3, XD, XD);
    CVTB(mem_v,  mv3, MD, XD);
    CVTB(mem_q,  mq3, MD, XD);
    CVTB(mem_r,  mr3, XD, XD);
    CVTB(mem_o,  mo3, XD, MD);
    CVTB(ff_in1, f13, FFD, XD);
    CVTB(ff_in2, f23, FFD, XD);
    CVTB(ff_out, fo3, XD, FFD);
    transpose256<<<MD, MD>>>(mem_k, wkT);
    CVTB(wkT, wk3, MD, MD);

    // 1. xn = scale_norm(xs, sn1); split
    scale_norm_k<<<T, blk256>>>(xs, xn, sn1);
    CVTA(xn, xn3, T, XD);
    // 2-5. attn projections + gate
    gemm_bf16<EPI_NONE><<<dim3(2, 16),  blk256>>>(xn3, aq3, q_, nullptr, nullptr, nullptr, T, QD, 3 * XD);
    CVTA(q_, q3, T, QD);
    gemm_bf16<EPI_NONE><<<dim3(2, 16),  blk256>>>(q3, ak3, k_, nullptr, nullptr, nullptr, T, QD, 3 * QD);
    gemm_bf16<EPI_NONE><<<dim3(16, 16), blk256>>>(xn3, av3, v_, nullptr, nullptr, nullptr, T, XD, 3 * XD);
    gemm_bf16<EPI_NONE><<<dim3(16, 16), blk256>>>(xn3, ar3, gate, nullptr, nullptr, nullptr, T, XD, 3 * XD);
    // 6. attention core
    rope_all<<<T, 128>>>(q_, k_, qhi, klo, khi);
    attn_score<<<T / 8, blk256>>>(qhi, klo, khi, A_);
    attn_av<<<dim3(8, 4, 32), blk256>>>(A_, v_, y_);
    // 7. attn out = (y @ Wo^T) * sigmoid(gate)
    CVTA(y_, y3, T, XD);
    gemm_bf16<EPI_GATE><<<dim3(16, 16), blk256>>>(y3, ao3, accb, gate, nullptr, nullptr, T, XD, 3 * XD);
    // 8-11. mem projections + mem gate
    gemm_tn<EPI_SIGMOID><<<dim3(1, 16), blk256>>>(xn, mem_f, memF, nullptr, nullptr, nullptr, T, MN, XD);
    gemm_bf16<EPI_NONE><<<dim3(2, 16),  blk256>>>(xn3, mv3, memV, nullptr, nullptr, nullptr, T, MD, 3 * XD);
    gemm_bf16<EPI_NONE><<<dim3(2, 16),  blk256>>>(xn3, mq3, memQ, nullptr, nullptr, nullptr, T, MD, 3 * XD);
    gemm_bf16<EPI_NONE><<<dim3(16, 16), blk256>>>(xn3, mr3, gate, nullptr, nullptr, nullptr, T, XD, 3 * XD);
    // 12-13. scan
    mem_prep<<<MN, MD>>>(mem_beta, mem_dec, gam, bg);
    mem_scan<<<MN, MD>>>(memF, memV, gam, bg, mems);
    // 14. readout
    CVTA(memQ, memQ3, T, MD);
    gemm_bf16<EPI_NONE><<<dim3(2, 16), blk256>>>(memQ3, wk3, qk2, nullptr, nullptr, nullptr, T, MD, 3 * MD);
    gemm_tn<EPI_NONE><<<dim3(1, 16), blk256>>>(memQ, mem_l, lq, nullptr, nullptr, nullptr, T, MN, MD);
    mem_readout<<<T, blk256>>>(mems, qk2, lq, memY);
    // 15. x1 = (memY @ mem_o^T)*sigmoid(gate) + attn_out + xs
    CVTA(memY, memY3, T, MD);
    gemm_bf16<EPI_GATE_ADD2><<<dim3(16, 16), blk256>>>(memY3, mo3, x1, gate, accb, xs, T, XD, 3 * MD);
    // 16-19. FF block
    scale_norm_k<<<T, blk256>>>(x1, x2n, sn2);
    CVTA(x2n, x2n3, T, XD);
    gemm_bf16<EPI_NONE><<<dim3(22, 16), blk256>>>(x2n3, f13, h1, nullptr, nullptr, nullptr, T, FFD, 3 * XD);
    gemm_bf16<EPI_SILU_MUL><<<dim3(22, 16), blk256>>>(x2n3, f23, h2, h1, nullptr, nullptr, T, FFD, 3 * XD);
    CVTA(h2, h23, T, FFD);
    gemm_bf16<EPI_ADD><<<dim3(16, 16), blk256>>>(h23, fo3, out, nullptr, x1, nullptr, T, XD, 3 * FFD);
#undef CVTA
#undef CVTB
}

// round 9
// speedup vs baseline: 1.9796x; 1.1885x over previous
#include <cuda_runtime.h>
#include <cuda_bf16.h>
#include <math.h>
#include <stdint.h>

// ---------------- problem dims ----------------
#define T    2048
#define XD   2048
#define QD   256
#define MN   64
#define MD   256
#define DCD  64
#define FFD  2816
#define CH   64

// ---------------- fp32 scratch ----------------
__device__ float B_xn  [(size_t)T*XD];
__device__ float B_q   [(size_t)T*QD];
__device__ float B_k   [(size_t)T*QD];
__device__ float B_qhi [(size_t)T*QD];
__device__ float B_klo [(size_t)T*QD];
__device__ float B_khi [(size_t)T*QD];
__device__ float B_v   [(size_t)T*XD];
__device__ float B_A   [(size_t)T*2*CH];
__device__ float B_gate[(size_t)T*XD];
__device__ float B_acc [(size_t)T*XD];
__device__ float B_memF[(size_t)T*MN];
__device__ float B_memV[(size_t)T*MD];
__device__ float B_memQ[(size_t)T*MD];
__device__ float B_gam [(size_t)MN*MD];
__device__ float B_bg  [(size_t)MN*MD];
__device__ float B_wkT [(size_t)MD*MD];
__device__ float B_qk2 [(size_t)T*MD];
__device__ float B_lq  [(size_t)T*MN];
__device__ float B_mems[(size_t)T*MN*MD];
__device__ float B_memY[(size_t)T*MD];
__device__ float B_x1  [(size_t)T*XD];
__device__ float B_x2n [(size_t)T*XD];
__device__ float B_h1  [(size_t)T*FFD];

// ---------------- bf16 split scratch: A-side [hi|lo|hi], B-side [hi|hi|lo] ----------------
__device__ __nv_bfloat16 C_xn3  [(size_t)T*3*XD];
__device__ __nv_bfloat16 C_q3   [(size_t)T*3*QD];
__device__ __nv_bfloat16 C_y3   [(size_t)T*3*XD];
__device__ __nv_bfloat16 C_memQ3[(size_t)T*3*MD];
__device__ __nv_bfloat16 C_memY3[(size_t)T*3*MD];
__device__ __nv_bfloat16 C_x2n3 [(size_t)T*3*XD];
__device__ __nv_bfloat16 C_h23  [(size_t)T*3*FFD];
__device__ __nv_bfloat16 W_aq3  [(size_t)QD*3*XD];
__device__ __nv_bfloat16 W_ak3  [(size_t)QD*3*QD];
__device__ __nv_bfloat16 W_av3  [(size_t)XD*3*XD];
__device__ __nv_bfloat16 W_ao3  [(size_t)XD*3*XD];
__device__ __nv_bfloat16 W_ar3  [(size_t)XD*3*XD];
__device__ __nv_bfloat16 W_mv3  [(size_t)MD*3*XD];
__device__ __nv_bfloat16 W_mq3  [(size_t)MD*3*XD];
__device__ __nv_bfloat16 W_mr3  [(size_t)XD*3*XD];
__device__ __nv_bfloat16 W_wk3  [(size_t)MD*3*MD];
__device__ __nv_bfloat16 W_mo3  [(size_t)XD*3*MD];
__device__ __nv_bfloat16 W_f13  [(size_t)FFD*3*XD];
__device__ __nv_bfloat16 W_f23  [(size_t)FFD*3*XD];
__device__ __nv_bfloat16 W_fo3  [(size_t)XD*3*FFD];

__device__ __forceinline__ float sigf(float x) { return 1.f / (1.f + expf(-x)); }

enum { EPI_NONE = 0, EPI_SIGMOID, EPI_GATE, EPI_GATE_ADD2, EPI_SILU_MUL_SPLIT, EPI_ADD };

__device__ __forceinline__ void split2(float v0, float v1, uint32_t& hi, uint32_t& lo)
{
    asm("cvt.rn.bf16x2.f32 %0, %1, %2;" : "=r"(hi) : "f"(v1), "f"(v0));
    float h0 = __uint_as_float(hi << 16);
    float h1 = __uint_as_float(hi & 0xffff0000u);
    asm("cvt.rn.bf16x2.f32 %0, %1, %2;" : "=r"(lo) : "f"(v1 - h1), "f"(v0 - h0));
}

// ---------------- split-conversion kernels ----------------
__global__ __launch_bounds__(256) void cvtA_k(const float* __restrict__ src,
                                              __nv_bfloat16* __restrict__ dst, int Khalf)
{
    size_t i = (size_t)blockIdx.x * 256 + threadIdx.x;
    size_t row = i / Khalf;
    int   cp  = (int)(i - row * Khalf);
    float2 v = ((const float2*)src)[i];
    uint32_t hi, lo; split2(v.x, v.y, hi, lo);
    uint32_t* dr = (uint32_t*)(dst + row * 6 * (size_t)Khalf);
    dr[cp]             = hi;
    dr[Khalf + cp]     = lo;
    dr[2 * Khalf + cp] = hi;
}

__global__ __launch_bounds__(256) void cvtB_k(const float* __restrict__ src,
                                              __nv_bfloat16* __restrict__ dst, int Khalf)
{
    size_t i = (size_t)blockIdx.x * 256 + threadIdx.x;
    size_t row = i / Khalf;
    int   cp  = (int)(i - row * Khalf);
    float2 v = ((const float2*)src)[i];
    uint32_t hi, lo; split2(v.x, v.y, hi, lo);
    uint32_t* dr = (uint32_t*)(dst + row * 6 * (size_t)Khalf);
    dr[cp]             = hi;
    dr[Khalf + cp]     = hi;
    dr[2 * Khalf + cp] = lo;
}

// =====================================================================
//  bf16 mma.sync GEMM over packed K3 = 3K operands (ldmatrix + SW128 smem)
//  C[M,N] = A3[M,K3] @ B3[N,K3]^T; tile 128x128, BK=64 bf16 (128B rows)
//  256 threads / 8 warps (2m x 4n), warp 64x32, m16n8k16; 2-stage cp.async
// =====================================================================
#define SWZ(off) ((off) ^ (((off) >> 3) & 0x70))
#define TILE_B   16384                 // 128 rows * 128 B
#define STAGE_B  (2 * TILE_B)          // A tile + B tile
#define GB_SMEM  (2 * STAGE_B)         // 64 KB

template <int EPI>
__device__ __forceinline__ float epi_apply(float c, size_t idx,
                                           const float* __restrict__ G,
                                           const float* __restrict__ R1,
                                           const float* __restrict__ R2)
{
    if (EPI == EPI_SIGMOID)        c = sigf(c);
    else if (EPI == EPI_GATE)      c = c * sigf(G[idx]);
    else if (EPI == EPI_GATE_ADD2) c = c * sigf(G[idx]) + R1[idx] + R2[idx];
    else if (EPI == EPI_ADD)       c = c + R1[idx];
    return c;
}

__device__ __forceinline__ void mma16(float* c, uint32_t a0, uint32_t a1, uint32_t a2, uint32_t a3,
                                      uint32_t b0, uint32_t b1)
{
    asm volatile(
        "mma.sync.aligned.m16n8k16.row.col.f32.bf16.bf16.f32 "
        "{%0,%1,%2,%3}, {%4,%5,%6,%7}, {%8,%9}, {%0,%1,%2,%3};"
        : "+f"(c[0]), "+f"(c[1]), "+f"(c[2]), "+f"(c[3])
        : "r"(a0), "r"(a1), "r"(a2), "r"(a3), "r"(b0), "r"(b1));
}

__device__ __forceinline__ void ldsm4(uint32_t addr, uint32_t& r0, uint32_t& r1,
                                      uint32_t& r2, uint32_t& r3)
{
    asm volatile("ldmatrix.sync.aligned.m8n8.x4.shared.b16 {%0,%1,%2,%3}, [%4];"
                 : "=r"(r0), "=r"(r1), "=r"(r2), "=r"(r3) : "r"(addr));
}

template <int EPI>
__global__ __launch_bounds__(256, 2) void gemm_bf16(
    const __nv_bfloat16* __restrict__ A, const __nv_bfloat16* __restrict__ B,
    float* __restrict__ D,
    const float* __restrict__ G, const float* __restrict__ R1, const float* __restrict__ R2,
    int M, int N, int K3)
{
    extern __shared__ __nv_bfloat16 smem[];

    const int tid  = threadIdx.x;
    const int wid  = tid >> 5, lane = tid & 31;
    const int wm   = wid & 1, wn = wid >> 1;
    const int g    = lane >> 2, tg = lane & 3;
    const int m0   = blockIdx.y * 128;
    const int n0   = blockIdx.x * 128;

    float acc[4][4][4];
#pragma unroll
    for (int mt = 0; mt < 4; mt++)
#pragma unroll
        for (int nt = 0; nt < 4; nt++)
#pragma unroll
            for (int e = 0; e < 4; e++) acc[mt][nt][e] = 0.f;

    const int KT = K3 >> 6;   // BK = 64

    uint32_t base;
    asm("{ .reg .u64 t; cvta.to.shared.u64 t, %1; cvt.u32.u64 %0, t; }" : "=r"(base) : "l"(smem));

    // cp.async slots: 1024 16B-chunks per tile, 4 per thread
    uint32_t swOff[4];
    const __nv_bfloat16* aG[4];
    const __nv_bfloat16* bG[4];
#pragma unroll
    for (int l = 0; l < 4; l++) {
        int idx = tid + l * 256;
        int r = idx >> 3, c = idx & 7;
        uint32_t off = r * 128 + c * 16;
        swOff[l] = SWZ(off);
        aG[l] = A + (size_t)(m0 + r) * K3 + c * 8;
        bG[l] = B + (size_t)(n0 + r) * K3 + c * 8;
    }

    // ldmatrix lane geometry
    const int lmRow = ((lane >> 3) & 1) * 8 + (lane & 7);
    const int lmCB  = ((lane >> 4) & 1) * 16;   // column byte within k16 chunk

#define LOADG(buf, kt)                                                                     \
    {                                                                                      \
        uint32_t aB_ = base + (buf) * STAGE_B;                                             \
        uint32_t bB_ = aB_ + TILE_B;                                                       \
        _Pragma("unroll")                                                                  \
        for (int l = 0; l < 4; l++) {                                                      \
            asm volatile("cp.async.ca.shared.global [%0], [%1], 16;"                       \
                         :: "r"(aB_ + swOff[l]), "l"(aG[l] + (size_t)(kt) * 64));          \
            asm volatile("cp.async.ca.shared.global [%0], [%1], 16;"                       \
                         :: "r"(bB_ + swOff[l]), "l"(bG[l] + (size_t)(kt) * 64));          \
        }                                                                                  \
    }

    LOADG(0, 0);
    asm volatile("cp.async.commit_group;");

    for (int kt = 0; kt < KT; kt++) {
        if (kt + 1 < KT) LOADG((kt + 1) & 1, kt + 1);
        asm volatile("cp.async.commit_group;");
        asm volatile("cp.async.wait_group 1;");
        __syncthreads();

        const uint32_t aBuf = base + (kt & 1) * STAGE_B;
        const uint32_t bBuf = aBuf + TILE_B;

#pragma unroll
        for (int ks = 0; ks < 4; ks++) {
            const int kbB = ks * 32;     // byte offset of this k16 chunk
            uint32_t bf[4][2];
#pragma unroll
            for (int h = 0; h < 2; h++) {
                uint32_t off = (uint32_t)(wn * 32 + h * 16 + lmRow) * 128 + kbB + lmCB;
                ldsm4(bBuf + SWZ(off), bf[2 * h][0], bf[2 * h + 1][0], bf[2 * h][1], bf[2 * h + 1][1]);
            }
            uint32_t af[4][4];
#pragma unroll
            for (int mt = 0; mt < 4; mt++) {
                uint32_t off = (uint32_t)(wm * 64 + mt * 16 + lmRow) * 128 + kbB + lmCB;
                ldsm4(aBuf + SWZ(off), af[mt][0], af[mt][1], af[mt][2], af[mt][3]);
            }
#pragma unroll
            for (int mt = 0; mt < 4; mt++)
#pragma unroll
                for (int nt = 0; nt < 4; nt++)
                    mma16(acc[mt][nt], af[mt][0], af[mt][1], af[mt][2], af[mt][3],
                          bf[nt][0], bf[nt][1]);
        }
        __syncthreads();
    }
#undef LOADG

    // epilogue
#pragma unroll
    for (int mt = 0; mt < 4; mt++) {
        int r0 = m0 + wm * 64 + mt * 16 + g;
#pragma unroll
        for (int nt = 0; nt < 4; nt++) {
            int col = n0 + wn * 32 + nt * 8 + tg * 2;
            size_t i0 = (size_t)r0 * N + col;
            size_t i1 = i0 + (size_t)8 * N;
            if (EPI == EPI_SILU_MUL_SPLIT) {
                // c = acc * silu(G); write bf16 split triple [hi|lo|hi] into D3 (row stride 3N)
                __nv_bfloat16* D3 = (__nv_bfloat16*)D;
                float g0 = G[i0], g1 = G[i0 + 1], g2 = G[i1], g3 = G[i1 + 1];
                float c0 = acc[mt][nt][0] * (g0 * sigf(g0));
                float c1 = acc[mt][nt][1] * (g1 * sigf(g1));
                float c2 = acc[mt][nt][2] * (g2 * sigf(g2));
                float c3 = acc[mt][nt][3] * (g3 * sigf(g3));
                uint32_t h, l;
                split2(c0, c1, h, l);
                size_t b0 = (size_t)r0 * 3 * N + col;
                *(uint32_t*)(D3 + b0)         = h;
                *(uint32_t*)(D3 + b0 + N)     = l;
                *(uint32_t*)(D3 + b0 + 2 * N) = h;
                split2(c2, c3, h, l);
                size_t b1 = (size_t)(r0 + 8) * 3 * N + col;
                *(uint32_t*)(D3 + b1)         = h;
                *(uint32_t*)(D3 + b1 + N)     = l;
                *(uint32_t*)(D3 + b1 + 2 * N) = h;
            } else {
                float2 o0, o1;
                o0.x = epi_apply<EPI>(acc[mt][nt][0], i0,     G, R1, R2);
                o0.y = epi_apply<EPI>(acc[mt][nt][1], i0 + 1, G, R1, R2);
                o1.x = epi_apply<EPI>(acc[mt][nt][2], i1,     G, R1, R2);
                o1.y = epi_apply<EPI>(acc[mt][nt][3], i1 + 1, G, R1, R2);
                *(float2*)&D[i0] = o0;
                *(float2*)&D[i1] = o1;
            }
        }
    }
}

// ---------------- legacy FFMA GEMM (tiny-N cases: N=64) ----------------
#define BM 128
#define BN 128
#define BKK 16

template <int EPI>
__global__ __launch_bounds__(256) void gemm_tn(
    const float* __restrict__ A, const float* __restrict__ B, float* __restrict__ D,
    const float* __restrict__ G, const float* __restrict__ R1, const float* __restrict__ R2,
    int M, int N, int K)
{
    __shared__ float As[BKK][BM + 4];
    __shared__ float Bs[BKK][BN + 4];

    const int tid = threadIdx.x;
    const int m0 = blockIdx.y * BM;
    const int n0 = blockIdx.x * BN;
    const int tx = tid & 15;
    const int ty = tid >> 4;

    float acc[8][8];
#pragma unroll
    for (int i = 0; i < 8; i++)
#pragma unroll
        for (int j = 0; j < 8; j++) acc[i][j] = 0.f;

    for (int k0 = 0; k0 < K; k0 += BKK) {
#pragma unroll
        for (int l = 0; l < 2; l++) {
            int qi  = tid + l * 256;
            int row = qi >> 2;
            int kk  = (qi & 3) * 4;
            float4 av = *(const float4*)&A[(size_t)(m0 + row) * K + k0 + kk];
            As[kk + 0][row] = av.x; As[kk + 1][row] = av.y;
            As[kk + 2][row] = av.z; As[kk + 3][row] = av.w;
        }
#pragma unroll
        for (int l = 0; l < 2; l++) {
            int qi  = tid + l * 256;
            int row = qi >> 2;
            int kk  = (qi & 3) * 4;
            float4 bv = make_float4(0.f, 0.f, 0.f, 0.f);
            if (n0 + row < N) bv = *(const float4*)&B[(size_t)(n0 + row) * K + k0 + kk];
            Bs[kk + 0][row] = bv.x; Bs[kk + 1][row] = bv.y;
            Bs[kk + 2][row] = bv.z; Bs[kk + 3][row] = bv.w;
        }
        __syncthreads();

#pragma unroll
        for (int kk = 0; kk < BKK; kk++) {
            float a[8], b[8];
#pragma unroll
            for (int i = 0; i < 8; i++) a[i] = As[kk][ty * 8 + i];
#pragma unroll
            for (int j = 0; j < 8; j++) b[j] = Bs[kk][tx * 8 + j];
#pragma unroll
            for (int i = 0; i < 8; i++)
#pragma unroll
                for (int j = 0; j < 8; j++) acc[i][j] += a[i] * b[j];
        }
        __syncthreads();
    }

#pragma unroll
    for (int i = 0; i < 8; i++) {
        int row = m0 + ty * 8 + i;
#pragma unroll
        for (int j = 0; j < 8; j++) {
            int col = n0 + tx * 8 + j;
            if (col < N) {
                size_t idx = (size_t)row * N + col;
                D[idx] = epi_apply<EPI>(acc[i][j], idx, G, R1, R2);
            }
        }
    }
}

// ---------------- scale_norm with fused A-side split ----------------
__global__ __launch_bounds__(256) void scale_norm_split(
    const float* __restrict__ x, float* __restrict__ o,
    __nv_bfloat16* __restrict__ o3, const float* __restrict__ g)
{
    int t = blockIdx.x;
    const float4* xr = (const float4*)(x + (size_t)t * XD);
    float4 v0 = xr[threadIdx.x];
    float4 v1 = xr[threadIdx.x + 256];
    float s = v0.x*v0.x + v0.y*v0.y + v0.z*v0.z + v0.w*v0.w
            + v1.x*v1.x + v1.y*v1.y + v1.z*v1.z + v1.w*v1.w;
    for (int off = 16; off; off >>= 1) s += __shfl_xor_sync(0xffffffffu, s, off);
    __shared__ float red[8];
    int w = threadIdx.x >> 5, lane = threadIdx.x & 31;
    if (lane == 0) red[w] = s;
    __syncthreads();
    float tot = red[0] + red[1] + red[2] + red[3] + red[4] + red[5] + red[6] + red[7];
    float sc = g[0] / (sqrtf(tot) + 1e-8f);
    v0.x *= sc; v0.y *= sc; v0.z *= sc; v0.w *= sc;
    v1.x *= sc; v1.y *= sc; v1.z *= sc; v1.w *= sc;
    float4* orow = (float4*)(o + (size_t)t * XD);
    orow[threadIdx.x] = v0;
    orow[threadIdx.x + 256] = v1;
    // split triple [hi|lo|hi]
    __nv_bfloat16* r3 = o3 + (size_t)t * 3 * XD;
    uint32_t h, l;
    int c0 = threadIdx.x * 4;
    split2(v0.x, v0.y, h, l);
    *(uint32_t*)(r3 + c0) = h; *(uint32_t*)(r3 + XD + c0) = l; *(uint32_t*)(r3 + 2 * XD + c0) = h;
    split2(v0.z, v0.w, h, l);
    *(uint32_t*)(r3 + c0 + 2) = h; *(uint32_t*)(r3 + XD + c0 + 2) = l; *(uint32_t*)(r3 + 2 * XD + c0 + 2) = h;
    int c1 = c0 + 1024;
    split2(v1.x, v1.y, h, l);
    *(uint32_t*)(r3 + c1) = h; *(uint32_t*)(r3 + XD + c1) = l; *(uint32_t*)(r3 + 2 * XD + c1) = h;
    split2(v1.z, v1.w, h, l);
    *(uint32_t*)(r3 + c1 + 2) = h; *(uint32_t*)(r3 + XD + c1 + 2) = l; *(uint32_t*)(r3 + 2 * XD + c1 + 2) = h;
}

// ---------------- RoPE ----------------
__global__ __launch_bounds__(128) void rope_all(
    const float* __restrict__ q, const float* __restrict__ k,
    float* __restrict__ qhi, float* __restrict__ klo, float* __restrict__ khi)
{
    int t = blockIdx.x, j = threadIdx.x;
    int r = t & 63;
    float freq = powf(10000.f, -(float)j / 128.f);
    float slo, clo, shi, chi;
    sincosf((float)r * freq, &slo, &clo);
    sincosf((float)(64 + r) * freq, &shi, &chi);
    size_t base = (size_t)t * QD + 2 * j;
    float qe = q[base], qo = q[base + 1];
    qhi[base]     = qe * chi - qo * shi;
    qhi[base + 1] = qo * chi + qe * shi;
    float ke = k[base], ko = k[base + 1];
    klo[base]     = ke * clo - ko * slo;
    klo[base + 1] = ko * clo + ke * slo;
    khi[base]     = ke * chi - ko * shi;
    khi[base + 1] = ko * chi + ke * shi;
}

// ---------------- attention scores + softmax ----------------
__global__ __launch_bounds__(256) void attn_score(
    const float* __restrict__ qr, const float* __restrict__ klo,
    const float* __restrict__ khi, float* __restrict__ Aout)
{
    int w = threadIdx.x >> 5, lane = threadIdx.x & 31;
    int t = blockIdx.x * 8 + w;
    int c = t >> 6, r = t & 63;
    float qreg[8];
#pragma unroll
    for (int i = 0; i < 8; i++) qreg[i] = qr[(size_t)t * QD + i * 32 + lane];

    __shared__ float s_s[8][128];
    for (int m = 0; m < 128; m++) {
        float sc;
        if (c == 0 && m < 64) {
            sc = 0.f;
        } else {
            const float* kp = (m < 64)
                ? &klo[(size_t)((c - 1) * 64 + m) * QD]
                : &khi[(size_t)(c * 64 + (m - 64)) * QD];
            float d = 0.f;
#pragma unroll
            for (int i = 0; i < 8; i++) d += qreg[i] * kp[i * 32 + lane];
            for (int off = 16; off; off >>= 1) d += __shfl_xor_sync(0xffffffffu, d, off);
            sc = d * (1.f / 16.f);
        }
        if (m > r + 64) sc = -1e30f;
        if (lane == 0) s_s[w][m] = sc;
    }
    __syncwarp();
    float a0 = s_s[w][lane], a1 = s_s[w][lane + 32], a2 = s_s[w][lane + 64], a3 = s_s[w][lane + 96];
    float mx = fmaxf(fmaxf(a0, a1), fmaxf(a2, a3));
    for (int off = 16; off; off >>= 1) mx = fmaxf(mx, __shfl_xor_sync(0xffffffffu, mx, off));
    float e0 = expf(a0 - mx), e1 = expf(a1 - mx), e2 = expf(a2 - mx), e3 = expf(a3 - mx);
    float sm = e0 + e1 + e2 + e3;
    for (int off = 16; off; off >>= 1) sm += __shfl_xor_sync(0xffffffffu, sm, off);
    float inv = 1.f / sm;
    size_t ob = (size_t)t * 128;
    Aout[ob + lane]      = e0 * inv;
    Aout[ob + lane + 32] = e1 * inv;
    Aout[ob + lane + 64] = e2 * inv;
    Aout[ob + lane + 96] = e3 * inv;
}

// ---------------- y = A @ v2, fused A-side split into y3 ----------------
__global__ __launch_bounds__(256) void attn_av(
    const float* __restrict__ Aat, const float* __restrict__ v,
    __nv_bfloat16* __restrict__ y3)
{
    int c = blockIdx.z, rg = blockIdx.y, ct = blockIdx.x;
    int col = ct * 256 + threadIdx.x;
    __shared__ float As[16][128];
    for (int idx = threadIdx.x; idx < 16 * 128; idx += 256) {
        int rr = idx >> 7, mm = idx & 127;
        As[rr][mm] = Aat[(size_t)(c * 64 + rg * 16 + rr) * 128 + mm];
    }
    __syncthreads();
    float acc[16];
#pragma unroll
    for (int r = 0; r < 16; r++) acc[r] = 0.f;
    int mstart = (c == 0) ? 64 : 0;
    for (int m = mstart; m < 128; m++) {
        float vv = v[(size_t)((c - 1) * 64 + m) * XD + col];
#pragma unroll
        for (int r = 0; r < 16; r++) acc[r] += As[r][m] * vv;
    }
#pragma unroll
    for (int r = 0; r < 16; r++) {
        float val = acc[r];
        __nv_bfloat16 hb = __float2bfloat16(val);
        __nv_bfloat16 lb = __float2bfloat16(val - __bfloat162float(hb));
        __nv_bfloat16* yr = y3 + (size_t)(c * 64 + rg * 16 + r) * 3 * XD;
        yr[col] = hb; yr[XD + col] = lb; yr[2 * XD + col] = hb;
    }
}

// ---------------- mem prep ----------------
__global__ void mem_prep(const float* __restrict__ beta, const float* __restrict__ decay,
                         float* __restrict__ gam, float* __restrict__ bg)
{
    int n = blockIdx.x, d = threadIdx.x;
    float g = (d < MD - DCD) ? 1.f : sigf(decay[n * DCD + (d - (MD - DCD))]);
    gam[n * MD + d] = g;
    bg[n * MD + d] = g * sigf(beta[n * MD + d]);
}

// ---------------- mem scan ----------------
__global__ __launch_bounds__(256) void mem_scan(
    const float* __restrict__ F, const float* __restrict__ V,
    const float* __restrict__ gam, const float* __restrict__ bg, float* __restrict__ mems)
{
    int n = blockIdx.x, d = threadIdx.x;
    float ga = gam[n * MD + d], b = bg[n * MD + d];
    float m = 0.f;
    float fn = F[n], vn = V[d];
    for (int t = 0; t < T; t++) {
        float f = fn, vv = vn;
        if (t + 1 < T) { fn = F[(t + 1) * MN + n]; vn = V[(size_t)(t + 1) * MD + d]; }
        m = (ga - f * b) * m + f * vv;
        mems[((size_t)t * MN + n) * MD + d] = m;
    }
}

// ---------------- transpose 256x256 ----------------
__global__ void transpose256(const float* __restrict__ W, float* __restrict__ WT)
{
    int rk = blockIdx.x, cd = threadIdx.x;
    WT[cd * MD + rk] = W[rk * MD + cd];
}

// ---------------- mem readout ----------------
__global__ __launch_bounds__(256) void mem_readout(
    const float* __restrict__ mems, const float* __restrict__ qk2,
    const float* __restrict__ lq, float* __restrict__ yout)
{
    int t = blockIdx.x;
    int tid = threadIdx.x, w = tid >> 5, lane = tid & 31;
    __shared__ float qs[MD];
    __shared__ float as[MN];
    qs[tid] = qk2[(size_t)t * MD + tid];
    __syncthreads();
    const float* mb = mems + (size_t)t * MN * MD;
#pragma unroll
    for (int mi = 0; mi < 8; mi++) {
        int m = w * 8 + mi;
        const float* mp = mb + m * MD;
        float d = 0.f;
#pragma unroll
        for (int i = 0; i < 8; i++) d += mp[i * 32 + lane] * qs[i * 32 + lane];
        for (int off = 16; off; off >>= 1) d += __shfl_xor_sync(0xffffffffu, d, off);
        if (lane == 0) as[m] = (d + lq[t * MN + m]) * (1.f / 16.f);
    }
    __syncthreads();
    if (w == 0) {
        float a0 = as[lane], a1 = as[lane + 32];
        float mx = fmaxf(a0, a1);
        for (int off = 16; off; off >>= 1) mx = fmaxf(mx, __shfl_xor_sync(0xffffffffu, mx, off));
        float e0 = expf(a0 - mx), e1 = expf(a1 - mx);
        float sm = e0 + e1;
        for (int off = 16; off; off >>= 1) sm += __shfl_xor_sync(0xffffffffu, sm, off);
        float inv = 1.f / sm;
        as[lane] = e0 * inv;
        as[lane + 32] = e1 * inv;
    }
    __syncthreads();
    float acc = 0.f;
    for (int m = 0; m < MN; m++) acc += as[m] * mb[m * MD + tid];
    yout[(size_t)t * MD + tid] = acc;
}

// ---------------- launcher ----------------
static float* sym(const void* s) { void* p = nullptr; cudaGetSymbolAddress(&p, s); return (float*)p; }
static __nv_bfloat16* symb(const void* s) { void* p = nullptr; cudaGetSymbolAddress(&p, s); return (__nv_bfloat16*)p; }

extern "C" void kernel_launch(void* const* d_in, const int* in_sizes, int n_in,
                              void* d_out, int out_size)
{
    const float* xs      = (const float*)d_in[0];
    const float* attn_q  = (const float*)d_in[1];
    const float* attn_k  = (const float*)d_in[2];
    const float* attn_v  = (const float*)d_in[3];
    const float* attn_o  = (const float*)d_in[4];
    const float* attn_r  = (const float*)d_in[5];
    const float* mem_f   = (const float*)d_in[6];
    const float* mem_q   = (const float*)d_in[7];
    const float* mem_k   = (const float*)d_in[8];
    const float* mem_v   = (const float*)d_in[9];
    const float* mem_o   = (const float*)d_in[10];
    const float* mem_r   = (const float*)d_in[11];
    const float* mem_beta= (const float*)d_in[12];
    const float* mem_dec = (const float*)d_in[13];
    const float* mem_l   = (const float*)d_in[14];
    const float* ff_in1  = (const float*)d_in[15];
    const float* ff_in2  = (const float*)d_in[16];
    const float* ff_out  = (const float*)d_in[17];
    const float* sn1     = (const float*)d_in[18];
    const float* sn2     = (const float*)d_in[19];
    float* out = (float*)d_out;

    float* xn   = sym(B_xn);   float* q_   = sym(B_q);    float* k_   = sym(B_k);
    float* qhi  = sym(B_qhi);  float* klo  = sym(B_klo);  float* khi  = sym(B_khi);
    float* v_   = sym(B_v);    float* A_   = sym(B_A);
    float* gate = sym(B_gate); float* accb = sym(B_acc);
    float* memF = sym(B_memF); float* memV = sym(B_memV); float* memQ = sym(B_memQ);
    float* gam  = sym(B_gam);  float* bg   = sym(B_bg);   float* wkT  = sym(B_wkT);
    float* qk2  = sym(B_qk2);  float* lq   = sym(B_lq);   float* mems = sym(B_mems);
    float* memY = sym(B_memY); float* x1   = sym(B_x1);   float* x2n  = sym(B_x2n);
    float* h1   = sym(B_h1);

    __nv_bfloat16* xn3  = symb(C_xn3);  __nv_bfloat16* q3   = symb(C_q3);
    __nv_bfloat16* y3   = symb(C_y3);   __nv_bfloat16* memQ3= symb(C_memQ3);
    __nv_bfloat16* memY3= symb(C_memY3);__nv_bfloat16* x2n3 = symb(C_x2n3);
    __nv_bfloat16* h23  = symb(C_h23);
    __nv_bfloat16* aq3  = symb(W_aq3);  __nv_bfloat16* ak3  = symb(W_ak3);
    __nv_bfloat16* av3  = symb(W_av3);  __nv_bfloat16* ao3  = symb(W_ao3);
    __nv_bfloat16* ar3  = symb(W_ar3);  __nv_bfloat16* mv3  = symb(W_mv3);
    __nv_bfloat16* mq3  = symb(W_mq3);  __nv_bfloat16* mr3  = symb(W_mr3);
    __nv_bfloat16* wk3  = symb(W_wk3);  __nv_bfloat16* mo3  = symb(W_mo3);
    __nv_bfloat16* f13  = symb(W_f13);  __nv_bfloat16* f23  = symb(W_f23);
    __nv_bfloat16* fo3  = symb(W_fo3);

    cudaFuncSetAttribute(gemm_bf16<EPI_NONE>,           cudaFuncAttributeMaxDynamicSharedMemorySize, GB_SMEM);
    cudaFuncSetAttribute(gemm_bf16<EPI_GATE>,           cudaFuncAttributeMaxDynamicSharedMemorySize, GB_SMEM);
    cudaFuncSetAttribute(gemm_bf16<EPI_GATE_ADD2>,      cudaFuncAttributeMaxDynamicSharedMemorySize, GB_SMEM);
    cudaFuncSetAttribute(gemm_bf16<EPI_SILU_MUL_SPLIT>, cudaFuncAttributeMaxDynamicSharedMemorySize, GB_SMEM);
    cudaFuncSetAttribute(gemm_bf16<EPI_ADD>,            cudaFuncAttributeMaxDynamicSharedMemorySize, GB_SMEM);

    const dim3 blk256(256);
#define CVTA(src, dst, M_, K_) cvtA_k<<<(unsigned)((size_t)(M_) * (K_) / 2 / 256), blk256>>>(src, dst, (K_) / 2)
#define CVTB(src, dst, M_, K_) cvtB_k<<<(unsigned)((size_t)(M_) * (K_) / 2 / 256), blk256>>>(src, dst, (K_) / 2)
#define GB(EPI_, gx, gy, Aa, Bb, Dd, Gg, Rr1, Rr2, Mm, Nn, Kk)                                  \
    gemm_bf16<EPI_><<<dim3(gx, gy), blk256, GB_SMEM>>>(Aa, Bb, Dd, Gg, Rr1, Rr2, Mm, Nn, Kk)

    // weight conversions
    CVTB(attn_q, aq3, QD, XD);
    CVTB(attn_k, ak3, QD, QD);
    CVTB(attn_v, av3, XD, XD);
    CVTB(attn_o, ao3, XD, XD);
    CVTB(attn_r, ar3, XD, XD);
    CVTB(mem_v,  mv3, MD, XD);
    CVTB(mem_q,  mq3, MD, XD);
    CVTB(mem_r,  mr3, XD, XD);
    CVTB(mem_o,  mo3, XD, MD);
    CVTB(ff_in1, f13, FFD, XD);
    CVTB(ff_in2, f23, FFD, XD);
    CVTB(ff_out, fo3, XD, FFD);
    transpose256<<<MD, MD>>>(mem_k, wkT);
    CVTB(wkT, wk3, MD, MD);

    // 1. xn = scale_norm(xs, sn1), fused split
    scale_norm_split<<<T, blk256>>>(xs, xn, xn3, sn1);
    // 2-5. attn projections + gate
    GB(EPI_NONE, 2, 16,  xn3, aq3, q_, nullptr, nullptr, nullptr, T, QD, 3 * XD);
    CVTA(q_, q3, T, QD);
    GB(EPI_NONE, 2, 16,  q3, ak3, k_, nullptr, nullptr, nullptr, T, QD, 3 * QD);
    GB(EPI_NONE, 16, 16, xn3, av3, v_, nullptr, nullptr, nullptr, T, XD, 3 * XD);
    GB(EPI_NONE, 16, 16, xn3, ar3, gate, nullptr, nullptr, nullptr, T, XD, 3 * XD);
    // 6. attention core (writes y3 split directly)
    rope_all<<<T, 128>>>(q_, k_, qhi, klo, khi);
    attn_score<<<T / 8, blk256>>>(qhi, klo, khi, A_);
    attn_av<<<dim3(8, 4, 32), blk256>>>(A_, v_, y3);
    // 7. attn out = (y @ Wo^T) * sigmoid(gate)
    GB(EPI_GATE, 16, 16, y3, ao3, accb, gate, nullptr, nullptr, T, XD, 3 * XD);
    // 8-11. mem projections + mem gate
    gemm_tn<EPI_SIGMOID><<<dim3(1, 16), blk256>>>(xn, mem_f, memF, nullptr, nullptr, nullptr, T, MN, XD);
    GB(EPI_NONE, 2, 16,  xn3, mv3, memV, nullptr, nullptr, nullptr, T, MD, 3 * XD);
    GB(EPI_NONE, 2, 16,  xn3, mq3, memQ, nullptr, nullptr, nullptr, T, MD, 3 * XD);
    GB(EPI_NONE, 16, 16, xn3, mr3, gate, nullptr, nullptr, nullptr, T, XD, 3 * XD);
    // 12-13. scan
    mem_prep<<<MN, MD>>>(mem_beta, mem_dec, gam, bg);
    mem_scan<<<MN, MD>>>(memF, memV, gam, bg, mems);
    // 14. readout
    CVTA(memQ, memQ3, T, MD);
    GB(EPI_NONE, 2, 16, memQ3, wk3, qk2, nullptr, nullptr, nullptr, T, MD, 3 * MD);
    gemm_tn<EPI_NONE><<<dim3(1, 16), blk256>>>(memQ, mem_l, lq, nullptr, nullptr, nullptr, T, MN, MD);
    mem_readout<<<T, blk256>>>(mems, qk2, lq, memY);
    // 15. x1 = (memY @ mem_o^T)*sigmoid(gate) + attn_out + xs
    CVTA(memY, memY3, T, MD);
    GB(EPI_GATE_ADD2, 16, 16, memY3, mo3, x1, gate, accb, xs, T, XD, 3 * MD);
    // 16-19. FF block (h2 split fused into SILU epilogue)
    scale_norm_split<<<T, blk256>>>(x1, x2n, x2n3, sn2);
    GB(EPI_NONE, 22, 16, x2n3, f13, h1, nullptr, nullptr, nullptr, T, FFD, 3 * XD);
    GB(EPI_SILU_MUL_SPLIT, 22, 16, x2n3, f23, (float*)h23, h1, nullptr, nullptr, T, FFD, 3 * XD);
    GB(EPI_ADD, 16, 16, h23, fo3, out, nullptr, x1, nullptr, T, XD, 3 * FFD);
#undef CVTA
#undef CVTB
#undef GB
}

// round 10
// speedup vs baseline: 2.0464x; 1.0337x over previous
#include <cuda_runtime.h>
#include <cuda_bf16.h>
#include <math.h>
#include <stdint.h>

// ---------------- problem dims ----------------
#define T    2048
#define XD   2048
#define QD   256
#define MN   64
#define MD   256
#define DCD  64
#define FFD  2816
#define CH   64

// ---------------- fp32 scratch ----------------
__device__ float B_xn  [(size_t)T*XD];
__device__ float B_q   [(size_t)T*QD];
__device__ float B_k   [(size_t)T*QD];
__device__ float B_qhi [(size_t)T*QD];
__device__ float B_klo [(size_t)T*QD];
__device__ float B_khi [(size_t)T*QD];
__device__ float B_v   [(size_t)T*XD];
__device__ float B_A   [(size_t)T*2*CH];
__device__ float B_gate[(size_t)T*XD];
__device__ float B_acc [(size_t)T*XD];
__device__ float B_memF[(size_t)T*MN];
__device__ float B_memV[(size_t)T*MD];
__device__ float B_memQ[(size_t)T*MD];
__device__ float B_gam [(size_t)MN*MD];
__device__ float B_bg  [(size_t)MN*MD];
__device__ float B_wkT [(size_t)MD*MD];
__device__ float B_qk2 [(size_t)T*MD];
__device__ float B_lq  [(size_t)T*MN];
__device__ float B_mems[(size_t)T*MN*MD];
__device__ float B_memY[(size_t)T*MD];
__device__ float B_x1  [(size_t)T*XD];
__device__ float B_x2n [(size_t)T*XD];
__device__ float B_h1  [(size_t)T*FFD];
__device__ float B_part[(size_t)4*T*MD];   // split-K partials (max N=256)

// ---------------- bf16 split scratch: A-side [hi|lo|hi], B-side [hi|hi|lo] ----------------
__device__ __nv_bfloat16 C_xn3  [(size_t)T*3*XD];
__device__ __nv_bfloat16 C_q3   [(size_t)T*3*QD];
__device__ __nv_bfloat16 C_y3   [(size_t)T*3*XD];
__device__ __nv_bfloat16 C_memQ3[(size_t)T*3*MD];
__device__ __nv_bfloat16 C_memY3[(size_t)T*3*MD];
__device__ __nv_bfloat16 C_x2n3 [(size_t)T*3*XD];
__device__ __nv_bfloat16 C_h23  [(size_t)T*3*FFD];
__device__ __nv_bfloat16 W_aq3  [(size_t)QD*3*XD];
__device__ __nv_bfloat16 W_ak3  [(size_t)QD*3*QD];
__device__ __nv_bfloat16 W_av3  [(size_t)XD*3*XD];
__device__ __nv_bfloat16 W_ao3  [(size_t)XD*3*XD];
__device__ __nv_bfloat16 W_ar3  [(size_t)XD*3*XD];
__device__ __nv_bfloat16 W_mv3  [(size_t)MD*3*XD];
__device__ __nv_bfloat16 W_mq3  [(size_t)MD*3*XD];
__device__ __nv_bfloat16 W_mr3  [(size_t)XD*3*XD];
__device__ __nv_bfloat16 W_wk3  [(size_t)MD*3*MD];
__device__ __nv_bfloat16 W_mo3  [(size_t)XD*3*MD];
__device__ __nv_bfloat16 W_f13  [(size_t)FFD*3*XD];
__device__ __nv_bfloat16 W_f23  [(size_t)FFD*3*XD];
__device__ __nv_bfloat16 W_fo3  [(size_t)XD*3*FFD];

__device__ __forceinline__ float sigf(float x) { return 1.f / (1.f + expf(-x)); }

enum { EPI_NONE = 0, EPI_SIGMOID, EPI_GATE, EPI_GATE_ADD2, EPI_SILU_MUL_SPLIT, EPI_ADD };

__device__ __forceinline__ void split2(float v0, float v1, uint32_t& hi, uint32_t& lo)
{
    asm("cvt.rn.bf16x2.f32 %0, %1, %2;" : "=r"(hi) : "f"(v1), "f"(v0));
    float h0 = __uint_as_float(hi << 16);
    float h1 = __uint_as_float(hi & 0xffff0000u);
    asm("cvt.rn.bf16x2.f32 %0, %1, %2;" : "=r"(lo) : "f"(v1 - h1), "f"(v0 - h0));
}

// ---------------- split-conversion kernels ----------------
__global__ __launch_bounds__(256) void cvtA_k(const float* __restrict__ src,
                                              __nv_bfloat16* __restrict__ dst, int Khalf)
{
    size_t i = (size_t)blockIdx.x * 256 + threadIdx.x;
    size_t row = i / Khalf;
    int   cp  = (int)(i - row * Khalf);
    float2 v = ((const float2*)src)[i];
    uint32_t hi, lo; split2(v.x, v.y, hi, lo);
    uint32_t* dr = (uint32_t*)(dst + row * 6 * (size_t)Khalf);
    dr[cp]             = hi;
    dr[Khalf + cp]     = lo;
    dr[2 * Khalf + cp] = hi;
}

__global__ __launch_bounds__(256) void cvtB_k(const float* __restrict__ src,
                                              __nv_bfloat16* __restrict__ dst, int Khalf)
{
    size_t i = (size_t)blockIdx.x * 256 + threadIdx.x;
    size_t row = i / Khalf;
    int   cp  = (int)(i - row * Khalf);
    float2 v = ((const float2*)src)[i];
    uint32_t hi, lo; split2(v.x, v.y, hi, lo);
    uint32_t* dr = (uint32_t*)(dst + row * 6 * (size_t)Khalf);
    dr[cp]             = hi;
    dr[Khalf + cp]     = hi;
    dr[2 * Khalf + cp] = lo;
}

// ---------------- split-K reduce: o = p0+p1+p2+p3 (fixed order, deterministic) ----------------
__global__ __launch_bounds__(256) void redk(const float* __restrict__ p,
                                            float* __restrict__ o, int n4)
{
    int i = blockIdx.x * 256 + threadIdx.x;
    const float4* p4 = (const float4*)p;
    float4 a = p4[i], b = p4[i + n4], c = p4[i + 2 * n4], d = p4[i + 3 * n4];
    float4 r;
    r.x = a.x + b.x + c.x + d.x;
    r.y = a.y + b.y + c.y + d.y;
    r.z = a.z + b.z + c.z + d.z;
    r.w = a.w + b.w + c.w + d.w;
    ((float4*)o)[i] = r;
}

// =====================================================================
//  bf16 mma.sync GEMM over packed K3 operands (ldmatrix + SW128 smem)
//  tile 128x128, BK=64, 3-stage cp.async, ONE barrier per K-iter
//  optional split-K: grid.z chunks of Kchunk, D offset by z*M*N
// =====================================================================
#define SWZ(off) ((off) ^ (((off) >> 3) & 0x70))
#define TILE_B   16384                 // 128 rows * 128 B
#define STAGE_B  (2 * TILE_B)          // A tile + B tile
#define GB_SMEM  (3 * STAGE_B)         // 96 KB, 3 stages

template <int EPI>
__device__ __forceinline__ float epi_apply(float c, size_t idx,
                                           const float* __restrict__ G,
                                           const float* __restrict__ R1,
                                           const float* __restrict__ R2)
{
    if (EPI == EPI_SIGMOID)        c = sigf(c);
    else if (EPI == EPI_GATE)      c = c * sigf(G[idx]);
    else if (EPI == EPI_GATE_ADD2) c = c * sigf(G[idx]) + R1[idx] + R2[idx];
    else if (EPI == EPI_ADD)       c = c + R1[idx];
    return c;
}

__device__ __forceinline__ void mma16(float* c, uint32_t a0, uint32_t a1, uint32_t a2, uint32_t a3,
                                      uint32_t b0, uint32_t b1)
{
    asm volatile(
        "mma.sync.aligned.m16n8k16.row.col.f32.bf16.bf16.f32 "
        "{%0,%1,%2,%3}, {%4,%5,%6,%7}, {%8,%9}, {%0,%1,%2,%3};"
        : "+f"(c[0]), "+f"(c[1]), "+f"(c[2]), "+f"(c[3])
        : "r"(a0), "r"(a1), "r"(a2), "r"(a3), "r"(b0), "r"(b1));
}

__device__ __forceinline__ void ldsm4(uint32_t addr, uint32_t& r0, uint32_t& r1,
                                      uint32_t& r2, uint32_t& r3)
{
    asm volatile("ldmatrix.sync.aligned.m8n8.x4.shared.b16 {%0,%1,%2,%3}, [%4];"
                 : "=r"(r0), "=r"(r1), "=r"(r2), "=r"(r3) : "r"(addr));
}

template <int EPI>
__global__ __launch_bounds__(256, 2) void gemm_bf16(
    const __nv_bfloat16* __restrict__ A, const __nv_bfloat16* __restrict__ B,
    float* __restrict__ D,
    const float* __restrict__ G, const float* __restrict__ R1, const float* __restrict__ R2,
    int M, int N, int Kstride, int Kchunk)
{
    extern __shared__ __nv_bfloat16 smem[];

    const int tid  = threadIdx.x;
    const int wid  = tid >> 5, lane = tid & 31;
    const int wm   = wid & 1, wn = wid >> 1;
    const int g    = lane >> 2, tg = lane & 3;
    const int m0   = blockIdx.y * 128;
    const int n0   = blockIdx.x * 128;
    const int z    = blockIdx.z;

    D += (size_t)z * M * N;   // split-K partial plane (z=0 when no split)

    float acc[4][4][4];
#pragma unroll
    for (int mt = 0; mt < 4; mt++)
#pragma unroll
        for (int nt = 0; nt < 4; nt++)
#pragma unroll
            for (int e = 0; e < 4; e++) acc[mt][nt][e] = 0.f;

    const int KT = Kchunk >> 6;   // BK = 64

    uint32_t base;
    asm("{ .reg .u64 t; cvta.to.shared.u64 t, %1; cvt.u32.u64 %0, t; }" : "=r"(base) : "l"(smem));

    // cp.async slots: 1024 16B-chunks per tile, 4 per thread
    uint32_t swOff[4];
    const __nv_bfloat16* aG[4];
    const __nv_bfloat16* bG[4];
#pragma unroll
    for (int l = 0; l < 4; l++) {
        int idx = tid + l * 256;
        int r = idx >> 3, c = idx & 7;
        uint32_t off = r * 128 + c * 16;
        swOff[l] = SWZ(off);
        aG[l] = A + (size_t)(m0 + r) * Kstride + (size_t)z * Kchunk + c * 8;
        bG[l] = B + (size_t)(n0 + r) * Kstride + (size_t)z * Kchunk + c * 8;
    }

    // ldmatrix lane geometry
    const int lmRow = ((lane >> 3) & 1) * 8 + (lane & 7);
    const int lmCB  = ((lane >> 4) & 1) * 16;

#define LOADG(buf, kt)                                                                     \
    {                                                                                      \
        uint32_t aB_ = base + (buf) * STAGE_B;                                             \
        uint32_t bB_ = aB_ + TILE_B;                                                       \
        _Pragma("unroll")                                                                  \
        for (int l = 0; l < 4; l++) {                                                      \
            asm volatile("cp.async.ca.shared.global [%0], [%1], 16;"                       \
                         :: "r"(aB_ + swOff[l]), "l"(aG[l] + (size_t)(kt) * 64));          \
            asm volatile("cp.async.ca.shared.global [%0], [%1], 16;"                       \
                         :: "r"(bB_ + swOff[l]), "l"(bG[l] + (size_t)(kt) * 64));          \
        }                                                                                  \
    }

    // prologue: 2 stages in flight
    LOADG(0, 0);
    asm volatile("cp.async.commit_group;");
    if (KT > 1) LOADG(1, 1);
    asm volatile("cp.async.commit_group;");

    int buf = 0;
    for (int kt = 0; kt < KT; kt++) {
        asm volatile("cp.async.wait_group 1;");
        __syncthreads();   // stage kt visible; all warps done with stage kt-1's buffer

        // prefetch kt+2 into the buffer freed by kt-1
        if (kt + 2 < KT) {
            int nb = buf + 2; if (nb >= 3) nb -= 3;
            LOADG(nb, kt + 2);
        }
        asm volatile("cp.async.commit_group;");

        const uint32_t aBuf = base + buf * STAGE_B;
        const uint32_t bBuf = aBuf + TILE_B;

#pragma unroll
        for (int ks = 0; ks < 4; ks++) {
            const int kbB = ks * 32;
            uint32_t bf[4][2];
#pragma unroll
            for (int h = 0; h < 2; h++) {
                uint32_t off = (uint32_t)(wn * 32 + h * 16 + lmRow) * 128 + kbB + lmCB;
                ldsm4(bBuf + SWZ(off), bf[2 * h][0], bf[2 * h + 1][0], bf[2 * h][1], bf[2 * h + 1][1]);
            }
            uint32_t af[4][4];
#pragma unroll
            for (int mt = 0; mt < 4; mt++) {
                uint32_t off = (uint32_t)(wm * 64 + mt * 16 + lmRow) * 128 + kbB + lmCB;
                ldsm4(aBuf + SWZ(off), af[mt][0], af[mt][1], af[mt][2], af[mt][3]);
            }
#pragma unroll
            for (int mt = 0; mt < 4; mt++)
#pragma unroll
                for (int nt = 0; nt < 4; nt++)
                    mma16(acc[mt][nt], af[mt][0], af[mt][1], af[mt][2], af[mt][3],
                          bf[nt][0], bf[nt][1]);
        }
        if (++buf >= 3) buf = 0;
    }
#undef LOADG

    // epilogue
#pragma unroll
    for (int mt = 0; mt < 4; mt++) {
        int r0 = m0 + wm * 64 + mt * 16 + g;
#pragma unroll
        for (int nt = 0; nt < 4; nt++) {
            int col = n0 + wn * 32 + nt * 8 + tg * 2;
            size_t i0 = (size_t)r0 * N + col;
            size_t i1 = i0 + (size_t)8 * N;
            if (EPI == EPI_SILU_MUL_SPLIT) {
                __nv_bfloat16* D3 = (__nv_bfloat16*)D;
                float g0 = G[i0], g1 = G[i0 + 1], g2 = G[i1], g3 = G[i1 + 1];
                float c0 = acc[mt][nt][0] * (g0 * sigf(g0));
                float c1 = acc[mt][nt][1] * (g1 * sigf(g1));
                float c2 = acc[mt][nt][2] * (g2 * sigf(g2));
                float c3 = acc[mt][nt][3] * (g3 * sigf(g3));
                uint32_t h, l;
                split2(c0, c1, h, l);
                size_t b0 = (size_t)r0 * 3 * N + col;
                *(uint32_t*)(D3 + b0)         = h;
                *(uint32_t*)(D3 + b0 + N)     = l;
                *(uint32_t*)(D3 + b0 + 2 * N) = h;
                split2(c2, c3, h, l);
                size_t b1 = (size_t)(r0 + 8) * 3 * N + col;
                *(uint32_t*)(D3 + b1)         = h;
                *(uint32_t*)(D3 + b1 + N)     = l;
                *(uint32_t*)(D3 + b1 + 2 * N) = h;
            } else {
                float2 o0, o1;
                o0.x = epi_apply<EPI>(acc[mt][nt][0], i0,     G, R1, R2);
                o0.y = epi_apply<EPI>(acc[mt][nt][1], i0 + 1, G, R1, R2);
                o1.x = epi_apply<EPI>(acc[mt][nt][2], i1,     G, R1, R2);
                o1.y = epi_apply<EPI>(acc[mt][nt][3], i1 + 1, G, R1, R2);
                *(float2*)&D[i0] = o0;
                *(float2*)&D[i1] = o1;
            }
        }
    }
}

// ---------------- legacy FFMA GEMM (tiny-N cases: N=64) ----------------
#define BM 128
#define BN 128
#define BKK 16

template <int EPI>
__global__ __launch_bounds__(256) void gemm_tn(
    const float* __restrict__ A, const float* __restrict__ B, float* __restrict__ D,
    const float* __restrict__ G, const float* __restrict__ R1, const float* __restrict__ R2,
    int M, int N, int K)
{
    __shared__ float As[BKK][BM + 4];
    __shared__ float Bs[BKK][BN + 4];

    const int tid = threadIdx.x;
    const int m0 = blockIdx.y * BM;
    const int n0 = blockIdx.x * BN;
    const int tx = tid & 15;
    const int ty = tid >> 4;

    float acc[8][8];
#pragma unroll
    for (int i = 0; i < 8; i++)
#pragma unroll
        for (int j = 0; j < 8; j++) acc[i][j] = 0.f;

    for (int k0 = 0; k0 < K; k0 += BKK) {
#pragma unroll
        for (int l = 0; l < 2; l++) {
            int qi  = tid + l * 256;
            int row = qi >> 2;
            int kk  = (qi & 3) * 4;
            float4 av = *(const float4*)&A[(size_t)(m0 + row) * K + k0 + kk];
            As[kk + 0][row] = av.x; As[kk + 1][row] = av.y;
            As[kk + 2][row] = av.z; As[kk + 3][row] = av.w;
        }
#pragma unroll
        for (int l = 0; l < 2; l++) {
            int qi  = tid + l * 256;
            int row = qi >> 2;
            int kk  = (qi & 3) * 4;
            float4 bv = make_float4(0.f, 0.f, 0.f, 0.f);
            if (n0 + row < N) bv = *(const float4*)&B[(size_t)(n0 + row) * K + k0 + kk];
            Bs[kk + 0][row] = bv.x; Bs[kk + 1][row] = bv.y;
            Bs[kk + 2][row] = bv.z; Bs[kk + 3][row] = bv.w;
        }
        __syncthreads();

#pragma unroll
        for (int kk = 0; kk < BKK; kk++) {
            float a[8], b[8];
#pragma unroll
            for (int i = 0; i < 8; i++) a[i] = As[kk][ty * 8 + i];
#pragma unroll
            for (int j = 0; j < 8; j++) b[j] = Bs[kk][tx * 8 + j];
#pragma unroll
            for (int i = 0; i < 8; i++)
#pragma unroll
                for (int j = 0; j < 8; j++) acc[i][j] += a[i] * b[j];
        }
        __syncthreads();
    }

#pragma unroll
    for (int i = 0; i < 8; i++) {
        int row = m0 + ty * 8 + i;
#pragma unroll
        for (int j = 0; j < 8; j++) {
            int col = n0 + tx * 8 + j;
            if (col < N) {
                size_t idx = (size_t)row * N + col;
                D[idx] = epi_apply<EPI>(acc[i][j], idx, G, R1, R2);
            }
        }
    }
}

// ---------------- scale_norm with fused A-side split ----------------
__global__ __launch_bounds__(256) void scale_norm_split(
    const float* __restrict__ x, float* __restrict__ o,
    __nv_bfloat16* __restrict__ o3, const float* __restrict__ g)
{
    int t = blockIdx.x;
    const float4* xr = (const float4*)(x + (size_t)t * XD);
    float4 v0 = xr[threadIdx.x];
    float4 v1 = xr[threadIdx.x + 256];
    float s = v0.x*v0.x + v0.y*v0.y + v0.z*v0.z + v0.w*v0.w
            + v1.x*v1.x + v1.y*v1.y + v1.z*v1.z + v1.w*v1.w;
    for (int off = 16; off; off >>= 1) s += __shfl_xor_sync(0xffffffffu, s, off);
    __shared__ float red[8];
    int w = threadIdx.x >> 5, lane = threadIdx.x & 31;
    if (lane == 0) red[w] = s;
    __syncthreads();
    float tot = red[0] + red[1] + red[2] + red[3] + red[4] + red[5] + red[6] + red[7];
    float sc = g[0] / (sqrtf(tot) + 1e-8f);
    v0.x *= sc; v0.y *= sc; v0.z *= sc; v0.w *= sc;
    v1.x *= sc; v1.y *= sc; v1.z *= sc; v1.w *= sc;
    float4* orow = (float4*)(o + (size_t)t * XD);
    orow[threadIdx.x] = v0;
    orow[threadIdx.x + 256] = v1;
    __nv_bfloat16* r3 = o3 + (size_t)t * 3 * XD;
    uint32_t h, l;
    int c0 = threadIdx.x * 4;
    split2(v0.x, v0.y, h, l);
    *(uint32_t*)(r3 + c0) = h; *(uint32_t*)(r3 + XD + c0) = l; *(uint32_t*)(r3 + 2 * XD + c0) = h;
    split2(v0.z, v0.w, h, l);
    *(uint32_t*)(r3 + c0 + 2) = h; *(uint32_t*)(r3 + XD + c0 + 2) = l; *(uint32_t*)(r3 + 2 * XD + c0 + 2) = h;
    int c1 = c0 + 1024;
    split2(v1.x, v1.y, h, l);
    *(uint32_t*)(r3 + c1) = h; *(uint32_t*)(r3 + XD + c1) = l; *(uint32_t*)(r3 + 2 * XD + c1) = h;
    split2(v1.z, v1.w, h, l);
    *(uint32_t*)(r3 + c1 + 2) = h; *(uint32_t*)(r3 + XD + c1 + 2) = l; *(uint32_t*)(r3 + 2 * XD + c1 + 2) = h;
}

// ---------------- RoPE ----------------
__global__ __launch_bounds__(128) void rope_all(
    const float* __restrict__ q, const float* __restrict__ k,
    float* __restrict__ qhi, float* __restrict__ klo, float* __restrict__ khi)
{
    int t = blockIdx.x, j = threadIdx.x;
    int r = t & 63;
    float freq = powf(10000.f, -(float)j / 128.f);
    float slo, clo, shi, chi;
    sincosf((float)r * freq, &slo, &clo);
    sincosf((float)(64 + r) * freq, &shi, &chi);
    size_t base = (size_t)t * QD + 2 * j;
    float qe = q[base], qo = q[base + 1];
    qhi[base]     = qe * chi - qo * shi;
    qhi[base + 1] = qo * chi + qe * shi;
    float ke = k[base], ko = k[base + 1];
    klo[base]     = ke * clo - ko * slo;
    klo[base + 1] = ko * clo + ke * slo;
    khi[base]     = ke * chi - ko * shi;
    khi[base + 1] = ko * chi + ke * shi;
}

// ---------------- attention scores + softmax ----------------
__global__ __launch_bounds__(256) void attn_score(
    const float* __restrict__ qr, const float* __restrict__ klo,
    const float* __restrict__ khi, float* __restrict__ Aout)
{
    int w = threadIdx.x >> 5, lane = threadIdx.x & 31;
    int t = blockIdx.x * 8 + w;
    int c = t >> 6, r = t & 63;
    float qreg[8];
#pragma unroll
    for (int i = 0; i < 8; i++) qreg[i] = qr[(size_t)t * QD + i * 32 + lane];

    __shared__ float s_s[8][128];
    for (int m = 0; m < 128; m++) {
        float sc;
        if (c == 0 && m < 64) {
            sc = 0.f;
        } else {
            const float* kp = (m < 64)
                ? &klo[(size_t)((c - 1) * 64 + m) * QD]
                : &khi[(size_t)(c * 64 + (m - 64)) * QD];
            float d = 0.f;
#pragma unroll
            for (int i = 0; i < 8; i++) d += qreg[i] * kp[i * 32 + lane];
            for (int off = 16; off; off >>= 1) d += __shfl_xor_sync(0xffffffffu, d, off);
            sc = d * (1.f / 16.f);
        }
        if (m > r + 64) sc = -1e30f;
        if (lane == 0) s_s[w][m] = sc;
    }
    __syncwarp();
    float a0 = s_s[w][lane], a1 = s_s[w][lane + 32], a2 = s_s[w][lane + 64], a3 = s_s[w][lane + 96];
    float mx = fmaxf(fmaxf(a0, a1), fmaxf(a2, a3));
    for (int off = 16; off; off >>= 1) mx = fmaxf(mx, __shfl_xor_sync(0xffffffffu, mx, off));
    float e0 = expf(a0 - mx), e1 = expf(a1 - mx), e2 = expf(a2 - mx), e3 = expf(a3 - mx);
    float sm = e0 + e1 + e2 + e3;
    for (int off = 16; off; off >>= 1) sm += __shfl_xor_sync(0xffffffffu, sm, off);
    float inv = 1.f / sm;
    size_t ob = (size_t)t * 128;
    Aout[ob + lane]      = e0 * inv;
    Aout[ob + lane + 32] = e1 * inv;
    Aout[ob + lane + 64] = e2 * inv;
    Aout[ob + lane + 96] = e3 * inv;
}

// ---------------- y = A @ v2, fused A-side split into y3 ----------------
__global__ __launch_bounds__(256) void attn_av(
    const float* __restrict__ Aat, const float* __restrict__ v,
    __nv_bfloat16* __restrict__ y3)
{
    int c = blockIdx.z, rg = blockIdx.y, ct = blockIdx.x;
    int col = ct * 256 + threadIdx.x;
    __shared__ float As[16][128];
    for (int idx = threadIdx.x; idx < 16 * 128; idx += 256) {
        int rr = idx >> 7, mm = idx & 127;
        As[rr][mm] = Aat[(size_t)(c * 64 + rg * 16 + rr) * 128 + mm];
    }
    __syncthreads();
    float acc[16];
#pragma unroll
    for (int r = 0; r < 16; r++) acc[r] = 0.f;
    int mstart = (c == 0) ? 64 : 0;
    for (int m = mstart; m < 128; m++) {
        float vv = v[(size_t)((c - 1) * 64 + m) * XD + col];
#pragma unroll
        for (int r = 0; r < 16; r++) acc[r] += As[r][m] * vv;
    }
#pragma unroll
    for (int r = 0; r < 16; r++) {
        float val = acc[r];
        __nv_bfloat16 hb = __float2bfloat16(val);
        __nv_bfloat16 lb = __float2bfloat16(val - __bfloat162float(hb));
        __nv_bfloat16* yr = y3 + (size_t)(c * 64 + rg * 16 + r) * 3 * XD;
        yr[col] = hb; yr[XD + col] = lb; yr[2 * XD + col] = hb;
    }
}

// ---------------- mem prep ----------------
__global__ void mem_prep(const float* __restrict__ beta, const float* __restrict__ decay,
                         float* __restrict__ gam, float* __restrict__ bg)
{
    int n = blockIdx.x, d = threadIdx.x;
    float g = (d < MD - DCD) ? 1.f : sigf(decay[n * DCD + (d - (MD - DCD))]);
    gam[n * MD + d] = g;
    bg[n * MD + d] = g * sigf(beta[n * MD + d]);
}

// ---------------- mem scan ----------------
__global__ __launch_bounds__(256) void mem_scan(
    const float* __restrict__ F, const float* __restrict__ V,
    const float* __restrict__ gam, const float* __restrict__ bg, float* __restrict__ mems)
{
    int n = blockIdx.x, d = threadIdx.x;
    float ga = gam[n * MD + d], b = bg[n * MD + d];
    float m = 0.f;
    float fn = F[n], vn = V[d];
    for (int t = 0; t < T; t++) {
        float f = fn, vv = vn;
        if (t + 1 < T) { fn = F[(t + 1) * MN + n]; vn = V[(size_t)(t + 1) * MD + d]; }
        m = (ga - f * b) * m + f * vv;
        mems[((size_t)t * MN + n) * MD + d] = m;
    }
}

// ---------------- transpose 256x256 ----------------
__global__ void transpose256(const float* __restrict__ W, float* __restrict__ WT)
{
    int rk = blockIdx.x, cd = threadIdx.x;
    WT[cd * MD + rk] = W[rk * MD + cd];
}

// ---------------- mem readout ----------------
__global__ __launch_bounds__(256) void mem_readout(
    const float* __restrict__ mems, const float* __restrict__ qk2,
    const float* __restrict__ lq, float* __restrict__ yout)
{
    int t = blockIdx.x;
    int tid = threadIdx.x, w = tid >> 5, lane = tid & 31;
    __shared__ float qs[MD];
    __shared__ float as[MN];
    qs[tid] = qk2[(size_t)t * MD + tid];
    __syncthreads();
    const float* mb = mems + (size_t)t * MN * MD;
#pragma unroll
    for (int mi = 0; mi < 8; mi++) {
        int m = w * 8 + mi;
        const float* mp = mb + m * MD;
        float d = 0.f;
#pragma unroll
        for (int i = 0; i < 8; i++) d += mp[i * 32 + lane] * qs[i * 32 + lane];
        for (int off = 16; off; off >>= 1) d += __shfl_xor_sync(0xffffffffu, d, off);
        if (lane == 0) as[m] = (d + lq[t * MN + m]) * (1.f / 16.f);
    }
    __syncthreads();
    if (w == 0) {
        float a0 = as[lane], a1 = as[lane + 32];
        float mx = fmaxf(a0, a1);
        for (int off = 16; off; off >>= 1) mx = fmaxf(mx, __shfl_xor_sync(0xffffffffu, mx, off));
        float e0 = expf(a0 - mx), e1 = expf(a1 - mx);
        float sm = e0 + e1;
        for (int off = 16; off; off >>= 1) sm += __shfl_xor_sync(0xffffffffu, sm, off);
        float inv = 1.f / sm;
        as[lane] = e0 * inv;
        as[lane + 32] = e1 * inv;
    }
    __syncthreads();
    float acc = 0.f;
    for (int m = 0; m < MN; m++) acc += as[m] * mb[m * MD + tid];
    yout[(size_t)t * MD + tid] = acc;
}

// ---------------- launcher ----------------
static float* sym(const void* s) { void* p = nullptr; cudaGetSymbolAddress(&p, s); return (float*)p; }
static __nv_bfloat16* symb(const void* s) { void* p = nullptr; cudaGetSymbolAddress(&p, s); return (__nv_bfloat16*)p; }

extern "C" void kernel_launch(void* const* d_in, const int* in_sizes, int n_in,
                              void* d_out, int out_size)
{
    const float* xs      = (const float*)d_in[0];
    const float* attn_q  = (const float*)d_in[1];
    const float* attn_k  = (const float*)d_in[2];
    const float* attn_v  = (const float*)d_in[3];
    const float* attn_o  = (const float*)d_in[4];
    const float* attn_r  = (const float*)d_in[5];
    const float* mem_f   = (const float*)d_in[6];
    const float* mem_q   = (const float*)d_in[7];
    const float* mem_k   = (const float*)d_in[8];
    const float* mem_v   = (const float*)d_in[9];
    const float* mem_o   = (const float*)d_in[10];
    const float* mem_r   = (const float*)d_in[11];
    const float* mem_beta= (const float*)d_in[12];
    const float* mem_dec = (const float*)d_in[13];
    const float* mem_l   = (const float*)d_in[14];
    const float* ff_in1  = (const float*)d_in[15];
    const float* ff_in2  = (const float*)d_in[16];
    const float* ff_out  = (const float*)d_in[17];
    const float* sn1     = (const float*)d_in[18];
    const float* sn2     = (const float*)d_in[19];
    float* out = (float*)d_out;

    float* xn   = sym(B_xn);   float* q_   = sym(B_q);    float* k_   = sym(B_k);
    float* qhi  = sym(B_qhi);  float* klo  = sym(B_klo);  float* khi  = sym(B_khi);
    float* v_   = sym(B_v);    float* A_   = sym(B_A);
    float* gate = sym(B_gate); float* accb = sym(B_acc);
    float* memF = sym(B_memF); float* memV = sym(B_memV); float* memQ = sym(B_memQ);
    float* gam  = sym(B_gam);  float* bg   = sym(B_bg);   float* wkT  = sym(B_wkT);
    float* qk2  = sym(B_qk2);  float* lq   = sym(B_lq);   float* mems = sym(B_mems);
    float* memY = sym(B_memY); float* x1   = sym(B_x1);   float* x2n  = sym(B_x2n);
    float* h1   = sym(B_h1);   float* part = sym(B_part);

    __nv_bfloat16* xn3  = symb(C_xn3);  __nv_bfloat16* q3   = symb(C_q3);
    __nv_bfloat16* y3   = symb(C_y3);   __nv_bfloat16* memQ3= symb(C_memQ3);
    __nv_bfloat16* memY3= symb(C_memY3);__nv_bfloat16* x2n3 = symb(C_x2n3);
    __nv_bfloat16* h23  = symb(C_h23);
    __nv_bfloat16* aq3  = symb(W_aq3);  __nv_bfloat16* ak3  = symb(W_ak3);
    __nv_bfloat16* av3  = symb(W_av3);  __nv_bfloat16* ao3  = symb(W_ao3);
    __nv_bfloat16* ar3  = symb(W_ar3);  __nv_bfloat16* mv3  = symb(W_mv3);
    __nv_bfloat16* mq3  = symb(W_mq3);  __nv_bfloat16* mr3  = symb(W_mr3);
    __nv_bfloat16* wk3  = symb(W_wk3);  __nv_bfloat16* mo3  = symb(W_mo3);
    __nv_bfloat16* f13  = symb(W_f13);  __nv_bfloat16* f23  = symb(W_f23);
    __nv_bfloat16* fo3  = symb(W_fo3);

    cudaFuncSetAttribute(gemm_bf16<EPI_NONE>,           cudaFuncAttributeMaxDynamicSharedMemorySize, GB_SMEM);
    cudaFuncSetAttribute(gemm_bf16<EPI_GATE>,           cudaFuncAttributeMaxDynamicSharedMemorySize, GB_SMEM);
    cudaFuncSetAttribute(gemm_bf16<EPI_GATE_ADD2>,      cudaFuncAttributeMaxDynamicSharedMemorySize, GB_SMEM);
    cudaFuncSetAttribute(gemm_bf16<EPI_SILU_MUL_SPLIT>, cudaFuncAttributeMaxDynamicSharedMemorySize, GB_SMEM);
    cudaFuncSetAttribute(gemm_bf16<EPI_ADD>,            cudaFuncAttributeMaxDynamicSharedMemorySize, GB_SMEM);

    const dim3 blk256(256);
#define CVTA(src, dst, M_, K_) cvtA_k<<<(unsigned)((size_t)(M_) * (K_) / 2 / 256), blk256>>>(src, dst, (K_) / 2)
#define CVTB(src, dst, M_, K_) cvtB_k<<<(unsigned)((size_t)(M_) * (K_) / 2 / 256), blk256>>>(src, dst, (K_) / 2)
#define GB(EPI_, gx, gy, Aa, Bb, Dd, Gg, Rr1, Rr2, Mm, Nn, Kk)                                  \
    gemm_bf16<EPI_><<<dim3(gx, gy, 1), blk256, GB_SMEM>>>(Aa, Bb, Dd, Gg, Rr1, Rr2, Mm, Nn, Kk, Kk)
// split-K x4 for N=256 GEMMs: partials into `part`, then fixed-order reduce
#define GBSK4(Aa, Bb, Dd, Kk)                                                                    \
    do {                                                                                         \
        gemm_bf16<EPI_NONE><<<dim3(2, 16, 4), blk256, GB_SMEM>>>(                                \
            Aa, Bb, part, nullptr, nullptr, nullptr, T, QD, Kk, (Kk) / 4);                       \
        redk<<<T * QD / 1024, blk256>>>(part, Dd, T * QD / 4);                                   \
    } while (0)

    // weight conversions
    CVTB(attn_q, aq3, QD, XD);
    CVTB(attn_k, ak3, QD, QD);
    CVTB(attn_v, av3, XD, XD);
    CVTB(attn_o, ao3, XD, XD);
    CVTB(attn_r, ar3, XD, XD);
    CVTB(mem_v,  mv3, MD, XD);
    CVTB(mem_q,  mq3, MD, XD);
    CVTB(mem_r,  mr3, XD, XD);
    CVTB(mem_o,  mo3, XD, MD);
    CVTB(ff_in1, f13, FFD, XD);
    CVTB(ff_in2, f23, FFD, XD);
    CVTB(ff_out, fo3, XD, FFD);
    transpose256<<<MD, MD>>>(mem_k, wkT);
    CVTB(wkT, wk3, MD, MD);

    // 1. xn = scale_norm(xs, sn1), fused split
    scale_norm_split<<<T, blk256>>>(xs, xn, xn3, sn1);
    // 2-5. attn projections + gate (N=256 ones via split-K x4)
    GBSK4(xn3, aq3, q_, 3 * XD);
    CVTA(q_, q3, T, QD);
    GBSK4(q3, ak3, k_, 3 * QD);
    GB(EPI_NONE, 16, 16, xn3, av3, v_, nullptr, nullptr, nullptr, T, XD, 3 * XD);
    GB(EPI_NONE, 16, 16, xn3, ar3, gate, nullptr, nullptr, nullptr, T, XD, 3 * XD);
    // 6. attention core
    rope_all<<<T, 128>>>(q_, k_, qhi, klo, khi);
    attn_score<<<T / 8, blk256>>>(qhi, klo, khi, A_);
    attn_av<<<dim3(8, 4, 32), blk256>>>(A_, v_, y3);
    // 7. attn out = (y @ Wo^T) * sigmoid(gate)
    GB(EPI_GATE, 16, 16, y3, ao3, accb, gate, nullptr, nullptr, T, XD, 3 * XD);
    // 8-11. mem projections + mem gate
    gemm_tn<EPI_SIGMOID><<<dim3(1, 16), blk256>>>(xn, mem_f, memF, nullptr, nullptr, nullptr, T, MN, XD);
    GBSK4(xn3, mv3, memV, 3 * XD);
    GBSK4(xn3, mq3, memQ, 3 * XD);
    GB(EPI_NONE, 16, 16, xn3, mr3, gate, nullptr, nullptr, nullptr, T, XD, 3 * XD);
    // 12-13. scan
    mem_prep<<<MN, MD>>>(mem_beta, mem_dec, gam, bg);
    mem_scan<<<MN, MD>>>(memF, memV, gam, bg, mems);
    // 14. readout
    CVTA(memQ, memQ3, T, MD);
    GBSK4(memQ3, wk3, qk2, 3 * MD);
    gemm_tn<EPI_NONE><<<dim3(1, 16), blk256>>>(memQ, mem_l, lq, nullptr, nullptr, nullptr, T, MN, MD);
    mem_readout<<<T, blk256>>>(mems, qk2, lq, memY);
    // 15. x1 = (memY @ mem_o^T)*sigmoid(gate) + attn_out + xs
    CVTA(memY, memY3, T, MD);
    GB(EPI_GATE_ADD2, 16, 16, memY3, mo3, x1, gate, accb, xs, T, XD, 3 * MD);
    // 16-19. FF block (h2 split fused into SILU epilogue)
    scale_norm_split<<<T, blk256>>>(x1, x2n, x2n3, sn2);
    GB(EPI_NONE, 22, 16, x2n3, f13, h1, nullptr, nullptr, nullptr, T, FFD, 3 * XD);
    GB(EPI_SILU_MUL_SPLIT, 22, 16, x2n3, f23, (float*)h23, h1, nullptr, nullptr, T, FFD, 3 * XD);
    GB(EPI_ADD, 16, 16, h23, fo3, out, nullptr, x1, nullptr, T, XD, 3 * FFD);
#undef CVTA
#undef CVTB
#undef GB
#undef GBSK4
}

// round 11
// speedup vs baseline: 2.1783x; 1.0645x over previous
#include <cuda_runtime.h>
#include <cuda_bf16.h>
#include <math.h>
#include <stdint.h>

// ---------------- problem dims ----------------
#define T    2048
#define XD   2048
#define QD   256
#define MN   64
#define MD   256
#define DCD  64
#define FFD  2816
#define CH   64

// ---------------- fp32 scratch ----------------
__device__ float B_xn  [(size_t)T*XD];
__device__ float B_q   [(size_t)T*QD];
__device__ float B_k   [(size_t)T*QD];
__device__ float B_qhi [(size_t)T*QD];
__device__ float B_klo [(size_t)T*QD];
__device__ float B_khi [(size_t)T*QD];
__device__ float B_v   [(size_t)T*XD];
__device__ float B_A   [(size_t)T*2*CH];
__device__ float B_gate[(size_t)T*XD];
__device__ float B_acc [(size_t)T*XD];
__device__ float B_memF[(size_t)T*MN];
__device__ float B_memV[(size_t)T*MD];
__device__ float B_memQ[(size_t)T*MD];
__device__ float B_gam [(size_t)MN*MD];
__device__ float B_bg  [(size_t)MN*MD];
__device__ float B_wkT [(size_t)MD*MD];
__device__ float B_qk2 [(size_t)T*MD];
__device__ float B_lq  [(size_t)T*MN];
__device__ float B_mems[(size_t)T*MN*MD];
__device__ float B_memY[(size_t)T*MD];
__device__ float B_x1  [(size_t)T*XD];
__device__ float B_x2n [(size_t)T*XD];
__device__ float B_h1  [(size_t)T*FFD];
__device__ float B_part[(size_t)4*T*MD];    // split-K x4 partials (N=256 GEMMs)
__device__ float B_partF[(size_t)2*T*FFD];  // split-K x2 partials (FF GEMMs)

// ---------------- bf16 split scratch: A-side [hi|lo|hi], B-side [hi|hi|lo] ----------------
__device__ __nv_bfloat16 C_xn3  [(size_t)T*3*XD];
__device__ __nv_bfloat16 C_q3   [(size_t)T*3*QD];
__device__ __nv_bfloat16 C_y3   [(size_t)T*3*XD];
__device__ __nv_bfloat16 C_memQ3[(size_t)T*3*MD];
__device__ __nv_bfloat16 C_memY3[(size_t)T*3*MD];
__device__ __nv_bfloat16 C_x2n3 [(size_t)T*3*XD];
__device__ __nv_bfloat16 C_h23  [(size_t)T*3*FFD];
__device__ __nv_bfloat16 W_aq3  [(size_t)QD*3*XD];
__device__ __nv_bfloat16 W_ak3  [(size_t)QD*3*QD];
__device__ __nv_bfloat16 W_av3  [(size_t)XD*3*XD];
__device__ __nv_bfloat16 W_ao3  [(size_t)XD*3*XD];
__device__ __nv_bfloat16 W_ar3  [(size_t)XD*3*XD];
__device__ __nv_bfloat16 W_mv3  [(size_t)MD*3*XD];
__device__ __nv_bfloat16 W_mq3  [(size_t)MD*3*XD];
__device__ __nv_bfloat16 W_mr3  [(size_t)XD*3*XD];
__device__ __nv_bfloat16 W_wk3  [(size_t)MD*3*MD];
__device__ __nv_bfloat16 W_mo3  [(size_t)XD*3*MD];
__device__ __nv_bfloat16 W_f13  [(size_t)FFD*3*XD];
__device__ __nv_bfloat16 W_f23  [(size_t)FFD*3*XD];
__device__ __nv_bfloat16 W_fo3  [(size_t)XD*3*FFD];

__device__ __forceinline__ float sigf(float x) { return 1.f / (1.f + expf(-x)); }

enum { EPI_NONE = 0, EPI_SIGMOID, EPI_GATE, EPI_GATE_ADD2, EPI_SILU_MUL_SPLIT, EPI_ADD };

__device__ __forceinline__ void split2(float v0, float v1, uint32_t& hi, uint32_t& lo)
{
    asm("cvt.rn.bf16x2.f32 %0, %1, %2;" : "=r"(hi) : "f"(v1), "f"(v0));
    float h0 = __uint_as_float(hi << 16);
    float h1 = __uint_as_float(hi & 0xffff0000u);
    asm("cvt.rn.bf16x2.f32 %0, %1, %2;" : "=r"(lo) : "f"(v1 - h1), "f"(v0 - h0));
}

// ---------------- fused split conversion (4 elems/thread, compile-time shapes) ----------------
// ASIDE: dst triple = [hi|lo|hi]; else (weights) [hi|hi|lo]
template <int KQ, bool ASIDE>
__device__ __forceinline__ void cvt_one(const float* __restrict__ src,
                                        __nv_bfloat16* __restrict__ dst, int b, int tid)
{
    int idx4 = b * 256 + tid;
    int row = idx4 / KQ;
    int cq  = idx4 - row * KQ;
    const int K = KQ * 4;
    float4 v = ((const float4*)src)[idx4];
    uint32_t h0, l0, h1, l1;
    split2(v.x, v.y, h0, l0);
    split2(v.z, v.w, h1, l1);
    __nv_bfloat16* dr = dst + (size_t)row * 3 * K + cq * 4;
    uint2 hh = make_uint2(h0, h1), ll = make_uint2(l0, l1);
    *(uint2*)dr = hh;
    *(uint2*)(dr + K)     = ASIDE ? ll : hh;
    *(uint2*)(dr + 2 * K) = ASIDE ? hh : ll;
}

// one launch converts all 13 weight matrices (shapes compile-time)
__global__ __launch_bounds__(256) void cvt_weights_all(
    const float* aq, const float* ak, const float* av, const float* ao, const float* ar,
    const float* mv, const float* mq, const float* mr, const float* wk, const float* mo,
    const float* f1, const float* f2, const float* fo,
    __nv_bfloat16* aq3, __nv_bfloat16* ak3, __nv_bfloat16* av3, __nv_bfloat16* ao3,
    __nv_bfloat16* ar3, __nv_bfloat16* mv3, __nv_bfloat16* mq3, __nv_bfloat16* mr3,
    __nv_bfloat16* wk3, __nv_bfloat16* mo3, __nv_bfloat16* f13, __nv_bfloat16* f23,
    __nv_bfloat16* fo3)
{
    int b = blockIdx.x, tid = threadIdx.x;
    if (b < 512)  { cvt_one<512, false>(aq, aq3, b, tid); return; }  b -= 512;   // 256x2048
    if (b < 64)   { cvt_one<64,  false>(ak, ak3, b, tid); return; }  b -= 64;    // 256x256
    if (b < 4096) { cvt_one<512, false>(av, av3, b, tid); return; }  b -= 4096;  // 2048x2048
    if (b < 4096) { cvt_one<512, false>(ao, ao3, b, tid); return; }  b -= 4096;
    if (b < 4096) { cvt_one<512, false>(ar, ar3, b, tid); return; }  b -= 4096;
    if (b < 512)  { cvt_one<512, false>(mv, mv3, b, tid); return; }  b -= 512;   // 256x2048
    if (b < 512)  { cvt_one<512, false>(mq, mq3, b, tid); return; }  b -= 512;
    if (b < 4096) { cvt_one<512, false>(mr, mr3, b, tid); return; }  b -= 4096;
    if (b < 64)   { cvt_one<64,  false>(wk, wk3, b, tid); return; }  b -= 64;    // 256x256
    if (b < 512)  { cvt_one<64,  false>(mo, mo3, b, tid); return; }  b -= 512;   // 2048x256
    if (b < 5632) { cvt_one<512, false>(f1, f13, b, tid); return; }  b -= 5632;  // 2816x2048
    if (b < 5632) { cvt_one<512, false>(f2, f23, b, tid); return; }  b -= 5632;
    cvt_one<704, false>(fo, fo3, b, tid);                                        // 2048x2816
}
#define CVTW_BLOCKS 35456

// activation split (A-side), compile-time KQ
template <int KQ>
__global__ __launch_bounds__(256) void cvtA_t(const float* __restrict__ src,
                                              __nv_bfloat16* __restrict__ dst)
{
    cvt_one<KQ, true>(src, dst, blockIdx.x, threadIdx.x);
}

// ---------------- split-K reduces ----------------
__global__ __launch_bounds__(256) void redk(const float* __restrict__ p,
                                            float* __restrict__ o, int n4)
{
    int i = blockIdx.x * 256 + threadIdx.x;
    const float4* p4 = (const float4*)p;
    float4 a = p4[i], b = p4[i + n4], c = p4[i + 2 * n4], d = p4[i + 3 * n4];
    float4 r;
    r.x = a.x + b.x + c.x + d.x;
    r.y = a.y + b.y + c.y + d.y;
    r.z = a.z + b.z + c.z + d.z;
    r.w = a.w + b.w + c.w + d.w;
    ((float4*)o)[i] = r;
}

__global__ __launch_bounds__(256) void redk2(const float* __restrict__ p,
                                             float* __restrict__ o, int n4)
{
    int i = blockIdx.x * 256 + threadIdx.x;
    const float4* p4 = (const float4*)p;
    float4 a = p4[i], b = p4[i + n4];
    float4 r = make_float4(a.x + b.x, a.y + b.y, a.z + b.z, a.w + b.w);
    ((float4*)o)[i] = r;
}

// reduce 2 planes + silu gate + A-side bf16 split (for FF h2)
__global__ __launch_bounds__(256) void red2_silu_split(
    const float* __restrict__ p, const float* __restrict__ h1,
    __nv_bfloat16* __restrict__ o3)
{
    int idx4 = blockIdx.x * 256 + threadIdx.x;
    const int KQ = FFD / 4;   // 704
    int row = idx4 / KQ;
    int cq  = idx4 - row * KQ;
    const float4* p4 = (const float4*)p;
    float4 a = p4[idx4], b = p4[idx4 + (size_t)T * FFD / 4];
    float4 g = ((const float4*)h1)[idx4];
    float c0 = (a.x + b.x) * (g.x * sigf(g.x));
    float c1 = (a.y + b.y) * (g.y * sigf(g.y));
    float c2 = (a.z + b.z) * (g.z * sigf(g.z));
    float c3 = (a.w + b.w) * (g.w * sigf(g.w));
    uint32_t h0, l0, h1b, l1;
    split2(c0, c1, h0, l0);
    split2(c2, c3, h1b, l1);
    __nv_bfloat16* dr = o3 + (size_t)row * 3 * FFD + cq * 4;
    *(uint2*)dr             = make_uint2(h0, h1b);
    *(uint2*)(dr + FFD)     = make_uint2(l0, l1);
    *(uint2*)(dr + 2 * FFD) = make_uint2(h0, h1b);
}

// =====================================================================
//  bf16 mma.sync GEMM over packed K3 operands (ldmatrix + SW128 smem)
//  tile 128x128, BK=64, 3-stage cp.async, one barrier per K-iter
//  split-K via grid.z: Kchunk per z, D offset z*M*N
// =====================================================================
#define SWZ(off) ((off) ^ (((off) >> 3) & 0x70))
#define TILE_B   16384
#define STAGE_B  (2 * TILE_B)
#define GB_SMEM  (3 * STAGE_B)   // 96 KB

template <int EPI>
__device__ __forceinline__ float epi_apply(float c, size_t idx,
                                           const float* __restrict__ G,
                                           const float* __restrict__ R1,
                                           const float* __restrict__ R2)
{
    if (EPI == EPI_SIGMOID)        c = sigf(c);
    else if (EPI == EPI_GATE)      c = c * sigf(G[idx]);
    else if (EPI == EPI_GATE_ADD2) c = c * sigf(G[idx]) + R1[idx] + R2[idx];
    else if (EPI == EPI_ADD)       c = c + R1[idx];
    return c;
}

__device__ __forceinline__ void mma16(float* c, uint32_t a0, uint32_t a1, uint32_t a2, uint32_t a3,
                                      uint32_t b0, uint32_t b1)
{
    asm volatile(
        "mma.sync.aligned.m16n8k16.row.col.f32.bf16.bf16.f32 "
        "{%0,%1,%2,%3}, {%4,%5,%6,%7}, {%8,%9}, {%0,%1,%2,%3};"
        : "+f"(c[0]), "+f"(c[1]), "+f"(c[2]), "+f"(c[3])
        : "r"(a0), "r"(a1), "r"(a2), "r"(a3), "r"(b0), "r"(b1));
}

__device__ __forceinline__ void ldsm4(uint32_t addr, uint32_t& r0, uint32_t& r1,
                                      uint32_t& r2, uint32_t& r3)
{
    asm volatile("ldmatrix.sync.aligned.m8n8.x4.shared.b16 {%0,%1,%2,%3}, [%4];"
                 : "=r"(r0), "=r"(r1), "=r"(r2), "=r"(r3) : "r"(addr));
}

template <int EPI>
__global__ __launch_bounds__(256, 2) void gemm_bf16(
    const __nv_bfloat16* __restrict__ A, const __nv_bfloat16* __restrict__ B,
    float* __restrict__ D,
    const float* __restrict__ G, const float* __restrict__ R1, const float* __restrict__ R2,
    int M, int N, int Kstride, int Kchunk)
{
    extern __shared__ __nv_bfloat16 smem[];

    const int tid  = threadIdx.x;
    const int wid  = tid >> 5, lane = tid & 31;
    const int wm   = wid & 1, wn = wid >> 1;
    const int g    = lane >> 2, tg = lane & 3;
    const int m0   = blockIdx.y * 128;
    const int n0   = blockIdx.x * 128;
    const int z    = blockIdx.z;

    D += (size_t)z * M * N;

    float acc[4][4][4];
#pragma unroll
    for (int mt = 0; mt < 4; mt++)
#pragma unroll
        for (int nt = 0; nt < 4; nt++)
#pragma unroll
            for (int e = 0; e < 4; e++) acc[mt][nt][e] = 0.f;

    const int KT = Kchunk >> 6;

    uint32_t base;
    asm("{ .reg .u64 t; cvta.to.shared.u64 t, %1; cvt.u32.u64 %0, t; }" : "=r"(base) : "l"(smem));

    uint32_t swOff[4];
    const __nv_bfloat16* aG[4];
    const __nv_bfloat16* bG[4];
#pragma unroll
    for (int l = 0; l < 4; l++) {
        int idx = tid + l * 256;
        int r = idx >> 3, c = idx & 7;
        uint32_t off = r * 128 + c * 16;
        swOff[l] = SWZ(off);
        aG[l] = A + (size_t)(m0 + r) * Kstride + (size_t)z * Kchunk + c * 8;
        bG[l] = B + (size_t)(n0 + r) * Kstride + (size_t)z * Kchunk + c * 8;
    }

    const int lmRow = ((lane >> 3) & 1) * 8 + (lane & 7);
    const int lmCB  = ((lane >> 4) & 1) * 16;

#define LOADG(buf, kt)                                                                     \
    {                                                                                      \
        uint32_t aB_ = base + (buf) * STAGE_B;                                             \
        uint32_t bB_ = aB_ + TILE_B;                                                       \
        _Pragma("unroll")                                                                  \
        for (int l = 0; l < 4; l++) {                                                      \
            asm volatile("cp.async.ca.shared.global [%0], [%1], 16;"                       \
                         :: "r"(aB_ + swOff[l]), "l"(aG[l] + (size_t)(kt) * 64));          \
            asm volatile("cp.async.ca.shared.global [%0], [%1], 16;"                       \
                         :: "r"(bB_ + swOff[l]), "l"(bG[l] + (size_t)(kt) * 64));          \
        }                                                                                  \
    }

    LOADG(0, 0);
    asm volatile("cp.async.commit_group;");
    if (KT > 1) LOADG(1, 1);
    asm volatile("cp.async.commit_group;");

    int buf = 0;
    for (int kt = 0; kt < KT; kt++) {
        asm volatile("cp.async.wait_group 1;");
        __syncthreads();

        if (kt + 2 < KT) {
            int nb = buf + 2; if (nb >= 3) nb -= 3;
            LOADG(nb, kt + 2);
        }
        asm volatile("cp.async.commit_group;");

        const uint32_t aBuf = base + buf * STAGE_B;
        const uint32_t bBuf = aBuf + TILE_B;

#pragma unroll
        for (int ks = 0; ks < 4; ks++) {
            const int kbB = ks * 32;
            uint32_t bf[4][2];
#pragma unroll
            for (int h = 0; h < 2; h++) {
                uint32_t off = (uint32_t)(wn * 32 + h * 16 + lmRow) * 128 + kbB + lmCB;
                ldsm4(bBuf + SWZ(off), bf[2 * h][0], bf[2 * h + 1][0], bf[2 * h][1], bf[2 * h + 1][1]);
            }
            uint32_t af[4][4];
#pragma unroll
            for (int mt = 0; mt < 4; mt++) {
                uint32_t off = (uint32_t)(wm * 64 + mt * 16 + lmRow) * 128 + kbB + lmCB;
                ldsm4(aBuf + SWZ(off), af[mt][0], af[mt][1], af[mt][2], af[mt][3]);
            }
#pragma unroll
            for (int mt = 0; mt < 4; mt++)
#pragma unroll
                for (int nt = 0; nt < 4; nt++)
                    mma16(acc[mt][nt], af[mt][0], af[mt][1], af[mt][2], af[mt][3],
                          bf[nt][0], bf[nt][1]);
        }
        if (++buf >= 3) buf = 0;
    }
#undef LOADG

#pragma unroll
    for (int mt = 0; mt < 4; mt++) {
        int r0 = m0 + wm * 64 + mt * 16 + g;
#pragma unroll
        for (int nt = 0; nt < 4; nt++) {
            int col = n0 + wn * 32 + nt * 8 + tg * 2;
            size_t i0 = (size_t)r0 * N + col;
            size_t i1 = i0 + (size_t)8 * N;
            if (EPI == EPI_SILU_MUL_SPLIT) {
                __nv_bfloat16* D3 = (__nv_bfloat16*)D;
                float g0 = G[i0], g1 = G[i0 + 1], g2 = G[i1], g3 = G[i1 + 1];
                float c0 = acc[mt][nt][0] * (g0 * sigf(g0));
                float c1 = acc[mt][nt][1] * (g1 * sigf(g1));
                float c2 = acc[mt][nt][2] * (g2 * sigf(g2));
                float c3 = acc[mt][nt][3] * (g3 * sigf(g3));
                uint32_t h, l;
                split2(c0, c1, h, l);
                size_t b0 = (size_t)r0 * 3 * N + col;
                *(uint32_t*)(D3 + b0)         = h;
                *(uint32_t*)(D3 + b0 + N)     = l;
                *(uint32_t*)(D3 + b0 + 2 * N) = h;
                split2(c2, c3, h, l);
                size_t b1 = (size_t)(r0 + 8) * 3 * N + col;
                *(uint32_t*)(D3 + b1)         = h;
                *(uint32_t*)(D3 + b1 + N)     = l;
                *(uint32_t*)(D3 + b1 + 2 * N) = h;
            } else {
                float2 o0, o1;
                o0.x = epi_apply<EPI>(acc[mt][nt][0], i0,     G, R1, R2);
                o0.y = epi_apply<EPI>(acc[mt][nt][1], i0 + 1, G, R1, R2);
                o1.x = epi_apply<EPI>(acc[mt][nt][2], i1,     G, R1, R2);
                o1.y = epi_apply<EPI>(acc[mt][nt][3], i1 + 1, G, R1, R2);
                *(float2*)&D[i0] = o0;
                *(float2*)&D[i1] = o1;
            }
        }
    }
}

// ---------------- legacy FFMA GEMM (tiny-N cases: N=64) ----------------
#define BM 128
#define BN 128
#define BKK 16

template <int EPI>
__global__ __launch_bounds__(256) void gemm_tn(
    const float* __restrict__ A, const float* __restrict__ B, float* __restrict__ D,
    const float* __restrict__ G, const float* __restrict__ R1, const float* __restrict__ R2,
    int M, int N, int K)
{
    __shared__ float As[BKK][BM + 4];
    __shared__ float Bs[BKK][BN + 4];

    const int tid = threadIdx.x;
    const int m0 = blockIdx.y * BM;
    const int n0 = blockIdx.x * BN;
    const int tx = tid & 15;
    const int ty = tid >> 4;

    float acc[8][8];
#pragma unroll
    for (int i = 0; i < 8; i++)
#pragma unroll
        for (int j = 0; j < 8; j++) acc[i][j] = 0.f;

    for (int k0 = 0; k0 < K; k0 += BKK) {
#pragma unroll
        for (int l = 0; l < 2; l++) {
            int qi  = tid + l * 256;
            int row = qi >> 2;
            int kk  = (qi & 3) * 4;
            float4 av = *(const float4*)&A[(size_t)(m0 + row) * K + k0 + kk];
            As[kk + 0][row] = av.x; As[kk + 1][row] = av.y;
            As[kk + 2][row] = av.z; As[kk + 3][row] = av.w;
        }
#pragma unroll
        for (int l = 0; l < 2; l++) {
            int qi  = tid + l * 256;
            int row = qi >> 2;
            int kk  = (qi & 3) * 4;
            float4 bv = make_float4(0.f, 0.f, 0.f, 0.f);
            if (n0 + row < N) bv = *(const float4*)&B[(size_t)(n0 + row) * K + k0 + kk];
            Bs[kk + 0][row] = bv.x; Bs[kk + 1][row] = bv.y;
            Bs[kk + 2][row] = bv.z; Bs[kk + 3][row] = bv.w;
        }
        __syncthreads();

#pragma unroll
        for (int kk = 0; kk < BKK; kk++) {
            float a[8], b[8];
#pragma unroll
            for (int i = 0; i < 8; i++) a[i] = As[kk][ty * 8 + i];
#pragma unroll
            for (int j = 0; j < 8; j++) b[j] = Bs[kk][tx * 8 + j];
#pragma unroll
            for (int i = 0; i < 8; i++)
#pragma unroll
                for (int j = 0; j < 8; j++) acc[i][j] += a[i] * b[j];
        }
        __syncthreads();
    }

#pragma unroll
    for (int i = 0; i < 8; i++) {
        int row = m0 + ty * 8 + i;
#pragma unroll
        for (int j = 0; j < 8; j++) {
            int col = n0 + tx * 8 + j;
            if (col < N) {
                size_t idx = (size_t)row * N + col;
                D[idx] = epi_apply<EPI>(acc[i][j], idx, G, R1, R2);
            }
        }
    }
}

// ---------------- scale_norm with fused A-side split ----------------
__global__ __launch_bounds__(256) void scale_norm_split(
    const float* __restrict__ x, float* __restrict__ o,
    __nv_bfloat16* __restrict__ o3, const float* __restrict__ g)
{
    int t = blockIdx.x;
    const float4* xr = (const float4*)(x + (size_t)t * XD);
    float4 v0 = xr[threadIdx.x];
    float4 v1 = xr[threadIdx.x + 256];
    float s = v0.x*v0.x + v0.y*v0.y + v0.z*v0.z + v0.w*v0.w
            + v1.x*v1.x + v1.y*v1.y + v1.z*v1.z + v1.w*v1.w;
    for (int off = 16; off; off >>= 1) s += __shfl_xor_sync(0xffffffffu, s, off);
    __shared__ float red[8];
    int w = threadIdx.x >> 5, lane = threadIdx.x & 31;
    if (lane == 0) red[w] = s;
    __syncthreads();
    float tot = red[0] + red[1] + red[2] + red[3] + red[4] + red[5] + red[6] + red[7];
    float sc = g[0] / (sqrtf(tot) + 1e-8f);
    v0.x *= sc; v0.y *= sc; v0.z *= sc; v0.w *= sc;
    v1.x *= sc; v1.y *= sc; v1.z *= sc; v1.w *= sc;
    float4* orow = (float4*)(o + (size_t)t * XD);
    orow[threadIdx.x] = v0;
    orow[threadIdx.x + 256] = v1;
    __nv_bfloat16* r3 = o3 + (size_t)t * 3 * XD;
    uint32_t h, l;
    int c0 = threadIdx.x * 4;
    split2(v0.x, v0.y, h, l);
    *(uint32_t*)(r3 + c0) = h; *(uint32_t*)(r3 + XD + c0) = l; *(uint32_t*)(r3 + 2 * XD + c0) = h;
    split2(v0.z, v0.w, h, l);
    *(uint32_t*)(r3 + c0 + 2) = h; *(uint32_t*)(r3 + XD + c0 + 2) = l; *(uint32_t*)(r3 + 2 * XD + c0 + 2) = h;
    int c1 = c0 + 1024;
    split2(v1.x, v1.y, h, l);
    *(uint32_t*)(r3 + c1) = h; *(uint32_t*)(r3 + XD + c1) = l; *(uint32_t*)(r3 + 2 * XD + c1) = h;
    split2(v1.z, v1.w, h, l);
    *(uint32_t*)(r3 + c1 + 2) = h; *(uint32_t*)(r3 + XD + c1 + 2) = l; *(uint32_t*)(r3 + 2 * XD + c1 + 2) = h;
}

// ---------------- RoPE ----------------
__global__ __launch_bounds__(128) void rope_all(
    const float* __restrict__ q, const float* __restrict__ k,
    float* __restrict__ qhi, float* __restrict__ klo, float* __restrict__ khi)
{
    int t = blockIdx.x, j = threadIdx.x;
    int r = t & 63;
    float freq = powf(10000.f, -(float)j / 128.f);
    float slo, clo, shi, chi;
    sincosf((float)r * freq, &slo, &clo);
    sincosf((float)(64 + r) * freq, &shi, &chi);
    size_t base = (size_t)t * QD + 2 * j;
    float qe = q[base], qo = q[base + 1];
    qhi[base]     = qe * chi - qo * shi;
    qhi[base + 1] = qo * chi + qe * shi;
    float ke = k[base], ko = k[base + 1];
    klo[base]     = ke * clo - ko * slo;
    klo[base + 1] = ko * clo + ke * slo;
    khi[base]     = ke * chi - ko * shi;
    khi[base + 1] = ko * chi + ke * shi;
}

// ---------------- attention scores + softmax ----------------
__global__ __launch_bounds__(256) void attn_score(
    const float* __restrict__ qr, const float* __restrict__ klo,
    const float* __restrict__ khi, float* __restrict__ Aout)
{
    int w = threadIdx.x >> 5, lane = threadIdx.x & 31;
    int t = blockIdx.x * 8 + w;
    int c = t >> 6, r = t & 63;
    float qreg[8];
#pragma unroll
    for (int i = 0; i < 8; i++) qreg[i] = qr[(size_t)t * QD + i * 32 + lane];

    __shared__ float s_s[8][128];
    for (int m = 0; m < 128; m++) {
        float sc;
        if (c == 0 && m < 64) {
            sc = 0.f;
        } else {
            const float* kp = (m < 64)
                ? &klo[(size_t)((c - 1) * 64 + m) * QD]
                : &khi[(size_t)(c * 64 + (m - 64)) * QD];
            float d = 0.f;
#pragma unroll
            for (int i = 0; i < 8; i++) d += qreg[i] * kp[i * 32 + lane];
            for (int off = 16; off; off >>= 1) d += __shfl_xor_sync(0xffffffffu, d, off);
            sc = d * (1.f / 16.f);
        }
        if (m > r + 64) sc = -1e30f;
        if (lane == 0) s_s[w][m] = sc;
    }
    __syncwarp();
    float a0 = s_s[w][lane], a1 = s_s[w][lane + 32], a2 = s_s[w][lane + 64], a3 = s_s[w][lane + 96];
    float mx = fmaxf(fmaxf(a0, a1), fmaxf(a2, a3));
    for (int off = 16; off; off >>= 1) mx = fmaxf(mx, __shfl_xor_sync(0xffffffffu, mx, off));
    float e0 = expf(a0 - mx), e1 = expf(a1 - mx), e2 = expf(a2 - mx), e3 = expf(a3 - mx);
    float sm = e0 + e1 + e2 + e3;
    for (int off = 16; off; off >>= 1) sm += __shfl_xor_sync(0xffffffffu, sm, off);
    float inv = 1.f / sm;
    size_t ob = (size_t)t * 128;
    Aout[ob + lane]      = e0 * inv;
    Aout[ob + lane + 32] = e1 * inv;
    Aout[ob + lane + 64] = e2 * inv;
    Aout[ob + lane + 96] = e3 * inv;
}

// ---------------- y = A @ v2, fused A-side split into y3 ----------------
__global__ __launch_bounds__(256) void attn_av(
    const float* __restrict__ Aat, const float* __restrict__ v,
    __nv_bfloat16* __restrict__ y3)
{
    int c = blockIdx.z, rg = blockIdx.y, ct = blockIdx.x;
    int col = ct * 256 + threadIdx.x;
    __shared__ float As[16][128];
    for (int idx = threadIdx.x; idx < 16 * 128; idx += 256) {
        int rr = idx >> 7, mm = idx & 127;
        As[rr][mm] = Aat[(size_t)(c * 64 + rg * 16 + rr) * 128 + mm];
    }
    __syncthreads();
    float acc[16];
#pragma unroll
    for (int r = 0; r < 16; r++) acc[r] = 0.f;
    int mstart = (c == 0) ? 64 : 0;
    for (int m = mstart; m < 128; m++) {
        float vv = v[(size_t)((c - 1) * 64 + m) * XD + col];
#pragma unroll
        for (int r = 0; r < 16; r++) acc[r] += As[r][m] * vv;
    }
#pragma unroll
    for (int r = 0; r < 16; r++) {
        float val = acc[r];
        __nv_bfloat16 hb = __float2bfloat16(val);
        __nv_bfloat16 lb = __float2bfloat16(val - __bfloat162float(hb));
        __nv_bfloat16* yr = y3 + (size_t)(c * 64 + rg * 16 + r) * 3 * XD;
        yr[col] = hb; yr[XD + col] = lb; yr[2 * XD + col] = hb;
    }
}

// ---------------- mem prep ----------------
__global__ void mem_prep(const float* __restrict__ beta, const float* __restrict__ decay,
                         float* __restrict__ gam, float* __restrict__ bg)
{
    int n = blockIdx.x, d = threadIdx.x;
    float g = (d < MD - DCD) ? 1.f : sigf(decay[n * DCD + (d - (MD - DCD))]);
    gam[n * MD + d] = g;
    bg[n * MD + d] = g * sigf(beta[n * MD + d]);
}

// ---------------- mem scan ----------------
__global__ __launch_bounds__(256) void mem_scan(
    const float* __restrict__ F, const float* __restrict__ V,
    const float* __restrict__ gam, const float* __restrict__ bg, float* __restrict__ mems)
{
    int n = blockIdx.x, d = threadIdx.x;
    float ga = gam[n * MD + d], b = bg[n * MD + d];
    float m = 0.f;
    float fn = F[n], vn = V[d];
    for (int t = 0; t < T; t++) {
        float f = fn, vv = vn;
        if (t + 1 < T) { fn = F[(t + 1) * MN + n]; vn = V[(size_t)(t + 1) * MD + d]; }
        m = (ga - f * b) * m + f * vv;
        mems[((size_t)t * MN + n) * MD + d] = m;
    }
}

// ---------------- transpose 256x256 ----------------
__global__ void transpose256(const float* __restrict__ W, float* __restrict__ WT)
{
    int rk = blockIdx.x, cd = threadIdx.x;
    WT[cd * MD + rk] = W[rk * MD + cd];
}

// ---------------- mem readout (smem-staged: read mems once) ----------------
__global__ __launch_bounds__(256) void mem_readout2(
    const float* __restrict__ mems, const float* __restrict__ qk2,
    const float* __restrict__ lq, float* __restrict__ yout)
{
    extern __shared__ float ms[];   // MN*MD = 16384 floats = 64 KB
    __shared__ float qs[MD];
    __shared__ float as[MN];
    int t = blockIdx.x;
    int tid = threadIdx.x, w = tid >> 5, lane = tid & 31;
    qs[tid] = qk2[(size_t)t * MD + tid];
    const float4* mb4 = (const float4*)(mems + (size_t)t * MN * MD);
    float4* ms4 = (float4*)ms;
#pragma unroll
    for (int i = 0; i < 16; i++) ms4[tid + i * 256] = mb4[tid + i * 256];
    __syncthreads();
#pragma unroll
    for (int mi = 0; mi < 8; mi++) {
        int m = w * 8 + mi;
        float d = 0.f;
#pragma unroll
        for (int i = 0; i < 8; i++) d += ms[m * MD + i * 32 + lane] * qs[i * 32 + lane];
        for (int off = 16; off; off >>= 1) d += __shfl_xor_sync(0xffffffffu, d, off);
        if (lane == 0) as[m] = (d + lq[t * MN + m]) * (1.f / 16.f);
    }
    __syncthreads();
    if (w == 0) {
        float a0 = as[lane], a1 = as[lane + 32];
        float mx = fmaxf(a0, a1);
        for (int off = 16; off; off >>= 1) mx = fmaxf(mx, __shfl_xor_sync(0xffffffffu, mx, off));
        float e0 = expf(a0 - mx), e1 = expf(a1 - mx);
        float sm = e0 + e1;
        for (int off = 16; off; off >>= 1) sm += __shfl_xor_sync(0xffffffffu, sm, off);
        float inv = 1.f / sm;
        as[lane] = e0 * inv;
        as[lane + 32] = e1 * inv;
    }
    __syncthreads();
    float acc = 0.f;
    for (int m = 0; m < MN; m++) acc += as[m] * ms[m * MD + tid];
    yout[(size_t)t * MD + tid] = acc;
}

// ---------------- launcher ----------------
static float* sym(const void* s) { void* p = nullptr; cudaGetSymbolAddress(&p, s); return (float*)p; }
static __nv_bfloat16* symb(const void* s) { void* p = nullptr; cudaGetSymbolAddress(&p, s); return (__nv_bfloat16*)p; }

extern "C" void kernel_launch(void* const* d_in, const int* in_sizes, int n_in,
                              void* d_out, int out_size)
{
    const float* xs      = (const float*)d_in[0];
    const float* attn_q  = (const float*)d_in[1];
    const float* attn_k  = (const float*)d_in[2];
    const float* attn_v  = (const float*)d_in[3];
    const float* attn_o  = (const float*)d_in[4];
    const float* attn_r  = (const float*)d_in[5];
    const float* mem_f   = (const float*)d_in[6];
    const float* mem_q   = (const float*)d_in[7];
    const float* mem_k   = (const float*)d_in[8];
    const float* mem_v   = (const float*)d_in[9];
    const float* mem_o   = (const float*)d_in[10];
    const float* mem_r   = (const float*)d_in[11];
    const float* mem_beta= (const float*)d_in[12];
    const float* mem_dec = (const float*)d_in[13];
    const float* mem_l   = (const float*)d_in[14];
    const float* ff_in1  = (const float*)d_in[15];
    const float* ff_in2  = (const float*)d_in[16];
    const float* ff_out  = (const float*)d_in[17];
    const float* sn1     = (const float*)d_in[18];
    const float* sn2     = (const float*)d_in[19];
    float* out = (float*)d_out;

    float* xn   = sym(B_xn);   float* q_   = sym(B_q);    float* k_   = sym(B_k);
    float* qhi  = sym(B_qhi);  float* klo  = sym(B_klo);  float* khi  = sym(B_khi);
    float* v_   = sym(B_v);    float* A_   = sym(B_A);
    float* gate = sym(B_gate); float* accb = sym(B_acc);
    float* memF = sym(B_memF); float* memV = sym(B_memV); float* memQ = sym(B_memQ);
    float* gam  = sym(B_gam);  float* bg   = sym(B_bg);   float* wkT  = sym(B_wkT);
    float* qk2  = sym(B_qk2);  float* lq   = sym(B_lq);   float* mems = sym(B_mems);
    float* memY = sym(B_memY); float* x1   = sym(B_x1);   float* x2n  = sym(B_x2n);
    float* h1   = sym(B_h1);   float* part = sym(B_part); float* partF= sym(B_partF);

    __nv_bfloat16* xn3  = symb(C_xn3);  __nv_bfloat16* q3   = symb(C_q3);
    __nv_bfloat16* y3   = symb(C_y3);   __nv_bfloat16* memQ3= symb(C_memQ3);
    __nv_bfloat16* memY3= symb(C_memY3);__nv_bfloat16* x2n3 = symb(C_x2n3);
    __nv_bfloat16* h23  = symb(C_h23);
    __nv_bfloat16* aq3  = symb(W_aq3);  __nv_bfloat16* ak3  = symb(W_ak3);
    __nv_bfloat16* av3  = symb(W_av3);  __nv_bfloat16* ao3  = symb(W_ao3);
    __nv_bfloat16* ar3  = symb(W_ar3);  __nv_bfloat16* mv3  = symb(W_mv3);
    __nv_bfloat16* mq3  = symb(W_mq3);  __nv_bfloat16* mr3  = symb(W_mr3);
    __nv_bfloat16* wk3  = symb(W_wk3);  __nv_bfloat16* mo3  = symb(W_mo3);
    __nv_bfloat16* f13  = symb(W_f13);  __nv_bfloat16* f23  = symb(W_f23);
    __nv_bfloat16* fo3  = symb(W_fo3);

    cudaFuncSetAttribute(gemm_bf16<EPI_NONE>,           cudaFuncAttributeMaxDynamicSharedMemorySize, GB_SMEM);
    cudaFuncSetAttribute(gemm_bf16<EPI_GATE>,           cudaFuncAttributeMaxDynamicSharedMemorySize, GB_SMEM);
    cudaFuncSetAttribute(gemm_bf16<EPI_GATE_ADD2>,      cudaFuncAttributeMaxDynamicSharedMemorySize, GB_SMEM);
    cudaFuncSetAttribute(gemm_bf16<EPI_SILU_MUL_SPLIT>, cudaFuncAttributeMaxDynamicSharedMemorySize, GB_SMEM);
    cudaFuncSetAttribute(gemm_bf16<EPI_ADD>,            cudaFuncAttributeMaxDynamicSharedMemorySize, GB_SMEM);
    cudaFuncSetAttribute(mem_readout2, cudaFuncAttributeMaxDynamicSharedMemorySize, MN * MD * 4);

    const dim3 blk256(256);
#define GB(EPI_, gx, gy, Aa, Bb, Dd, Gg, Rr1, Rr2, Mm, Nn, Kk)                                  \
    gemm_bf16<EPI_><<<dim3(gx, gy, 1), blk256, GB_SMEM>>>(Aa, Bb, Dd, Gg, Rr1, Rr2, Mm, Nn, Kk, Kk)
#define GBSK4(Aa, Bb, Dd, Kk)                                                                    \
    do {                                                                                         \
        gemm_bf16<EPI_NONE><<<dim3(2, 16, 4), blk256, GB_SMEM>>>(                                \
            Aa, Bb, part, nullptr, nullptr, nullptr, T, QD, Kk, (Kk) / 4);                       \
        redk<<<T * QD / 1024, blk256>>>(part, Dd, T * QD / 4);                                   \
    } while (0)

    // -------- launch order chosen so launch #5 (0-based) is gemm_bf16 (profiled by ncu -s 5) ----
    // 0: transpose (wk for fused cvt)
    transpose256<<<MD, MD>>>(mem_k, wkT);
    // 1: all 13 weight splits in one launch
    cvt_weights_all<<<CVTW_BLOCKS, blk256>>>(
        attn_q, attn_k, attn_v, attn_o, attn_r, mem_v, mem_q, mem_r, wkT, mem_o,
        ff_in1, ff_in2, ff_out,
        aq3, ak3, av3, ao3, ar3, mv3, mq3, mr3, wk3, mo3, f13, f23, fo3);
    // 2: xn = scale_norm(xs) + split
    scale_norm_split<<<T, blk256>>>(xs, xn, xn3, sn1);
    // 3-4: q projection (split-K x4 + reduce)
    gemm_bf16<EPI_NONE><<<dim3(2, 16, 4), blk256, GB_SMEM>>>(
        xn3, aq3, part, nullptr, nullptr, nullptr, T, QD, 3 * XD, 3 * XD / 4);
    redk<<<T * QD / 1024, blk256>>>(part, q_, T * QD / 4);
    // 5: v projection  <-- PROFILED LAUNCH
    GB(EPI_NONE, 16, 16, xn3, av3, v_, nullptr, nullptr, nullptr, T, XD, 3 * XD);
    // 6+: rest of attn projections
    cvtA_t<QD / 4><<<T * QD / 1024, blk256>>>(q_, q3);
    GBSK4(q3, ak3, k_, 3 * QD);
    GB(EPI_NONE, 16, 16, xn3, ar3, gate, nullptr, nullptr, nullptr, T, XD, 3 * XD);
    // attention core
    rope_all<<<T, 128>>>(q_, k_, qhi, klo, khi);
    attn_score<<<T / 8, blk256>>>(qhi, klo, khi, A_);
    attn_av<<<dim3(8, 4, 32), blk256>>>(A_, v_, y3);
    // attn out = (y @ Wo^T) * sigmoid(gate)
    GB(EPI_GATE, 16, 16, y3, ao3, accb, gate, nullptr, nullptr, T, XD, 3 * XD);
    // mem projections + mem gate
    gemm_tn<EPI_SIGMOID><<<dim3(1, 16), blk256>>>(xn, mem_f, memF, nullptr, nullptr, nullptr, T, MN, XD);
    GBSK4(xn3, mv3, memV, 3 * XD);
    GBSK4(xn3, mq3, memQ, 3 * XD);
    GB(EPI_NONE, 16, 16, xn3, mr3, gate, nullptr, nullptr, nullptr, T, XD, 3 * XD);
    // scan
    mem_prep<<<MN, MD>>>(mem_beta, mem_dec, gam, bg);
    mem_scan<<<MN, MD>>>(memF, memV, gam, bg, mems);
    // readout
    cvtA_t<MD / 4><<<T * MD / 1024, blk256>>>(memQ, memQ3);
    GBSK4(memQ3, wk3, qk2, 3 * MD);
    gemm_tn<EPI_NONE><<<dim3(1, 16), blk256>>>(memQ, mem_l, lq, nullptr, nullptr, nullptr, T, MN, MD);
    mem_readout2<<<T, blk256, MN * MD * 4>>>(mems, qk2, lq, memY);
    // x1 = (memY @ mem_o^T)*sigmoid(gate) + attn_out + xs
    cvtA_t<MD / 4><<<T * MD / 1024, blk256>>>(memY, memY3);
    GB(EPI_GATE_ADD2, 16, 16, memY3, mo3, x1, gate, accb, xs, T, XD, 3 * MD);
    // FF block: split-K x2 on f1/f2 to fix wave quantization (352 CTAs vs 296 slots)
    scale_norm_split<<<T, blk256>>>(x1, x2n, x2n3, sn2);
    gemm_bf16<EPI_NONE><<<dim3(22, 16, 2), blk256, GB_SMEM>>>(
        x2n3, f13, partF, nullptr, nullptr, nullptr, T, FFD, 3 * XD, 3 * XD / 2);
    redk2<<<T * FFD / 1024, blk256>>>(partF, h1, T * FFD / 4);
    gemm_bf16<EPI_NONE><<<dim3(22, 16, 2), blk256, GB_SMEM>>>(
        x2n3, f23, partF, nullptr, nullptr, nullptr, T, FFD, 3 * XD, 3 * XD / 2);
    red2_silu_split<<<T * FFD / 1024, blk256>>>(partF, h1, h23);
    GB(EPI_ADD, 16, 16, h23, fo3, out, nullptr, x1, nullptr, T, XD, 3 * FFD);
#undef GB
#undef GBSK4
}

// round 12
// speedup vs baseline: 2.4802x; 1.1386x over previous
#include <cuda_runtime.h>
#include <cuda_bf16.h>
#include <math.h>
#include <stdint.h>

// ---------------- problem dims ----------------
#define T    2048
#define XD   2048
#define QD   256
#define MN   64
#define MD   256
#define DCD  64
#define FFD  2816
#define CH   64

// ---------------- fp32 scratch ----------------
__device__ float B_xn  [(size_t)T*XD];
__device__ float B_q   [(size_t)T*QD];
__device__ float B_k   [(size_t)T*QD];
__device__ float B_qhi [(size_t)T*QD];
__device__ float B_klo [(size_t)T*QD];
__device__ float B_khi [(size_t)T*QD];
__device__ float B_v   [(size_t)T*XD];
__device__ float B_A   [(size_t)T*2*CH];
__device__ float B_gate[(size_t)T*XD];
__device__ float B_acc [(size_t)T*XD];
__device__ float B_memF[(size_t)T*MN];
__device__ float B_memV[(size_t)T*MD];
__device__ float B_memQ[(size_t)T*MD];
__device__ float B_gam [(size_t)MN*MD];
__device__ float B_bg  [(size_t)MN*MD];
__device__ float B_wkT [(size_t)MD*MD];
__device__ float B_qk2 [(size_t)T*MD];
__device__ float B_lq  [(size_t)T*MN];
__device__ float B_mems[(size_t)T*MN*MD];
__device__ float B_memY[(size_t)T*MD];
__device__ float B_x1  [(size_t)T*XD];
__device__ float B_x2n [(size_t)T*XD];
__device__ float B_h1  [(size_t)T*FFD];
__device__ float B_part[(size_t)4*T*MD];    // split-K x4 partials (N=256 GEMMs)
__device__ float B_partF[(size_t)2*T*FFD];  // split-K x2 partials (FF GEMMs)

// ---------------- bf16 2-plane scratch: row = [hi(K) | lo(K)] ----------------
__device__ __nv_bfloat16 C_xn2  [(size_t)T*2*XD];
__device__ __nv_bfloat16 C_q2   [(size_t)T*2*QD];
__device__ __nv_bfloat16 C_y2   [(size_t)T*2*XD];
__device__ __nv_bfloat16 C_memQ2[(size_t)T*2*MD];
__device__ __nv_bfloat16 C_memY2[(size_t)T*2*MD];
__device__ __nv_bfloat16 C_x2n2 [(size_t)T*2*XD];
__device__ __nv_bfloat16 C_h22  [(size_t)T*2*FFD];
__device__ __nv_bfloat16 W_aq2  [(size_t)QD*2*XD];
__device__ __nv_bfloat16 W_ak2  [(size_t)QD*2*QD];
__device__ __nv_bfloat16 W_av2  [(size_t)XD*2*XD];
__device__ __nv_bfloat16 W_ao2  [(size_t)XD*2*XD];
__device__ __nv_bfloat16 W_ar2  [(size_t)XD*2*XD];
__device__ __nv_bfloat16 W_mv2  [(size_t)MD*2*XD];
__device__ __nv_bfloat16 W_mq2  [(size_t)MD*2*XD];
__device__ __nv_bfloat16 W_mr2  [(size_t)XD*2*XD];
__device__ __nv_bfloat16 W_wk2  [(size_t)MD*2*MD];
__device__ __nv_bfloat16 W_mo2  [(size_t)XD*2*MD];
__device__ __nv_bfloat16 W_f12  [(size_t)FFD*2*XD];
__device__ __nv_bfloat16 W_f22  [(size_t)FFD*2*XD];
__device__ __nv_bfloat16 W_fo2  [(size_t)XD*2*FFD];

__device__ __forceinline__ float sigf(float x) { return 1.f / (1.f + expf(-x)); }

enum { EPI_NONE = 0, EPI_SIGMOID, EPI_GATE, EPI_GATE_ADD2, EPI_ADD };

__device__ __forceinline__ void split2(float v0, float v1, uint32_t& hi, uint32_t& lo)
{
    asm("cvt.rn.bf16x2.f32 %0, %1, %2;" : "=r"(hi) : "f"(v1), "f"(v0));
    float h0 = __uint_as_float(hi << 16);
    float h1 = __uint_as_float(hi & 0xffff0000u);
    asm("cvt.rn.bf16x2.f32 %0, %1, %2;" : "=r"(lo) : "f"(v1 - h1), "f"(v0 - h0));
}

// ---------------- split conversion: 4 elems/thread -> 2-plane row [hi|lo] ----------------
template <int KQ>
__device__ __forceinline__ void cvt_one(const float* __restrict__ src,
                                        __nv_bfloat16* __restrict__ dst, int b, int tid)
{
    int idx4 = b * 256 + tid;
    int row = idx4 / KQ;
    int cq  = idx4 - row * KQ;
    const int K = KQ * 4;
    float4 v = ((const float4*)src)[idx4];
    uint32_t h0, l0, h1, l1;
    split2(v.x, v.y, h0, l0);
    split2(v.z, v.w, h1, l1);
    __nv_bfloat16* dr = dst + (size_t)row * 2 * K + cq * 4;
    *(uint2*)dr       = make_uint2(h0, h1);
    *(uint2*)(dr + K) = make_uint2(l0, l1);
}

// one launch converts all 13 weight matrices (shapes compile-time)
__global__ __launch_bounds__(256) void cvt_weights_all(
    const float* aq, const float* ak, const float* av, const float* ao, const float* ar,
    const float* mv, const float* mq, const float* mr, const float* wk, const float* mo,
    const float* f1, const float* f2, const float* fo,
    __nv_bfloat16* aq2, __nv_bfloat16* ak2, __nv_bfloat16* av2, __nv_bfloat16* ao2,
    __nv_bfloat16* ar2, __nv_bfloat16* mv2, __nv_bfloat16* mq2, __nv_bfloat16* mr2,
    __nv_bfloat16* wk2, __nv_bfloat16* mo2, __nv_bfloat16* f12, __nv_bfloat16* f22,
    __nv_bfloat16* fo2)
{
    int b = blockIdx.x, tid = threadIdx.x;
    if (b < 512)  { cvt_one<512>(aq, aq2, b, tid); return; }  b -= 512;   // 256x2048
    if (b < 64)   { cvt_one<64 >(ak, ak2, b, tid); return; }  b -= 64;    // 256x256
    if (b < 4096) { cvt_one<512>(av, av2, b, tid); return; }  b -= 4096;  // 2048x2048
    if (b < 4096) { cvt_one<512>(ao, ao2, b, tid); return; }  b -= 4096;
    if (b < 4096) { cvt_one<512>(ar, ar2, b, tid); return; }  b -= 4096;
    if (b < 512)  { cvt_one<512>(mv, mv2, b, tid); return; }  b -= 512;
    if (b < 512)  { cvt_one<512>(mq, mq2, b, tid); return; }  b -= 512;
    if (b < 4096) { cvt_one<512>(mr, mr2, b, tid); return; }  b -= 4096;
    if (b < 64)   { cvt_one<64 >(wk, wk2, b, tid); return; }  b -= 64;
    if (b < 512)  { cvt_one<64 >(mo, mo2, b, tid); return; }  b -= 512;   // 2048x256
    if (b < 5632) { cvt_one<512>(f1, f12, b, tid); return; }  b -= 5632;  // 2816x2048
    if (b < 5632) { cvt_one<512>(f2, f22, b, tid); return; }  b -= 5632;
    cvt_one<704>(fo, fo2, b, tid);                                        // 2048x2816
}
#define CVTW_BLOCKS 35456

template <int KQ>
__global__ __launch_bounds__(256) void cvtA_t(const float* __restrict__ src,
                                              __nv_bfloat16* __restrict__ dst)
{
    cvt_one<KQ>(src, dst, blockIdx.x, threadIdx.x);
}

// ---------------- split-K reduces ----------------
__global__ __launch_bounds__(256) void redk(const float* __restrict__ p,
                                            float* __restrict__ o, int n4)
{
    int i = blockIdx.x * 256 + threadIdx.x;
    const float4* p4 = (const float4*)p;
    float4 a = p4[i], b = p4[i + n4], c = p4[i + 2 * n4], d = p4[i + 3 * n4];
    ((float4*)o)[i] = make_float4(a.x + b.x + c.x + d.x, a.y + b.y + c.y + d.y,
                                  a.z + b.z + c.z + d.z, a.w + b.w + c.w + d.w);
}

__global__ __launch_bounds__(256) void redk2(const float* __restrict__ p,
                                             float* __restrict__ o, int n4)
{
    int i = blockIdx.x * 256 + threadIdx.x;
    const float4* p4 = (const float4*)p;
    float4 a = p4[i], b = p4[i + n4];
    ((float4*)o)[i] = make_float4(a.x + b.x, a.y + b.y, a.z + b.z, a.w + b.w);
}

// reduce 2 planes + silu gate + 2-plane bf16 split (for FF h2)
__global__ __launch_bounds__(256) void red2_silu_split(
    const float* __restrict__ p, const float* __restrict__ h1,
    __nv_bfloat16* __restrict__ o2)
{
    int idx4 = blockIdx.x * 256 + threadIdx.x;
    const int KQ = FFD / 4;
    int row = idx4 / KQ;
    int cq  = idx4 - row * KQ;
    const float4* p4 = (const float4*)p;
    float4 a = p4[idx4], b = p4[idx4 + (size_t)T * FFD / 4];
    float4 g = ((const float4*)h1)[idx4];
    float c0 = (a.x + b.x) * (g.x * sigf(g.x));
    float c1 = (a.y + b.y) * (g.y * sigf(g.y));
    float c2 = (a.z + b.z) * (g.z * sigf(g.z));
    float c3 = (a.w + b.w) * (g.w * sigf(g.w));
    uint32_t h0, l0, h1b, l1;
    split2(c0, c1, h0, l0);
    split2(c2, c3, h1b, l1);
    __nv_bfloat16* dr = o2 + (size_t)row * 2 * FFD + cq * 4;
    *(uint2*)dr         = make_uint2(h0, h1b);
    *(uint2*)(dr + FFD) = make_uint2(l0, l1);
}

// =====================================================================
//  bf16 mma.sync GEMM over 2-plane [hi|lo] operands.
//  Compensated product = sum over Kpack of segment pairs:
//    A segs: hi,lo,hi   B segs: hi,hi,lo   (Kpack=3*Kplane)
//  Plain bf16: Kpack=Kplane (hi*hi only).
//  tile 128x128, BK=64, 3-stage cp.async, one barrier per K-iter; split-K by z.
// =====================================================================
#define SWZ(off) ((off) ^ (((off) >> 3) & 0x70))
#define TILE_B   16384
#define STAGE_B  (2 * TILE_B)
#define GB_SMEM  (3 * STAGE_B)   // 96 KB

template <int EPI>
__device__ __forceinline__ float epi_apply(float c, size_t idx,
                                           const float* __restrict__ G,
                                           const float* __restrict__ R1,
                                           const float* __restrict__ R2)
{
    if (EPI == EPI_SIGMOID)        c = sigf(c);
    else if (EPI == EPI_GATE)      c = c * sigf(G[idx]);
    else if (EPI == EPI_GATE_ADD2) c = c * sigf(G[idx]) + R1[idx] + R2[idx];
    else if (EPI == EPI_ADD)       c = c + R1[idx];
    return c;
}

__device__ __forceinline__ void mma16(float* c, uint32_t a0, uint32_t a1, uint32_t a2, uint32_t a3,
                                      uint32_t b0, uint32_t b1)
{
    asm volatile(
        "mma.sync.aligned.m16n8k16.row.col.f32.bf16.bf16.f32 "
        "{%0,%1,%2,%3}, {%4,%5,%6,%7}, {%8,%9}, {%0,%1,%2,%3};"
        : "+f"(c[0]), "+f"(c[1]), "+f"(c[2]), "+f"(c[3])
        : "r"(a0), "r"(a1), "r"(a2), "r"(a3), "r"(b0), "r"(b1));
}

__device__ __forceinline__ void ldsm4(uint32_t addr, uint32_t& r0, uint32_t& r1,
                                      uint32_t& r2, uint32_t& r3)
{
    asm volatile("ldmatrix.sync.aligned.m8n8.x4.shared.b16 {%0,%1,%2,%3}, [%4];"
                 : "=r"(r0), "=r"(r1), "=r"(r2), "=r"(r3) : "r"(addr));
}

template <int EPI>
__global__ __launch_bounds__(256, 2) void gemm_bf16(
    const __nv_bfloat16* __restrict__ A, const __nv_bfloat16* __restrict__ B,
    float* __restrict__ D,
    const float* __restrict__ G, const float* __restrict__ R1, const float* __restrict__ R2,
    int M, int N, int Kpack, int Kchunk, int Kplane)
{
    extern __shared__ __nv_bfloat16 smem[];

    const int tid  = threadIdx.x;
    const int wid  = tid >> 5, lane = tid & 31;
    const int wm   = wid & 1, wn = wid >> 1;
    const int g    = lane >> 2, tg = lane & 3;
    const int m0   = blockIdx.y * 128;
    const int n0   = blockIdx.x * 128;
    const int z    = blockIdx.z;

    D += (size_t)z * M * N;

    float acc[4][4][4];
#pragma unroll
    for (int mt = 0; mt < 4; mt++)
#pragma unroll
        for (int nt = 0; nt < 4; nt++)
#pragma unroll
            for (int e = 0; e < 4; e++) acc[mt][nt][e] = 0.f;

    const int KT  = Kchunk >> 6;
    const int KT1 = Kplane >> 6;
    const int zKT = z * KT;
    const int rowStride = 2 * Kplane;

    uint32_t base;
    asm("{ .reg .u64 t; cvta.to.shared.u64 t, %1; cvt.u32.u64 %0, t; }" : "=r"(base) : "l"(smem));

    uint32_t swOff[4];
    const __nv_bfloat16* aG[4];
    const __nv_bfloat16* bG[4];
#pragma unroll
    for (int l = 0; l < 4; l++) {
        int idx = tid + l * 256;
        int r = idx >> 3, c = idx & 7;
        uint32_t off = r * 128 + c * 16;
        swOff[l] = SWZ(off);
        aG[l] = A + (size_t)(m0 + r) * rowStride + c * 8;
        bG[l] = B + (size_t)(n0 + r) * rowStride + c * 8;
    }

    const int lmRow = ((lane >> 3) & 1) * 8 + (lane & 7);
    const int lmCB  = ((lane >> 4) & 1) * 16;

    // per-chunk plane mapping: seg 0:(hi,hi) 1:(lo,hi) 2:(hi,lo)
#define LOADG(buf, kt)                                                                     \
    {                                                                                      \
        int ktg_ = zKT + (kt);                                                             \
        int s_ = (ktg_ >= KT1) + (ktg_ >= 2 * KT1);                                        \
        int rr_ = ktg_ - s_ * KT1;                                                         \
        size_t aO_ = (size_t)(((s_ == 1) ? KT1 : 0) + rr_) * 64;                           \
        size_t bO_ = (size_t)(((s_ == 2) ? KT1 : 0) + rr_) * 64;                           \
        uint32_t aB_ = base + (buf) * STAGE_B;                                             \
        uint32_t bB_ = aB_ + TILE_B;                                                       \
        _Pragma("unroll")                                                                  \
        for (int l = 0; l < 4; l++) {                                                      \
            asm volatile("cp.async.ca.shared.global [%0], [%1], 16;"                       \
                         :: "r"(aB_ + swOff[l]), "l"(aG[l] + aO_));                        \
            asm volatile("cp.async.ca.shared.global [%0], [%1], 16;"                       \
                         :: "r"(bB_ + swOff[l]), "l"(bG[l] + bO_));                        \
        }                                                                                  \
    }

    LOADG(0, 0);
    asm volatile("cp.async.commit_group;");
    if (KT > 1) LOADG(1, 1);
    asm volatile("cp.async.commit_group;");

    int buf = 0;
    for (int kt = 0; kt < KT; kt++) {
        asm volatile("cp.async.wait_group 1;");
        __syncthreads();

        if (kt + 2 < KT) {
            int nb = buf + 2; if (nb >= 3) nb -= 3;
            LOADG(nb, kt + 2);
        }
        asm volatile("cp.async.commit_group;");

        const uint32_t aBuf = base + buf * STAGE_B;
        const uint32_t bBuf = aBuf + TILE_B;

#pragma unroll
        for (int ks = 0; ks < 4; ks++) {
            const int kbB = ks * 32;
            uint32_t bf[4][2];
#pragma unroll
            for (int h = 0; h < 2; h++) {
                uint32_t off = (uint32_t)(wn * 32 + h * 16 + lmRow) * 128 + kbB + lmCB;
                ldsm4(bBuf + SWZ(off), bf[2 * h][0], bf[2 * h + 1][0], bf[2 * h][1], bf[2 * h + 1][1]);
            }
            uint32_t af[4][4];
#pragma unroll
            for (int mt = 0; mt < 4; mt++) {
                uint32_t off = (uint32_t)(wm * 64 + mt * 16 + lmRow) * 128 + kbB + lmCB;
                ldsm4(aBuf + SWZ(off), af[mt][0], af[mt][1], af[mt][2], af[mt][3]);
            }
#pragma unroll
            for (int mt = 0; mt < 4; mt++)
#pragma unroll
                for (int nt = 0; nt < 4; nt++)
                    mma16(acc[mt][nt], af[mt][0], af[mt][1], af[mt][2], af[mt][3],
                          bf[nt][0], bf[nt][1]);
        }
        if (++buf >= 3) buf = 0;
    }
#undef LOADG

#pragma unroll
    for (int mt = 0; mt < 4; mt++) {
        int r0 = m0 + wm * 64 + mt * 16 + g;
#pragma unroll
        for (int nt = 0; nt < 4; nt++) {
            int col = n0 + wn * 32 + nt * 8 + tg * 2;
            size_t i0 = (size_t)r0 * N + col;
            size_t i1 = i0 + (size_t)8 * N;
            float2 o0, o1;
            o0.x = epi_apply<EPI>(acc[mt][nt][0], i0,     G, R1, R2);
            o0.y = epi_apply<EPI>(acc[mt][nt][1], i0 + 1, G, R1, R2);
            o1.x = epi_apply<EPI>(acc[mt][nt][2], i1,     G, R1, R2);
            o1.y = epi_apply<EPI>(acc[mt][nt][3], i1 + 1, G, R1, R2);
            *(float2*)&D[i0] = o0;
            *(float2*)&D[i1] = o1;
        }
    }
}

// ---------------- legacy FFMA GEMM (tiny-N cases: N=64) ----------------
#define BM 128
#define BN 128
#define BKK 16

template <int EPI>
__global__ __launch_bounds__(256) void gemm_tn(
    const float* __restrict__ A, const float* __restrict__ B, float* __restrict__ D,
    const float* __restrict__ G, const float* __restrict__ R1, const float* __restrict__ R2,
    int M, int N, int K)
{
    __shared__ float As[BKK][BM + 4];
    __shared__ float Bs[BKK][BN + 4];

    const int tid = threadIdx.x;
    const int m0 = blockIdx.y * BM;
    const int n0 = blockIdx.x * BN;
    const int tx = tid & 15;
    const int ty = tid >> 4;

    float acc[8][8];
#pragma unroll
    for (int i = 0; i < 8; i++)
#pragma unroll
        for (int j = 0; j < 8; j++) acc[i][j] = 0.f;

    for (int k0 = 0; k0 < K; k0 += BKK) {
#pragma unroll
        for (int l = 0; l < 2; l++) {
            int qi  = tid + l * 256;
            int row = qi >> 2;
            int kk  = (qi & 3) * 4;
            float4 av = *(const float4*)&A[(size_t)(m0 + row) * K + k0 + kk];
            As[kk + 0][row] = av.x; As[kk + 1][row] = av.y;
            As[kk + 2][row] = av.z; As[kk + 3][row] = av.w;
        }
#pragma unroll
        for (int l = 0; l < 2; l++) {
            int qi  = tid + l * 256;
            int row = qi >> 2;
            int kk  = (qi & 3) * 4;
            float4 bv = make_float4(0.f, 0.f, 0.f, 0.f);
            if (n0 + row < N) bv = *(const float4*)&B[(size_t)(n0 + row) * K + k0 + kk];
            Bs[kk + 0][row] = bv.x; Bs[kk + 1][row] = bv.y;
            Bs[kk + 2][row] = bv.z; Bs[kk + 3][row] = bv.w;
        }
        __syncthreads();

#pragma unroll
        for (int kk = 0; kk < BKK; kk++) {
            float a[8], b[8];
#pragma unroll
            for (int i = 0; i < 8; i++) a[i] = As[kk][ty * 8 + i];
#pragma unroll
            for (int j = 0; j < 8; j++) b[j] = Bs[kk][tx * 8 + j];
#pragma unroll
            for (int i = 0; i < 8; i++)
#pragma unroll
                for (int j = 0; j < 8; j++) acc[i][j] += a[i] * b[j];
        }
        __syncthreads();
    }

#pragma unroll
    for (int i = 0; i < 8; i++) {
        int row = m0 + ty * 8 + i;
#pragma unroll
        for (int j = 0; j < 8; j++) {
            int col = n0 + tx * 8 + j;
            if (col < N) {
                size_t idx = (size_t)row * N + col;
                D[idx] = epi_apply<EPI>(acc[i][j], idx, G, R1, R2);
            }
        }
    }
}

// ---------------- scale_norm with fused 2-plane split ----------------
__global__ __launch_bounds__(256) void scale_norm_split(
    const float* __restrict__ x, float* __restrict__ o,
    __nv_bfloat16* __restrict__ o2, const float* __restrict__ g)
{
    int t = blockIdx.x;
    const float4* xr = (const float4*)(x + (size_t)t * XD);
    float4 v0 = xr[threadIdx.x];
    float4 v1 = xr[threadIdx.x + 256];
    float s = v0.x*v0.x + v0.y*v0.y + v0.z*v0.z + v0.w*v0.w
            + v1.x*v1.x + v1.y*v1.y + v1.z*v1.z + v1.w*v1.w;
    for (int off = 16; off; off >>= 1) s += __shfl_xor_sync(0xffffffffu, s, off);
    __shared__ float red[8];
    int w = threadIdx.x >> 5, lane = threadIdx.x & 31;
    if (lane == 0) red[w] = s;
    __syncthreads();
    float tot = red[0] + red[1] + red[2] + red[3] + red[4] + red[5] + red[6] + red[7];
    float sc = g[0] / (sqrtf(tot) + 1e-8f);
    v0.x *= sc; v0.y *= sc; v0.z *= sc; v0.w *= sc;
    v1.x *= sc; v1.y *= sc; v1.z *= sc; v1.w *= sc;
    float4* orow = (float4*)(o + (size_t)t * XD);
    orow[threadIdx.x] = v0;
    orow[threadIdx.x + 256] = v1;
    __nv_bfloat16* r2 = o2 + (size_t)t * 2 * XD;
    uint32_t h, l;
    int c0 = threadIdx.x * 4;
    split2(v0.x, v0.y, h, l);
    *(uint32_t*)(r2 + c0) = h; *(uint32_t*)(r2 + XD + c0) = l;
    split2(v0.z, v0.w, h, l);
    *(uint32_t*)(r2 + c0 + 2) = h; *(uint32_t*)(r2 + XD + c0 + 2) = l;
    int c1 = c0 + 1024;
    split2(v1.x, v1.y, h, l);
    *(uint32_t*)(r2 + c1) = h; *(uint32_t*)(r2 + XD + c1) = l;
    split2(v1.z, v1.w, h, l);
    *(uint32_t*)(r2 + c1 + 2) = h; *(uint32_t*)(r2 + XD + c1 + 2) = l;
}

// ---------------- RoPE ----------------
__global__ __launch_bounds__(128) void rope_all(
    const float* __restrict__ q, const float* __restrict__ k,
    float* __restrict__ qhi, float* __restrict__ klo, float* __restrict__ khi)
{
    int t = blockIdx.x, j = threadIdx.x;
    int r = t & 63;
    float freq = powf(10000.f, -(float)j / 128.f);
    float slo, clo, shi, chi;
    sincosf((float)r * freq, &slo, &clo);
    sincosf((float)(64 + r) * freq, &shi, &chi);
    size_t base = (size_t)t * QD + 2 * j;
    float qe = q[base], qo = q[base + 1];
    qhi[base]     = qe * chi - qo * shi;
    qhi[base + 1] = qo * chi + qe * shi;
    float ke = k[base], ko = k[base + 1];
    klo[base]     = ke * clo - ko * slo;
    klo[base + 1] = ko * clo + ke * slo;
    khi[base]     = ke * chi - ko * shi;
    khi[base + 1] = ko * chi + ke * shi;
}

// ---------------- attention scores + softmax ----------------
__global__ __launch_bounds__(256) void attn_score(
    const float* __restrict__ qr, const float* __restrict__ klo,
    const float* __restrict__ khi, float* __restrict__ Aout)
{
    int w = threadIdx.x >> 5, lane = threadIdx.x & 31;
    int t = blockIdx.x * 8 + w;
    int c = t >> 6, r = t & 63;
    float qreg[8];
#pragma unroll
    for (int i = 0; i < 8; i++) qreg[i] = qr[(size_t)t * QD + i * 32 + lane];

    __shared__ float s_s[8][128];
    for (int m = 0; m < 128; m++) {
        float sc;
        if (c == 0 && m < 64) {
            sc = 0.f;
        } else {
            const float* kp = (m < 64)
                ? &klo[(size_t)((c - 1) * 64 + m) * QD]
                : &khi[(size_t)(c * 64 + (m - 64)) * QD];
            float d = 0.f;
#pragma unroll
            for (int i = 0; i < 8; i++) d += qreg[i] * kp[i * 32 + lane];
            for (int off = 16; off; off >>= 1) d += __shfl_xor_sync(0xffffffffu, d, off);
            sc = d * (1.f / 16.f);
        }
        if (m > r + 64) sc = -1e30f;
        if (lane == 0) s_s[w][m] = sc;
    }
    __syncwarp();
    float a0 = s_s[w][lane], a1 = s_s[w][lane + 32], a2 = s_s[w][lane + 64], a3 = s_s[w][lane + 96];
    float mx = fmaxf(fmaxf(a0, a1), fmaxf(a2, a3));
    for (int off = 16; off; off >>= 1) mx = fmaxf(mx, __shfl_xor_sync(0xffffffffu, mx, off));
    float e0 = expf(a0 - mx), e1 = expf(a1 - mx), e2 = expf(a2 - mx), e3 = expf(a3 - mx);
    float sm = e0 + e1 + e2 + e3;
    for (int off = 16; off; off >>= 1) sm += __shfl_xor_sync(0xffffffffu, sm, off);
    float inv = 1.f / sm;
    size_t ob = (size_t)t * 128;
    Aout[ob + lane]      = e0 * inv;
    Aout[ob + lane + 32] = e1 * inv;
    Aout[ob + lane + 64] = e2 * inv;
    Aout[ob + lane + 96] = e3 * inv;
}

// ---------------- y = A @ v2, fused 2-plane split into y2 ----------------
__global__ __launch_bounds__(256) void attn_av(
    const float* __restrict__ Aat, const float* __restrict__ v,
    __nv_bfloat16* __restrict__ y2)
{
    int c = blockIdx.z, rg = blockIdx.y, ct = blockIdx.x;
    int col = ct * 256 + threadIdx.x;
    __shared__ float As[16][128];
    for (int idx = threadIdx.x; idx < 16 * 128; idx += 256) {
        int rr = idx >> 7, mm = idx & 127;
        As[rr][mm] = Aat[(size_t)(c * 64 + rg * 16 + rr) * 128 + mm];
    }
    __syncthreads();
    float acc[16];
#pragma unroll
    for (int r = 0; r < 16; r++) acc[r] = 0.f;
    int mstart = (c == 0) ? 64 : 0;
    for (int m = mstart; m < 128; m++) {
        float vv = v[(size_t)((c - 1) * 64 + m) * XD + col];
#pragma unroll
        for (int r = 0; r < 16; r++) acc[r] += As[r][m] * vv;
    }
#pragma unroll
    for (int r = 0; r < 16; r++) {
        float val = acc[r];
        __nv_bfloat16 hb = __float2bfloat16(val);
        __nv_bfloat16 lb = __float2bfloat16(val - __bfloat162float(hb));
        __nv_bfloat16* yr = y2 + (size_t)(c * 64 + rg * 16 + r) * 2 * XD;
        yr[col] = hb; yr[XD + col] = lb;
    }
}

// ---------------- mem prep ----------------
__global__ void mem_prep(const float* __restrict__ beta, const float* __restrict__ decay,
                         float* __restrict__ gam, float* __restrict__ bg)
{
    int n = blockIdx.x, d = threadIdx.x;
    float g = (d < MD - DCD) ? 1.f : sigf(decay[n * DCD + (d - (MD - DCD))]);
    gam[n * MD + d] = g;
    bg[n * MD + d] = g * sigf(beta[n * MD + d]);
}

// ---------------- mem scan ----------------
__global__ __launch_bounds__(256) void mem_scan(
    const float* __restrict__ F, const float* __restrict__ V,
    const float* __restrict__ gam, const float* __restrict__ bg, float* __restrict__ mems)
{
    int n = blockIdx.x, d = threadIdx.x;
    float ga = gam[n * MD + d], b = bg[n * MD + d];
    float m = 0.f;
    float fn = F[n], vn = V[d];
    for (int t = 0; t < T; t++) {
        float f = fn, vv = vn;
        if (t + 1 < T) { fn = F[(t + 1) * MN + n]; vn = V[(size_t)(t + 1) * MD + d]; }
        m = (ga - f * b) * m + f * vv;
        mems[((size_t)t * MN + n) * MD + d] = m;
    }
}

// ---------------- transpose 256x256 ----------------
__global__ void transpose256(const float* __restrict__ W, float* __restrict__ WT)
{
    int rk = blockIdx.x, cd = threadIdx.x;
    WT[cd * MD + rk] = W[rk * MD + cd];
}

// ---------------- mem readout (smem-staged) ----------------
__global__ __launch_bounds__(256) void mem_readout2(
    const float* __restrict__ mems, const float* __restrict__ qk2,
    const float* __restrict__ lq, float* __restrict__ yout)
{
    extern __shared__ float ms[];
    __shared__ float qs[MD];
    __shared__ float as[MN];
    int t = blockIdx.x;
    int tid = threadIdx.x, w = tid >> 5, lane = tid & 31;
    qs[tid] = qk2[(size_t)t * MD + tid];
    const float4* mb4 = (const float4*)(mems + (size_t)t * MN * MD);
    float4* ms4 = (float4*)ms;
#pragma unroll
    for (int i = 0; i < 16; i++) ms4[tid + i * 256] = mb4[tid + i * 256];
    __syncthreads();
#pragma unroll
    for (int mi = 0; mi < 8; mi++) {
        int m = w * 8 + mi;
        float d = 0.f;
#pragma unroll
        for (int i = 0; i < 8; i++) d += ms[m * MD + i * 32 + lane] * qs[i * 32 + lane];
        for (int off = 16; off; off >>= 1) d += __shfl_xor_sync(0xffffffffu, d, off);
        if (lane == 0) as[m] = (d + lq[t * MN + m]) * (1.f / 16.f);
    }
    __syncthreads();
    if (w == 0) {
        float a0 = as[lane], a1 = as[lane + 32];
        float mx = fmaxf(a0, a1);
        for (int off = 16; off; off >>= 1) mx = fmaxf(mx, __shfl_xor_sync(0xffffffffu, mx, off));
        float e0 = expf(a0 - mx), e1 = expf(a1 - mx);
        float sm = e0 + e1;
        for (int off = 16; off; off >>= 1) sm += __shfl_xor_sync(0xffffffffu, sm, off);
        float inv = 1.f / sm;
        as[lane] = e0 * inv;
        as[lane + 32] = e1 * inv;
    }
    __syncthreads();
    float acc = 0.f;
    for (int m = 0; m < MN; m++) acc += as[m] * ms[m * MD + tid];
    yout[(size_t)t * MD + tid] = acc;
}

// ---------------- launcher ----------------
static float* sym(const void* s) { void* p = nullptr; cudaGetSymbolAddress(&p, s); return (float*)p; }
static __nv_bfloat16* symb(const void* s) { void* p = nullptr; cudaGetSymbolAddress(&p, s); return (__nv_bfloat16*)p; }

extern "C" void kernel_launch(void* const* d_in, const int* in_sizes, int n_in,
                              void* d_out, int out_size)
{
    const float* xs      = (const float*)d_in[0];
    const float* attn_q  = (const float*)d_in[1];
    const float* attn_k  = (const float*)d_in[2];
    const float* attn_v  = (const float*)d_in[3];
    const float* attn_o  = (const float*)d_in[4];
    const float* attn_r  = (const float*)d_in[5];
    const float* mem_f   = (const float*)d_in[6];
    const float* mem_q   = (const float*)d_in[7];
    const float* mem_k   = (const float*)d_in[8];
    const float* mem_v   = (const float*)d_in[9];
    const float* mem_o   = (const float*)d_in[10];
    const float* mem_r   = (const float*)d_in[11];
    const float* mem_beta= (const float*)d_in[12];
    const float* mem_dec = (const float*)d_in[13];
    const float* mem_l   = (const float*)d_in[14];
    const float* ff_in1  = (const float*)d_in[15];
    const float* ff_in2  = (const float*)d_in[16];
    const float* ff_out  = (const float*)d_in[17];
    const float* sn1     = (const float*)d_in[18];
    const float* sn2     = (const float*)d_in[19];
    float* out = (float*)d_out;

    float* xn   = sym(B_xn);   float* q_   = sym(B_q);    float* k_   = sym(B_k);
    float* qhi  = sym(B_qhi);  float* klo  = sym(B_klo);  float* khi  = sym(B_khi);
    float* v_   = sym(B_v);    float* A_   = sym(B_A);
    float* gate = sym(B_gate); float* accb = sym(B_acc);
    float* memF = sym(B_memF); float* memV = sym(B_memV); float* memQ = sym(B_memQ);
    float* gam  = sym(B_gam);  float* bg   = sym(B_bg);   float* wkT  = sym(B_wkT);
    float* qk2  = sym(B_qk2);  float* lq   = sym(B_lq);   float* mems = sym(B_mems);
    float* memY = sym(B_memY); float* x1   = sym(B_x1);   float* x2n  = sym(B_x2n);
    float* h1   = sym(B_h1);   float* part = sym(B_part); float* partF= sym(B_partF);

    __nv_bfloat16* xn2  = symb(C_xn2);  __nv_bfloat16* q2   = symb(C_q2);
    __nv_bfloat16* y2   = symb(C_y2);   __nv_bfloat16* memQ2= symb(C_memQ2);
    __nv_bfloat16* memY2= symb(C_memY2);__nv_bfloat16* x2n2 = symb(C_x2n2);
    __nv_bfloat16* h22  = symb(C_h22);
    __nv_bfloat16* aq2  = symb(W_aq2);  __nv_bfloat16* ak2  = symb(W_ak2);
    __nv_bfloat16* av2  = symb(W_av2);  __nv_bfloat16* ao2  = symb(W_ao2);
    __nv_bfloat16* ar2  = symb(W_ar2);  __nv_bfloat16* mv2  = symb(W_mv2);
    __nv_bfloat16* mq2  = symb(W_mq2);  __nv_bfloat16* mr2  = symb(W_mr2);
    __nv_bfloat16* wk2  = symb(W_wk2);  __nv_bfloat16* mo2  = symb(W_mo2);
    __nv_bfloat16* f12  = symb(W_f12);  __nv_bfloat16* f22  = symb(W_f22);
    __nv_bfloat16* fo2  = symb(W_fo2);

    cudaFuncSetAttribute(gemm_bf16<EPI_NONE>,      cudaFuncAttributeMaxDynamicSharedMemorySize, GB_SMEM);
    cudaFuncSetAttribute(gemm_bf16<EPI_GATE>,      cudaFuncAttributeMaxDynamicSharedMemorySize, GB_SMEM);
    cudaFuncSetAttribute(gemm_bf16<EPI_GATE_ADD2>, cudaFuncAttributeMaxDynamicSharedMemorySize, GB_SMEM);
    cudaFuncSetAttribute(gemm_bf16<EPI_ADD>,       cudaFuncAttributeMaxDynamicSharedMemorySize, GB_SMEM);
    cudaFuncSetAttribute(mem_readout2, cudaFuncAttributeMaxDynamicSharedMemorySize, MN * MD * 4);

    const dim3 blk256(256);
#define GB(EPI_, gx, gy, Aa, Bb, Dd, Gg, Rr1, Rr2, Mm, Nn, Kpk, Kpl)                            \
    gemm_bf16<EPI_><<<dim3(gx, gy, 1), blk256, GB_SMEM>>>(Aa, Bb, Dd, Gg, Rr1, Rr2, Mm, Nn, Kpk, Kpk, Kpl)
#define GBSK4(Aa, Bb, Dd, Kpk, Kpl)                                                              \
    do {                                                                                         \
        gemm_bf16<EPI_NONE><<<dim3(2, 16, 4), blk256, GB_SMEM>>>(                                \
            Aa, Bb, part, nullptr, nullptr, nullptr, T, QD, Kpk, (Kpk) / 4, Kpl);                \
        redk<<<T * QD / 1024, blk256>>>(part, Dd, T * QD / 4);                                   \
    } while (0)

    // -------- launch order: #5 (0-based) = grid-256 gemm_bf16 for ncu -s 5 ----
    transpose256<<<MD, MD>>>(mem_k, wkT);                                   // 0
    cvt_weights_all<<<CVTW_BLOCKS, blk256>>>(                               // 1
        attn_q, attn_k, attn_v, attn_o, attn_r, mem_v, mem_q, mem_r, wkT, mem_o,
        ff_in1, ff_in2, ff_out,
        aq2, ak2, av2, ao2, ar2, mv2, mq2, mr2, wk2, mo2, f12, f22, fo2);
    scale_norm_split<<<T, blk256>>>(xs, xn, xn2, sn1);                      // 2
    gemm_bf16<EPI_NONE><<<dim3(2, 16, 4), blk256, GB_SMEM>>>(               // 3: q proj split-K
        xn2, aq2, part, nullptr, nullptr, nullptr, T, QD, 3 * XD, 3 * XD / 4, XD);
    redk<<<T * QD / 1024, blk256>>>(part, q_, T * QD / 4);                  // 4
    GB(EPI_NONE, 16, 16, xn2, av2, v_, nullptr, nullptr, nullptr, T, XD, 3 * XD, XD);  // 5 PROFILED
    cvtA_t<QD / 4><<<T * QD / 1024, blk256>>>(q_, q2);
    GBSK4(q2, ak2, k_, 3 * QD, QD);
    // gates: 1-term bf16 (hi*hi only) — sigmoid-damped precision budget
    GB(EPI_NONE, 16, 16, xn2, ar2, gate, nullptr, nullptr, nullptr, T, XD, XD, XD);
    // attention core
    rope_all<<<T, 128>>>(q_, k_, qhi, klo, khi);
    attn_score<<<T / 8, blk256>>>(qhi, klo, khi, A_);
    attn_av<<<dim3(8, 4, 32), blk256>>>(A_, v_, y2);
    GB(EPI_GATE, 16, 16, y2, ao2, accb, gate, nullptr, nullptr, T, XD, 3 * XD, XD);
    // mem projections + gate
    gemm_tn<EPI_SIGMOID><<<dim3(1, 16), blk256>>>(xn, mem_f, memF, nullptr, nullptr, nullptr, T, MN, XD);
    GBSK4(xn2, mv2, memV, 3 * XD, XD);
    GBSK4(xn2, mq2, memQ, 3 * XD, XD);
    GB(EPI_NONE, 16, 16, xn2, mr2, gate, nullptr, nullptr, nullptr, T, XD, XD, XD);   // 1-term
    // scan
    mem_prep<<<MN, MD>>>(mem_beta, mem_dec, gam, bg);
    mem_scan<<<MN, MD>>>(memF, memV, gam, bg, mems);
    // readout
    cvtA_t<MD / 4><<<T * MD / 1024, blk256>>>(memQ, memQ2);
    GBSK4(memQ2, wk2, qk2, 3 * MD, MD);
    gemm_tn<EPI_NONE><<<dim3(1, 16), blk256>>>(memQ, mem_l, lq, nullptr, nullptr, nullptr, T, MN, MD);
    mem_readout2<<<T, blk256, MN * MD * 4>>>(mems, qk2, lq, memY);
    // x1 = (memY @ mem_o^T)*sigmoid(gate) + attn_out + xs
    cvtA_t<MD / 4><<<T * MD / 1024, blk256>>>(memY, memY2);
    GB(EPI_GATE_ADD2, 16, 16, memY2, mo2, x1, gate, accb, xs, T, XD, 3 * MD, MD);
    // FF block
    scale_norm_split<<<T, blk256>>>(x1, x2n, x2n2, sn2);
    gemm_bf16<EPI_NONE><<<dim3(22, 16, 2), blk256, GB_SMEM>>>(
        x2n2, f12, partF, nullptr, nullptr, nullptr, T, FFD, 3 * XD, 3 * XD / 2, XD);
    redk2<<<T * FFD / 1024, blk256>>>(partF, h1, T * FFD / 4);
    gemm_bf16<EPI_NONE><<<dim3(22, 16, 2), blk256, GB_SMEM>>>(
        x2n2, f22, partF, nullptr, nullptr, nullptr, T, FFD, 3 * XD, 3 * XD / 2, XD);
    red2_silu_split<<<T * FFD / 1024, blk256>>>(partF, h1, h22);
    GB(EPI_ADD, 16, 16, h22, fo2, out, nullptr, x1, nullptr, T, XD, 3 * FFD, FFD);
#undef GB
#undef GBSK4
}

// round 14
// speedup vs baseline: 2.9437x; 1.1868x over previous
#include <cuda_runtime.h>
#include <cuda_fp16.h>
#include <math.h>
#include <stdint.h>

// ---------------- problem dims ----------------
#define T    2048
#define XD   2048
#define QD   256
#define MN   64
#define MD   256
#define DCD  64
#define FFD  2816
#define CH   64

// ---------------- fp32 scratch ----------------
__device__ float B_xn  [(size_t)T*XD];
__device__ float B_q   [(size_t)T*QD];
__device__ float B_k   [(size_t)T*QD];
__device__ float B_qhi [(size_t)T*QD];
__device__ float B_klo [(size_t)T*QD];
__device__ float B_khi [(size_t)T*QD];
__device__ float B_v   [(size_t)T*XD];
__device__ float B_A   [(size_t)T*2*CH];
__device__ float B_gate[(size_t)T*XD];
__device__ float B_acc [(size_t)T*XD];
__device__ float B_memF[(size_t)T*MN];
__device__ float B_memV[(size_t)T*MD];
__device__ float B_memQ[(size_t)T*MD];
__device__ float B_gam [(size_t)MN*MD];
__device__ float B_bg  [(size_t)MN*MD];
__device__ float B_wkT [(size_t)MD*MD];
__device__ float B_qk2 [(size_t)T*MD];
__device__ float B_lq  [(size_t)T*MN];
__device__ float B_mems[(size_t)T*MN*MD];
__device__ float B_memY[(size_t)T*MD];
__device__ float B_x1  [(size_t)T*XD];
__device__ float B_x2n [(size_t)T*XD];
__device__ float B_h1  [(size_t)T*FFD];
__device__ float B_part[(size_t)4*T*MD];    // split-K x4 partials (N=256 GEMMs)
__device__ float B_partF[(size_t)2*T*FFD];  // split-K x2 partials (FF GEMMs)

// ---------------- fp16 2-plane scratch: row = [hi(K) | lo(K)] ----------------
__device__ __half C_xn2  [(size_t)T*2*XD];
__device__ __half C_q2   [(size_t)T*2*QD];
__device__ __half C_y2   [(size_t)T*2*XD];
__device__ __half C_memQ2[(size_t)T*2*MD];
__device__ __half C_memY2[(size_t)T*2*MD];
__device__ __half C_x2n2 [(size_t)T*2*XD];
__device__ __half C_h22  [(size_t)T*2*FFD];
__device__ __half W_aq2  [(size_t)QD*2*XD];
__device__ __half W_ak2  [(size_t)QD*2*QD];
__device__ __half W_av2  [(size_t)XD*2*XD];
__device__ __half W_ao2  [(size_t)XD*2*XD];
__device__ __half W_ar2  [(size_t)XD*2*XD];
__device__ __half W_mv2  [(size_t)MD*2*XD];
__device__ __half W_mq2  [(size_t)MD*2*XD];
__device__ __half W_mr2  [(size_t)XD*2*XD];
__device__ __half W_wk2  [(size_t)MD*2*MD];
__device__ __half W_mo2  [(size_t)XD*2*MD];
__device__ __half W_f12  [(size_t)FFD*2*XD];
__device__ __half W_f22  [(size_t)FFD*2*XD];
__device__ __half W_fo2  [(size_t)XD*2*FFD];

__device__ __forceinline__ float sigf(float x) { return 1.f / (1.f + expf(-x)); }

enum { EPI_NONE = 0, EPI_SIGMOID, EPI_GATE, EPI_GATE_ADD2, EPI_ADD };

// fp16 hi/lo split: hi = f16x2(v0,v1) (v0 low), lo = f16x2 of residuals
__device__ __forceinline__ void split2h(float v0, float v1, uint32_t& hi, uint32_t& lo)
{
    asm("cvt.rn.f16x2.f32 %0, %1, %2;" : "=r"(hi) : "f"(v1), "f"(v0));
    __half2 hh = *(__half2*)&hi;
    float h0 = __half2float(__low2half(hh));
    float h1 = __half2float(__high2half(hh));
    asm("cvt.rn.f16x2.f32 %0, %1, %2;" : "=r"(lo) : "f"(v1 - h1), "f"(v0 - h0));
}

// ---------------- split conversion: 4 elems/thread -> 2-plane row [hi|lo] ----------------
template <int KQ>
__device__ __forceinline__ void cvt_one(const float* __restrict__ src,
                                        __half* __restrict__ dst, int b, int tid)
{
    int idx4 = b * 256 + tid;
    int row = idx4 / KQ;
    int cq  = idx4 - row * KQ;
    const int K = KQ * 4;
    float4 v = ((const float4*)src)[idx4];
    uint32_t h0, l0, h1, l1;
    split2h(v.x, v.y, h0, l0);
    split2h(v.z, v.w, h1, l1);
    __half* dr = dst + (size_t)row * 2 * K + cq * 4;
    *(uint2*)dr       = make_uint2(h0, h1);
    *(uint2*)(dr + K) = make_uint2(l0, l1);
}

// one launch converts all 13 weight matrices (shapes compile-time)
__global__ __launch_bounds__(256) void cvt_weights_all(
    const float* aq, const float* ak, const float* av, const float* ao, const float* ar,
    const float* mv, const float* mq, const float* mr, const float* wk, const float* mo,
    const float* f1, const float* f2, const float* fo,
    __half* aq2, __half* ak2, __half* av2, __half* ao2,
    __half* ar2, __half* mv2, __half* mq2, __half* mr2,
    __half* wk2, __half* mo2, __half* f12, __half* f22,
    __half* fo2)
{
    int b = blockIdx.x, tid = threadIdx.x;
    if (b < 512)  { cvt_one<512>(aq, aq2, b, tid); return; }  b -= 512;   // 256x2048
    if (b < 64)   { cvt_one<64 >(ak, ak2, b, tid); return; }  b -= 64;    // 256x256
    if (b < 4096) { cvt_one<512>(av, av2, b, tid); return; }  b -= 4096;  // 2048x2048
    if (b < 4096) { cvt_one<512>(ao, ao2, b, tid); return; }  b -= 4096;
    if (b < 4096) { cvt_one<512>(ar, ar2, b, tid); return; }  b -= 4096;
    if (b < 512)  { cvt_one<512>(mv, mv2, b, tid); return; }  b -= 512;
    if (b < 512)  { cvt_one<512>(mq, mq2, b, tid); return; }  b -= 512;
    if (b < 4096) { cvt_one<512>(mr, mr2, b, tid); return; }  b -= 4096;
    if (b < 64)   { cvt_one<64 >(wk, wk2, b, tid); return; }  b -= 64;
    if (b < 512)  { cvt_one<64 >(mo, mo2, b, tid); return; }  b -= 512;   // 2048x256
    if (b < 5632) { cvt_one<512>(f1, f12, b, tid); return; }  b -= 5632;  // 2816x2048
    if (b < 5632) { cvt_one<512>(f2, f22, b, tid); return; }  b -= 5632;
    cvt_one<704>(fo, fo2, b, tid);                                        // 2048x2816
}
#define CVTW_BLOCKS 35456

template <int KQ>
__global__ __launch_bounds__(256) void cvtA_t(const float* __restrict__ src,
                                              __half* __restrict__ dst)
{
    cvt_one<KQ>(src, dst, blockIdx.x, threadIdx.x);
}

// ---------------- split-K reduces ----------------
__global__ __launch_bounds__(256) void redk(const float* __restrict__ p,
                                            float* __restrict__ o, int n4)
{
    int i = blockIdx.x * 256 + threadIdx.x;
    const float4* p4 = (const float4*)p;
    float4 a = p4[i], b = p4[i + n4], c = p4[i + 2 * n4], d = p4[i + 3 * n4];
    ((float4*)o)[i] = make_float4(a.x + b.x + c.x + d.x, a.y + b.y + c.y + d.y,
                                  a.z + b.z + c.z + d.z, a.w + b.w + c.w + d.w);
}

__global__ __launch_bounds__(256) void redk2(const float* __restrict__ p,
                                             float* __restrict__ o, int n4)
{
    int i = blockIdx.x * 256 + threadIdx.x;
    const float4* p4 = (const float4*)p;
    float4 a = p4[i], b = p4[i + n4];
    ((float4*)o)[i] = make_float4(a.x + b.x, a.y + b.y, a.z + b.z, a.w + b.w);
}

// reduce 2 planes + silu gate + 2-plane fp16 split (for FF h2)
__global__ __launch_bounds__(256) void red2_silu_split(
    const float* __restrict__ p, const float* __restrict__ h1,
    __half* __restrict__ o2)
{
    int idx4 = blockIdx.x * 256 + threadIdx.x;
    const int KQ = FFD / 4;
    int row = idx4 / KQ;
    int cq  = idx4 - row * KQ;
    const float4* p4 = (const float4*)p;
    float4 a = p4[idx4], b = p4[idx4 + (size_t)T * FFD / 4];
    float4 g = ((const float4*)h1)[idx4];
    float c0 = (a.x + b.x) * (g.x * sigf(g.x));
    float c1 = (a.y + b.y) * (g.y * sigf(g.y));
    float c2 = (a.z + b.z) * (g.z * sigf(g.z));
    float c3 = (a.w + b.w) * (g.w * sigf(g.w));
    uint32_t h0, l0, h1b, l1;
    split2h(c0, c1, h0, l0);
    split2h(c2, c3, h1b, l1);
    __half* dr = o2 + (size_t)row * 2 * FFD + cq * 4;
    *(uint2*)dr         = make_uint2(h0, h1b);
    *(uint2*)(dr + FFD) = make_uint2(l0, l1);
}

// =====================================================================
//  fp16 mma.sync GEMM over 2-plane [hi|lo] operands.
//  Segment pairs per K-chunk: 0:(hi,hi) 1:(lo,hi) 2:(hi,lo)
//  Kpack = Kplane (1-term) / 2*Kplane (2-term) / 3*Kplane (full compensation)
//  tile 128x128, BK=64, 3-stage cp.async, one barrier per K-iter; split-K by z.
// =====================================================================
#define SWZ(off) ((off) ^ (((off) >> 3) & 0x70))
#define TILE_B   16384
#define STAGE_B  (2 * TILE_B)
#define GB_SMEM  (3 * STAGE_B)   // 96 KB

template <int EPI>
__device__ __forceinline__ float epi_apply(float c, size_t idx,
                                           const float* __restrict__ G,
                                           const float* __restrict__ R1,
                                           const float* __restrict__ R2)
{
    if (EPI == EPI_SIGMOID)        c = sigf(c);
    else if (EPI == EPI_GATE)      c = c * sigf(G[idx]);
    else if (EPI == EPI_GATE_ADD2) c = c * sigf(G[idx]) + R1[idx] + R2[idx];
    else if (EPI == EPI_ADD)       c = c + R1[idx];
    return c;
}

__device__ __forceinline__ void mma16(float* c, uint32_t a0, uint32_t a1, uint32_t a2, uint32_t a3,
                                      uint32_t b0, uint32_t b1)
{
    asm volatile(
        "mma.sync.aligned.m16n8k16.row.col.f32.f16.f16.f32 "
        "{%0,%1,%2,%3}, {%4,%5,%6,%7}, {%8,%9}, {%0,%1,%2,%3};"
        : "+f"(c[0]), "+f"(c[1]), "+f"(c[2]), "+f"(c[3])
        : "r"(a0), "r"(a1), "r"(a2), "r"(a3), "r"(b0), "r"(b1));
}

__device__ __forceinline__ void ldsm4(uint32_t addr, uint32_t& r0, uint32_t& r1,
                                      uint32_t& r2, uint32_t& r3)
{
    asm volatile("ldmatrix.sync.aligned.m8n8.x4.shared.b16 {%0,%1,%2,%3}, [%4];"
                 : "=r"(r0), "=r"(r1), "=r"(r2), "=r"(r3) : "r"(addr));
}

template <int EPI>
__global__ __launch_bounds__(256, 2) void gemm_h16(
    const __half* __restrict__ A, const __half* __restrict__ B,
    float* __restrict__ D,
    const float* __restrict__ G, const float* __restrict__ R1, const float* __restrict__ R2,
    int M, int N, int Kpack, int Kchunk, int Kplane)
{
    extern __shared__ __half smem[];

    const int tid  = threadIdx.x;
    const int wid  = tid >> 5, lane = tid & 31;
    const int wm   = wid & 1, wn = wid >> 1;
    const int g    = lane >> 2, tg = lane & 3;
    const int m0   = blockIdx.y * 128;
    const int n0   = blockIdx.x * 128;
    const int z    = blockIdx.z;

    D += (size_t)z * M * N;

    float acc[4][4][4];
#pragma unroll
    for (int mt = 0; mt < 4; mt++)
#pragma unroll
        for (int nt = 0; nt < 4; nt++)
#pragma unroll
            for (int e = 0; e < 4; e++) acc[mt][nt][e] = 0.f;

    const int KT  = Kchunk >> 6;
    const int KT1 = Kplane >> 6;
    const int zKT = z * KT;
    const int rowStride = 2 * Kplane;

    uint32_t base;
    asm("{ .reg .u64 t; cvta.to.shared.u64 t, %1; cvt.u32.u64 %0, t; }" : "=r"(base) : "l"(smem));

    uint32_t swOff[4];
    const __half* aG[4];
    const __half* bG[4];
#pragma unroll
    for (int l = 0; l < 4; l++) {
        int idx = tid + l * 256;
        int r = idx >> 3, c = idx & 7;
        uint32_t off = r * 128 + c * 16;
        swOff[l] = SWZ(off);
        aG[l] = A + (size_t)(m0 + r) * rowStride + c * 8;
        bG[l] = B + (size_t)(n0 + r) * rowStride + c * 8;
    }

    const int lmRow = ((lane >> 3) & 1) * 8 + (lane & 7);
    const int lmCB  = ((lane >> 4) & 1) * 16;

    // per-chunk plane mapping: seg 0:(hi,hi) 1:(lo,hi) 2:(hi,lo)
#define LOADG(buf, kt)                                                                     \
    {                                                                                      \
        int ktg_ = zKT + (kt);                                                             \
        int s_ = (ktg_ >= KT1) + (ktg_ >= 2 * KT1);                                        \
        int rr_ = ktg_ - s_ * KT1;                                                         \
        size_t aO_ = (size_t)(((s_ == 1) ? KT1 : 0) + rr_) * 64;                           \
        size_t bO_ = (size_t)(((s_ == 2) ? KT1 : 0) + rr_) * 64;                           \
        uint32_t aB_ = base + (buf) * STAGE_B;                                             \
        uint32_t bB_ = aB_ + TILE_B;                                                       \
        _Pragma("unroll")                                                                  \
        for (int l = 0; l < 4; l++) {                                                      \
            asm volatile("cp.async.ca.shared.global [%0], [%1], 16;"                       \
                         :: "r"(aB_ + swOff[l]), "l"(aG[l] + aO_));                        \
            asm volatile("cp.async.ca.shared.global [%0], [%1], 16;"                       \
                         :: "r"(bB_ + swOff[l]), "l"(bG[l] + bO_));                        \
        }                                                                                  \
    }

    LOADG(0, 0);
    asm volatile("cp.async.commit_group;");
    if (KT > 1) LOADG(1, 1);
    asm volatile("cp.async.commit_group;");

    int buf = 0;
    for (int kt = 0; kt < KT; kt++) {
        asm volatile("cp.async.wait_group 1;");
        __syncthreads();

        if (kt + 2 < KT) {
            int nb = buf + 2; if (nb >= 3) nb -= 3;
            LOADG(nb, kt + 2);
        }
        asm volatile("cp.async.commit_group;");

        const uint32_t aBuf = base + buf * STAGE_B;
        const uint32_t bBuf = aBuf + TILE_B;

#pragma unroll
        for (int ks = 0; ks < 4; ks++) {
            const int kbB = ks * 32;
            uint32_t bf[4][2];
#pragma unroll
            for (int h = 0; h < 2; h++) {
                uint32_t off = (uint32_t)(wn * 32 + h * 16 + lmRow) * 128 + kbB + lmCB;
                ldsm4(bBuf + SWZ(off), bf[2 * h][0], bf[2 * h + 1][0], bf[2 * h][1], bf[2 * h + 1][1]);
            }
            uint32_t af[4][4];
#pragma unroll
            for (int mt = 0; mt < 4; mt++) {
                uint32_t off = (uint32_t)(wm * 64 + mt * 16 + lmRow) * 128 + kbB + lmCB;
                ldsm4(aBuf + SWZ(off), af[mt][0], af[mt][1], af[mt][2], af[mt][3]);
            }
#pragma unroll
            for (int mt = 0; mt < 4; mt++)
#pragma unroll
                for (int nt = 0; nt < 4; nt++)
                    mma16(acc[mt][nt], af[mt][0], af[mt][1], af[mt][2], af[mt][3],
                          bf[nt][0], bf[nt][1]);
        }
        if (++buf >= 3) buf = 0;
    }
#undef LOADG

#pragma unroll
    for (int mt = 0; mt < 4; mt++) {
        int r0 = m0 + wm * 64 + mt * 16 + g;
#pragma unroll
        for (int nt = 0; nt < 4; nt++) {
            int col = n0 + wn * 32 + nt * 8 + tg * 2;
            size_t i0 = (size_t)r0 * N + col;
            size_t i1 = i0 + (size_t)8 * N;
            float2 o0, o1;
            o0.x = epi_apply<EPI>(acc[mt][nt][0], i0,     G, R1, R2);
            o0.y = epi_apply<EPI>(acc[mt][nt][1], i0 + 1, G, R1, R2);
            o1.x = epi_apply<EPI>(acc[mt][nt][2], i1,     G, R1, R2);
            o1.y = epi_apply<EPI>(acc[mt][nt][3], i1 + 1, G, R1, R2);
            *(float2*)&D[i0] = o0;
            *(float2*)&D[i1] = o1;
        }
    }
}

// ---------------- legacy FFMA GEMM (tiny-N cases: N=64) ----------------
#define BM 128
#define BN 128
#define BKK 16

template <int EPI>
__global__ __launch_bounds__(256) void gemm_tn(
    const float* __restrict__ A, const float* __restrict__ B, float* __restrict__ D,
    const float* __restrict__ G, const float* __restrict__ R1, const float* __restrict__ R2,
    int M, int N, int K)
{
    __shared__ float As[BKK][BM + 4];
    __shared__ float Bs[BKK][BN + 4];

    const int tid = threadIdx.x;
    const int m0 = blockIdx.y * BM;
    const int n0 = blockIdx.x * BN;
    const int tx = tid & 15;
    const int ty = tid >> 4;

    float acc[8][8];
#pragma unroll
    for (int i = 0; i < 8; i++)
#pragma unroll
        for (int j = 0; j < 8; j++) acc[i][j] = 0.f;

    for (int k0 = 0; k0 < K; k0 += BKK) {
#pragma unroll
        for (int l = 0; l < 2; l++) {
            int qi  = tid + l * 256;
            int row = qi >> 2;
            int kk  = (qi & 3) * 4;
            float4 av = *(const float4*)&A[(size_t)(m0 + row) * K + k0 + kk];
            As[kk + 0][row] = av.x; As[kk + 1][row] = av.y;
            As[kk + 2][row] = av.z; As[kk + 3][row] = av.w;
        }
#pragma unroll
        for (int l = 0; l < 2; l++) {
            int qi  = tid + l * 256;
            int row = qi >> 2;
            int kk  = (qi & 3) * 4;
            float4 bv = make_float4(0.f, 0.f, 0.f, 0.f);
            if (n0 + row < N) bv = *(const float4*)&B[(size_t)(n0 + row) * K + k0 + kk];
            Bs[kk + 0][row] = bv.x; Bs[kk + 1][row] = bv.y;
            Bs[kk + 2][row] = bv.z; Bs[kk + 3][row] = bv.w;
        }
        __syncthreads();

#pragma unroll
        for (int kk = 0; kk < BKK; kk++) {
            float a[8], b[8];
#pragma unroll
            for (int i = 0; i < 8; i++) a[i] = As[kk][ty * 8 + i];
#pragma unroll
            for (int j = 0; j < 8; j++) b[j] = Bs[kk][tx * 8 + j];
#pragma unroll
            for (int i = 0; i < 8; i++)
#pragma unroll
                for (int j = 0; j < 8; j++) acc[i][j] += a[i] * b[j];
        }
        __syncthreads();
    }

#pragma unroll
    for (int i = 0; i < 8; i++) {
        int row = m0 + ty * 8 + i;
#pragma unroll
        for (int j = 0; j < 8; j++) {
            int col = n0 + tx * 8 + j;
            if (col < N) {
                size_t idx = (size_t)row * N + col;
                D[idx] = epi_apply<EPI>(acc[i][j], idx, G, R1, R2);
            }
        }
    }
}

// ---------------- scale_norm with fused 2-plane split ----------------
__global__ __launch_bounds__(256) void scale_norm_split(
    const float* __restrict__ x, float* __restrict__ o,
    __half* __restrict__ o2, const float* __restrict__ g)
{
    int t = blockIdx.x;
    const float4* xr = (const float4*)(x + (size_t)t * XD);
    float4 v0 = xr[threadIdx.x];
    float4 v1 = xr[threadIdx.x + 256];
    float s = v0.x*v0.x + v0.y*v0.y + v0.z*v0.z + v0.w*v0.w
            + v1.x*v1.x + v1.y*v1.y + v1.z*v1.z + v1.w*v1.w;
    for (int off = 16; off; off >>= 1) s += __shfl_xor_sync(0xffffffffu, s, off);
    __shared__ float red[8];
    int w = threadIdx.x >> 5, lane = threadIdx.x & 31;
    if (lane == 0) red[w] = s;
    __syncthreads();
    float tot = red[0] + red[1] + red[2] + red[3] + red[4] + red[5] + red[6] + red[7];
    float sc = g[0] / (sqrtf(tot) + 1e-8f);
    v0.x *= sc; v0.y *= sc; v0.z *= sc; v0.w *= sc;
    v1.x *= sc; v1.y *= sc; v1.z *= sc; v1.w *= sc;
    float4* orow = (float4*)(o + (size_t)t * XD);
    orow[threadIdx.x] = v0;
    orow[threadIdx.x + 256] = v1;
    __half* r2 = o2 + (size_t)t * 2 * XD;
    uint32_t h, l;
    int c0 = threadIdx.x * 4;
    split2h(v0.x, v0.y, h, l);
    *(uint32_t*)(r2 + c0) = h; *(uint32_t*)(r2 + XD + c0) = l;
    split2h(v0.z, v0.w, h, l);
    *(uint32_t*)(r2 + c0 + 2) = h; *(uint32_t*)(r2 + XD + c0 + 2) = l;
    int c1 = c0 + 1024;
    split2h(v1.x, v1.y, h, l);
    *(uint32_t*)(r2 + c1) = h; *(uint32_t*)(r2 + XD + c1) = l;
    split2h(v1.z, v1.w, h, l);
    *(uint32_t*)(r2 + c1 + 2) = h; *(uint32_t*)(r2 + XD + c1 + 2) = l;
}

// ---------------- RoPE ----------------
__global__ __launch_bounds__(128) void rope_all(
    const float* __restrict__ q, const float* __restrict__ k,
    float* __restrict__ qhi, float* __restrict__ klo, float* __restrict__ khi)
{
    int t = blockIdx.x, j = threadIdx.x;
    int r = t & 63;
    float freq = powf(10000.f, -(float)j / 128.f);
    float slo, clo, shi, chi;
    sincosf((float)r * freq, &slo, &clo);
    sincosf((float)(64 + r) * freq, &shi, &chi);
    size_t base = (size_t)t * QD + 2 * j;
    float qe = q[base], qo = q[base + 1];
    qhi[base]     = qe * chi - qo * shi;
    qhi[base + 1] = qo * chi + qe * shi;
    float ke = k[base], ko = k[base + 1];
    klo[base]     = ke * clo - ko * slo;
    klo[base + 1] = ko * clo + ke * slo;
    khi[base]     = ke * chi - ko * shi;
    khi[base + 1] = ko * chi + ke * shi;
}

// ---------------- attention scores + softmax ----------------
__global__ __launch_bounds__(256) void attn_score(
    const float* __restrict__ qr, const float* __restrict__ klo,
    const float* __restrict__ khi, float* __restrict__ Aout)
{
    int w = threadIdx.x >> 5, lane = threadIdx.x & 31;
    int t = blockIdx.x * 8 + w;
    int c = t >> 6, r = t & 63;
    float qreg[8];
#pragma unroll
    for (int i = 0; i < 8; i++) qreg[i] = qr[(size_t)t * QD + i * 32 + lane];

    __shared__ float s_s[8][128];
    for (int m = 0; m < 128; m++) {
        float sc;
        if (c == 0 && m < 64) {
            sc = 0.f;
        } else {
            const float* kp = (m < 64)
                ? &klo[(size_t)((c - 1) * 64 + m) * QD]
                : &khi[(size_t)(c * 64 + (m - 64)) * QD];
            float d = 0.f;
#pragma unroll
            for (int i = 0; i < 8; i++) d += qreg[i] * kp[i * 32 + lane];
            for (int off = 16; off; off >>= 1) d += __shfl_xor_sync(0xffffffffu, d, off);
            sc = d * (1.f / 16.f);
        }
        if (m > r + 64) sc = -1e30f;
        if (lane == 0) s_s[w][m] = sc;
    }
    __syncwarp();
    float a0 = s_s[w][lane], a1 = s_s[w][lane + 32], a2 = s_s[w][lane + 64], a3 = s_s[w][lane + 96];
    float mx = fmaxf(fmaxf(a0, a1), fmaxf(a2, a3));
    for (int off = 16; off; off >>= 1) mx = fmaxf(mx, __shfl_xor_sync(0xffffffffu, mx, off));
    float e0 = expf(a0 - mx), e1 = expf(a1 - mx), e2 = expf(a2 - mx), e3 = expf(a3 - mx);
    float sm = e0 + e1 + e2 + e3;
    for (int off = 16; off; off >>= 1) sm += __shfl_xor_sync(0xffffffffu, sm, off);
    float inv = 1.f / sm;
    size_t ob = (size_t)t * 128;
    Aout[ob + lane]      = e0 * inv;
    Aout[ob + lane + 32] = e1 * inv;
    Aout[ob + lane + 64] = e2 * inv;
    Aout[ob + lane + 96] = e3 * inv;
}

// ---------------- y = A @ v2, fused 2-plane split into y2 ----------------
__global__ __launch_bounds__(256) void attn_av(
    const float* __restrict__ Aat, const float* __restrict__ v,
    __half* __restrict__ y2)
{
    int c = blockIdx.z, rg = blockIdx.y, ct = blockIdx.x;
    int col = ct * 256 + threadIdx.x;
    __shared__ float As[16][128];
    for (int idx = threadIdx.x; idx < 16 * 128; idx += 256) {
        int rr = idx >> 7, mm = idx & 127;
        As[rr][mm] = Aat[(size_t)(c * 64 + rg * 16 + rr) * 128 + mm];
    }
    __syncthreads();
    float acc[16];
#pragma unroll
    for (int r = 0; r < 16; r++) acc[r] = 0.f;
    int mstart = (c == 0) ? 64 : 0;
    for (int m = mstart; m < 128; m++) {
        float vv = v[(size_t)((c - 1) * 64 + m) * XD + col];
#pragma unroll
        for (int r = 0; r < 16; r++) acc[r] += As[r][m] * vv;
    }
#pragma unroll
    for (int r = 0; r < 16; r++) {
        float val = acc[r];
        __half hb = __float2half_rn(val);
        __half lb = __float2half_rn(val - __half2float(hb));
        __half* yr = y2 + (size_t)(c * 64 + rg * 16 + r) * 2 * XD;
        yr[col] = hb; yr[XD + col] = lb;
    }
}

// ---------------- mem prep ----------------
__global__ void mem_prep(const float* __restrict__ beta, const float* __restrict__ decay,
                         float* __restrict__ gam, float* __restrict__ bg)
{
    int n = blockIdx.x, d = threadIdx.x;
    float g = (d < MD - DCD) ? 1.f : sigf(decay[n * DCD + (d - (MD - DCD))]);
    gam[n * MD + d] = g;
    bg[n * MD + d] = g * sigf(beta[n * MD + d]);
}

// ---------------- mem scan ----------------
__global__ __launch_bounds__(256) void mem_scan(
    const float* __restrict__ F, const float* __restrict__ V,
    const float* __restrict__ gam, const float* __restrict__ bg, float* __restrict__ mems)
{
    int n = blockIdx.x, d = threadIdx.x;
    float ga = gam[n * MD + d], b = bg[n * MD + d];
    float m = 0.f;
    float fn = F[n], vn = V[d];
    for (int t = 0; t < T; t++) {
        float f = fn, vv = vn;
        if (t + 1 < T) { fn = F[(t + 1) * MN + n]; vn = V[(size_t)(t + 1) * MD + d]; }
        m = (ga - f * b) * m + f * vv;
        mems[((size_t)t * MN + n) * MD + d] = m;
    }
}

// ---------------- transpose 256x256 ----------------
__global__ void transpose256(const float* __restrict__ W, float* __restrict__ WT)
{
    int rk = blockIdx.x, cd = threadIdx.x;
    WT[cd * MD + rk] = W[rk * MD + cd];
}

// ---------------- mem readout (smem-staged) ----------------
__global__ __launch_bounds__(256) void mem_readout2(
    const float* __restrict__ mems, const float* __restrict__ qk2,
    const float* __restrict__ lq, float* __restrict__ yout)
{
    extern __shared__ float ms[];
    __shared__ float qs[MD];
    __shared__ float as[MN];
    int t = blockIdx.x;
    int tid = threadIdx.x, w = tid >> 5, lane = tid & 31;
    qs[tid] = qk2[(size_t)t * MD + tid];
    const float4* mb4 = (const float4*)(mems + (size_t)t * MN * MD);
    float4* ms4 = (float4*)ms;
#pragma unroll
    for (int i = 0; i < 16; i++) ms4[tid + i * 256] = mb4[tid + i * 256];
    __syncthreads();
#pragma unroll
    for (int mi = 0; mi < 8; mi++) {
        int m = w * 8 + mi;
        float d = 0.f;
#pragma unroll
        for (int i = 0; i < 8; i++) d += ms[m * MD + i * 32 + lane] * qs[i * 32 + lane];
        for (int off = 16; off; off >>= 1) d += __shfl_xor_sync(0xffffffffu, d, off);
        if (lane == 0) as[m] = (d + lq[t * MN + m]) * (1.f / 16.f);
    }
    __syncthreads();
    if (w == 0) {
        float a0 = as[lane], a1 = as[lane + 32];
        float mx = fmaxf(a0, a1);
        for (int off = 16; off; off >>= 1) mx = fmaxf(mx, __shfl_xor_sync(0xffffffffu, mx, off));
        float e0 = expf(a0 - mx), e1 = expf(a1 - mx);
        float sm = e0 + e1;
        for (int off = 16; off; off >>= 1) sm += __shfl_xor_sync(0xffffffffu, sm, off);
        float inv = 1.f / sm;
        as[lane] = e0 * inv;
        as[lane + 32] = e1 * inv;
    }
    __syncthreads();
    float acc = 0.f;
    for (int m = 0; m < MN; m++) acc += as[m] * ms[m * MD + tid];
    yout[(size_t)t * MD + tid] = acc;
}

// ---------------- launcher ----------------
static float* sym(const void* s) { void* p = nullptr; cudaGetSymbolAddress(&p, s); return (float*)p; }
static __half* symh(const void* s) { void* p = nullptr; cudaGetSymbolAddress(&p, s); return (__half*)p; }

extern "C" void kernel_launch(void* const* d_in, const int* in_sizes, int n_in,
                              void* d_out, int out_size)
{
    const float* xs      = (const float*)d_in[0];
    const float* attn_q  = (const float*)d_in[1];
    const float* attn_k  = (const float*)d_in[2];
    const float* attn_v  = (const float*)d_in[3];
    const float* attn_o  = (const float*)d_in[4];
    const float* attn_r  = (const float*)d_in[5];
    const float* mem_f   = (const float*)d_in[6];
    const float* mem_q   = (const float*)d_in[7];
    const float* mem_k   = (const float*)d_in[8];
    const float* mem_v   = (const float*)d_in[9];
    const float* mem_o   = (const float*)d_in[10];
    const float* mem_r   = (const float*)d_in[11];
    const float* mem_beta= (const float*)d_in[12];
    const float* mem_dec = (const float*)d_in[13];
    const float* mem_l   = (const float*)d_in[14];
    const float* ff_in1  = (const float*)d_in[15];
    const float* ff_in2  = (const float*)d_in[16];
    const float* ff_out  = (const float*)d_in[17];
    const float* sn1     = (const float*)d_in[18];
    const float* sn2     = (const float*)d_in[19];
    float* out = (float*)d_out;

    float* xn   = sym(B_xn);   float* q_   = sym(B_q);    float* k_   = sym(B_k);
    float* qhi  = sym(B_qhi);  float* klo  = sym(B_klo);  float* khi  = sym(B_khi);
    float* v_   = sym(B_v);    float* A_   = sym(B_A);
    float* gate = sym(B_gate); float* accb = sym(B_acc);
    float* memF = sym(B_memF); float* memV = sym(B_memV); float* memQ = sym(B_memQ);
    float* gam  = sym(B_gam);  float* bg   = sym(B_bg);   float* wkT  = sym(B_wkT);
    float* qk2  = sym(B_qk2);  float* lq   = sym(B_lq);   float* mems = sym(B_mems);
    float* memY = sym(B_memY); float* x1   = sym(B_x1);   float* x2n  = sym(B_x2n);
    float* h1   = sym(B_h1);   float* part = sym(B_part); float* partF= sym(B_partF);

    __half* xn2  = symh(C_xn2);  __half* q2   = symh(C_q2);
    __half* y2   = symh(C_y2);   __half* memQ2= symh(C_memQ2);
    __half* memY2= symh(C_memY2);__half* x2n2 = symh(C_x2n2);
    __half* h22  = symh(C_h22);
    __half* aq2  = symh(W_aq2);  __half* ak2  = symh(W_ak2);
    __half* av2  = symh(W_av2);  __half* ao2  = symh(W_ao2);
    __half* ar2  = symh(W_ar2);  __half* mv2  = symh(W_mv2);
    __half* mq2  = symh(W_mq2);  __half* mr2  = symh(W_mr2);
    __half* wk2  = symh(W_wk2);  __half* mo2  = symh(W_mo2);
    __half* f12  = symh(W_f12);  __half* f22  = symh(W_f22);
    __half* fo2  = symh(W_fo2);

    cudaFuncSetAttribute(gemm_h16<EPI_NONE>,      cudaFuncAttributeMaxDynamicSharedMemorySize, GB_SMEM);
    cudaFuncSetAttribute(gemm_h16<EPI_GATE>,      cudaFuncAttributeMaxDynamicSharedMemorySize, GB_SMEM);
    cudaFuncSetAttribute(gemm_h16<EPI_GATE_ADD2>, cudaFuncAttributeMaxDynamicSharedMemorySize, GB_SMEM);
    cudaFuncSetAttribute(gemm_h16<EPI_ADD>,       cudaFuncAttributeMaxDynamicSharedMemorySize, GB_SMEM);
    cudaFuncSetAttribute(mem_readout2, cudaFuncAttributeMaxDynamicSharedMemorySize, MN * MD * 4);

    const dim3 blk256(256);
#define GB(EPI_, gx, gy, Aa, Bb, Dd, Gg, Rr1, Rr2, Mm, Nn, Kpk, Kpl)                            \
    gemm_h16<EPI_><<<dim3(gx, gy, 1), blk256, GB_SMEM>>>(Aa, Bb, Dd, Gg, Rr1, Rr2, Mm, Nn, Kpk, Kpk, Kpl)
#define GBSK4(Aa, Bb, Dd, Kpk, Kpl)                                                              \
    do {                                                                                         \
        gemm_h16<EPI_NONE><<<dim3(2, 16, 4), blk256, GB_SMEM>>>(                                 \
            Aa, Bb, part, nullptr, nullptr, nullptr, T, QD, Kpk, (Kpk) / 4, Kpl);                \
        redk<<<T * QD / 1024, blk256>>>(part, Dd, T * QD / 4);                                   \
    } while (0)

    // -------- launch order: #5 (0-based) = grid-256 gemm for ncu -s 5 ----
    transpose256<<<MD, MD>>>(mem_k, wkT);                                   // 0
    cvt_weights_all<<<CVTW_BLOCKS, blk256>>>(                               // 1
        attn_q, attn_k, attn_v, attn_o, attn_r, mem_v, mem_q, mem_r, wkT, mem_o,
        ff_in1, ff_in2, ff_out,
        aq2, ak2, av2, ao2, ar2, mv2, mq2, mr2, wk2, mo2, f12, f22, fo2);
    scale_norm_split<<<T, blk256>>>(xs, xn, xn2, sn1);                      // 2
    gemm_h16<EPI_NONE><<<dim3(2, 16, 4), blk256, GB_SMEM>>>(                // 3: q proj 3-term split-K
        xn2, aq2, part, nullptr, nullptr, nullptr, T, QD, 3 * XD, 3 * XD / 4, XD);
    redk<<<T * QD / 1024, blk256>>>(part, q_, T * QD / 4);                  // 4
    GB(EPI_NONE, 16, 16, xn2, av2, v_, nullptr, nullptr, nullptr, T, XD, 2 * XD, XD);  // 5: v 2-term, PROFILED
    cvtA_t<QD / 4><<<T * QD / 1024, blk256>>>(q_, q2);
    GBSK4(q2, ak2, k_, 3 * QD, QD);                                          // k: 3-term
    GB(EPI_NONE, 16, 16, xn2, ar2, gate, nullptr, nullptr, nullptr, T, XD, XD, XD);   // gate: 1-term
    // attention core
    rope_all<<<T, 128>>>(q_, k_, qhi, klo, khi);
    attn_score<<<T / 8, blk256>>>(qhi, klo, khi, A_);
    attn_av<<<dim3(8, 4, 32), blk256>>>(A_, v_, y2);
    GB(EPI_GATE, 16, 16, y2, ao2, accb, gate, nullptr, nullptr, T, XD, 2 * XD, XD);   // ao: 2-term
    // mem projections + gate
    gemm_tn<EPI_SIGMOID><<<dim3(1, 16), blk256>>>(xn, mem_f, memF, nullptr, nullptr, nullptr, T, MN, XD);
    GBSK4(xn2, mv2, memV, 3 * XD, XD);                                       // 3-term
    GBSK4(xn2, mq2, memQ, 3 * XD, XD);                                       // 3-term
    GB(EPI_NONE, 16, 16, xn2, mr2, gate, nullptr, nullptr, nullptr, T, XD, XD, XD);   // gate: 1-term
    // scan
    mem_prep<<<MN, MD>>>(mem_beta, mem_dec, gam, bg);
    mem_scan<<<MN, MD>>>(memF, memV, gam, bg, mems);
    // readout
    cvtA_t<MD / 4><<<T * MD / 1024, blk256>>>(memQ, memQ2);
    GBSK4(memQ2, wk2, qk2, 3 * MD, MD);                                      // 3-term
    gemm_tn<EPI_NONE><<<dim3(1, 16), blk256>>>(memQ, mem_l, lq, nullptr, nullptr, nullptr, T, MN, MD);
    mem_readout2<<<T, blk256, MN * MD * 4>>>(mems, qk2, lq, memY);
    // x1 = (memY @ mem_o^T)*sigmoid(gate) + attn_out + xs
    cvtA_t<MD / 4><<<T * MD / 1024, blk256>>>(memY, memY2);
    GB(EPI_GATE_ADD2, 16, 16, memY2, mo2, x1, gate, accb, xs, T, XD, 3 * MD, MD);     // 3-term (cheap)
    // FF block: f1/f2 2-term with split-K x2; fo 2-term
    scale_norm_split<<<T, blk256>>>(x1, x2n, x2n2, sn2);
    gemm_h16<EPI_NONE><<<dim3(22, 16, 2), blk256, GB_SMEM>>>(
        x2n2, f12, partF, nullptr, nullptr, nullptr, T, FFD, 2 * XD, XD, XD);
    redk2<<<T * FFD / 1024, blk256>>>(partF, h1, T * FFD / 4);
    gemm_h16<EPI_NONE><<<dim3(22, 16, 2), blk256, GB_SMEM>>>(
        x2n2, f22, partF, nullptr, nullptr, nullptr, T, FFD, 2 * XD, XD, XD);
    red2_silu_split<<<T * FFD / 1024, blk256>>>(partF, h1, h22);
    GB(EPI_ADD, 16, 16, h22, fo2, out, nullptr, x1, nullptr, T, XD, 2 * FFD, FFD);    // fo: 2-term
#undef GB
#undef GBSK4
}

// round 15
// speedup vs baseline: 3.4275x; 1.1644x over previous
#include <cuda_runtime.h>
#include <cuda_fp16.h>
#include <math.h>
#include <stdint.h>

// ---------------- problem dims ----------------
#define T    2048
#define XD   2048
#define QD   256
#define MN   64
#define MD   256
#define DCD  64
#define FFD  2816
#define CH   64

// ---------------- fp32 scratch ----------------
__device__ float B_xn  [(size_t)T*XD];
__device__ float B_q   [(size_t)T*QD];
__device__ float B_k   [(size_t)T*QD];
__device__ float B_qhi [(size_t)T*QD];
__device__ float B_klo [(size_t)T*QD];
__device__ float B_khi [(size_t)T*QD];
__device__ float B_v   [(size_t)T*XD];
__device__ float B_A   [(size_t)T*2*CH];
__device__ float B_gate[(size_t)T*XD];
__device__ float B_acc [(size_t)T*XD];
__device__ float B_memF[(size_t)T*MN];
__device__ float B_memV[(size_t)T*MD];
__device__ float B_memQ[(size_t)T*MD];
__device__ float B_gam [(size_t)MN*MD];
__device__ float B_bg  [(size_t)MN*MD];
__device__ float B_wkT [(size_t)MD*MD];
__device__ float B_qk2 [(size_t)T*MD];
__device__ float B_lq  [(size_t)T*MN];
__device__ float B_mems[(size_t)T*MN*MD];
__device__ float B_memY[(size_t)T*MD];
__device__ float B_x1  [(size_t)T*XD];
__device__ float B_x2n [(size_t)T*XD];
__device__ float B_h1  [(size_t)T*FFD];
__device__ float B_part[(size_t)4*T*MD];    // split-K x4 partials (N=256 GEMMs)
__device__ float B_partF[(size_t)2*T*FFD];  // split-K x2 partials (FF GEMMs)

// ---------------- fp16 2-plane scratch: row = [hi(K) | lo(K)] ----------------
__device__ __half C_xn2  [(size_t)T*2*XD];
__device__ __half C_q2   [(size_t)T*2*QD];
__device__ __half C_y2   [(size_t)T*2*XD];
__device__ __half C_memQ2[(size_t)T*2*MD];
__device__ __half C_memY2[(size_t)T*2*MD];
__device__ __half C_x2n2 [(size_t)T*2*XD];
__device__ __half C_h22  [(size_t)T*2*FFD];
__device__ __half W_aq2  [(size_t)QD*2*XD];
__device__ __half W_ak2  [(size_t)QD*2*QD];
__device__ __half W_av2  [(size_t)XD*2*XD];
__device__ __half W_ao2  [(size_t)XD*2*XD];
__device__ __half W_ar2  [(size_t)XD*2*XD];
__device__ __half W_mv2  [(size_t)MD*2*XD];
__device__ __half W_mq2  [(size_t)MD*2*XD];
__device__ __half W_mr2  [(size_t)XD*2*XD];
__device__ __half W_wk2  [(size_t)MD*2*MD];
__device__ __half W_mo2  [(size_t)XD*2*MD];
__device__ __half W_f12  [(size_t)FFD*2*XD];
__device__ __half W_f22  [(size_t)FFD*2*XD];
__device__ __half W_fo2  [(size_t)XD*2*FFD];

__device__ __forceinline__ float sigf(float x) { return 1.f / (1.f + expf(-x)); }

enum { EPI_NONE = 0, EPI_SIGMOID, EPI_GATE, EPI_GATE_ADD2, EPI_ADD };

// fp16 hi/lo split: hi = f16x2(v0,v1) (v0 low), lo = f16x2 of residuals
__device__ __forceinline__ void split2h(float v0, float v1, uint32_t& hi, uint32_t& lo)
{
    asm("cvt.rn.f16x2.f32 %0, %1, %2;" : "=r"(hi) : "f"(v1), "f"(v0));
    __half2 hh = *(__half2*)&hi;
    float h0 = __half2float(__low2half(hh));
    float h1 = __half2float(__high2half(hh));
    asm("cvt.rn.f16x2.f32 %0, %1, %2;" : "=r"(lo) : "f"(v1 - h1), "f"(v0 - h0));
}

// ---------------- split conversion: 4 elems/thread -> 2-plane row [hi|lo] ----------------
template <int KQ>
__device__ __forceinline__ void cvt_one(const float* __restrict__ src,
                                        __half* __restrict__ dst, int b, int tid)
{
    int idx4 = b * 256 + tid;
    int row = idx4 / KQ;
    int cq  = idx4 - row * KQ;
    const int K = KQ * 4;
    float4 v = ((const float4*)src)[idx4];
    uint32_t h0, l0, h1, l1;
    split2h(v.x, v.y, h0, l0);
    split2h(v.z, v.w, h1, l1);
    __half* dr = dst + (size_t)row * 2 * K + cq * 4;
    *(uint2*)dr       = make_uint2(h0, h1);
    *(uint2*)(dr + K) = make_uint2(l0, l1);
}

// one launch converts all 13 weight matrices (shapes compile-time)
__global__ __launch_bounds__(256) void cvt_weights_all(
    const float* aq, const float* ak, const float* av, const float* ao, const float* ar,
    const float* mv, const float* mq, const float* mr, const float* wk, const float* mo,
    const float* f1, const float* f2, const float* fo,
    __half* aq2, __half* ak2, __half* av2, __half* ao2,
    __half* ar2, __half* mv2, __half* mq2, __half* mr2,
    __half* wk2, __half* mo2, __half* f12, __half* f22,
    __half* fo2)
{
    int b = blockIdx.x, tid = threadIdx.x;
    if (b < 512)  { cvt_one<512>(aq, aq2, b, tid); return; }  b -= 512;   // 256x2048
    if (b < 64)   { cvt_one<64 >(ak, ak2, b, tid); return; }  b -= 64;    // 256x256
    if (b < 4096) { cvt_one<512>(av, av2, b, tid); return; }  b -= 4096;  // 2048x2048
    if (b < 4096) { cvt_one<512>(ao, ao2, b, tid); return; }  b -= 4096;
    if (b < 4096) { cvt_one<512>(ar, ar2, b, tid); return; }  b -= 4096;
    if (b < 512)  { cvt_one<512>(mv, mv2, b, tid); return; }  b -= 512;
    if (b < 512)  { cvt_one<512>(mq, mq2, b, tid); return; }  b -= 512;
    if (b < 4096) { cvt_one<512>(mr, mr2, b, tid); return; }  b -= 4096;
    if (b < 64)   { cvt_one<64 >(wk, wk2, b, tid); return; }  b -= 64;
    if (b < 512)  { cvt_one<64 >(mo, mo2, b, tid); return; }  b -= 512;   // 2048x256
    if (b < 5632) { cvt_one<512>(f1, f12, b, tid); return; }  b -= 5632;  // 2816x2048
    if (b < 5632) { cvt_one<512>(f2, f22, b, tid); return; }  b -= 5632;
    cvt_one<704>(fo, fo2, b, tid);                                        // 2048x2816
}
#define CVTW_BLOCKS 35456

template <int KQ>
__global__ __launch_bounds__(256) void cvtA_t(const float* __restrict__ src,
                                              __half* __restrict__ dst)
{
    cvt_one<KQ>(src, dst, blockIdx.x, threadIdx.x);
}

// ---------------- split-K reduces ----------------
__global__ __launch_bounds__(256) void redk(const float* __restrict__ p,
                                            float* __restrict__ o, int n4)
{
    int i = blockIdx.x * 256 + threadIdx.x;
    const float4* p4 = (const float4*)p;
    float4 a = p4[i], b = p4[i + n4], c = p4[i + 2 * n4], d = p4[i + 3 * n4];
    ((float4*)o)[i] = make_float4(a.x + b.x + c.x + d.x, a.y + b.y + c.y + d.y,
                                  a.z + b.z + c.z + d.z, a.w + b.w + c.w + d.w);
}

__global__ __launch_bounds__(256) void redk2(const float* __restrict__ p,
                                             float* __restrict__ o, int n4)
{
    int i = blockIdx.x * 256 + threadIdx.x;
    const float4* p4 = (const float4*)p;
    float4 a = p4[i], b = p4[i + n4];
    ((float4*)o)[i] = make_float4(a.x + b.x, a.y + b.y, a.z + b.z, a.w + b.w);
}

// reduce 2 planes + silu gate + 2-plane fp16 split (for FF h2)
__global__ __launch_bounds__(256) void red2_silu_split(
    const float* __restrict__ p, const float* __restrict__ h1,
    __half* __restrict__ o2)
{
    int idx4 = blockIdx.x * 256 + threadIdx.x;
    const int KQ = FFD / 4;
    int row = idx4 / KQ;
    int cq  = idx4 - row * KQ;
    const float4* p4 = (const float4*)p;
    float4 a = p4[idx4], b = p4[idx4 + (size_t)T * FFD / 4];
    float4 g = ((const float4*)h1)[idx4];
    float c0 = (a.x + b.x) * (g.x * sigf(g.x));
    float c1 = (a.y + b.y) * (g.y * sigf(g.y));
    float c2 = (a.z + b.z) * (g.z * sigf(g.z));
    float c3 = (a.w + b.w) * (g.w * sigf(g.w));
    uint32_t h0, l0, h1b, l1;
    split2h(c0, c1, h0, l0);
    split2h(c2, c3, h1b, l1);
    __half* dr = o2 + (size_t)row * 2 * FFD + cq * 4;
    *(uint2*)dr         = make_uint2(h0, h1b);
    *(uint2*)(dr + FFD) = make_uint2(l0, l1);
}

// =====================================================================
//  fp16 mma.sync GEMM over 2-plane [hi|lo] operands.
//  Segment pairs per K-chunk: 0:(hi,hi) 1:(lo,hi) 2:(hi,lo)
//  Kpack = Kplane (1-term) / 2*Kplane (2-term) / 3*Kplane (full compensation)
//  tile 128x128, BK=64, 3-stage cp.async, one barrier per K-iter; split-K by z.
// =====================================================================
#define SWZ(off) ((off) ^ (((off) >> 3) & 0x70))
#define TILE_B   16384
#define STAGE_B  (2 * TILE_B)
#define GB_SMEM  (3 * STAGE_B)   // 96 KB

template <int EPI>
__device__ __forceinline__ float epi_apply(float c, size_t idx,
                                           const float* __restrict__ G,
                                           const float* __restrict__ R1,
                                           const float* __restrict__ R2)
{
    if (EPI == EPI_SIGMOID)        c = sigf(c);
    else if (EPI == EPI_GATE)      c = c * sigf(G[idx]);
    else if (EPI == EPI_GATE_ADD2) c = c * sigf(G[idx]) + R1[idx] + R2[idx];
    else if (EPI == EPI_ADD)       c = c + R1[idx];
    return c;
}

__device__ __forceinline__ void mma16(float* c, uint32_t a0, uint32_t a1, uint32_t a2, uint32_t a3,
                                      uint32_t b0, uint32_t b1)
{
    asm volatile(
        "mma.sync.aligned.m16n8k16.row.col.f32.f16.f16.f32 "
        "{%0,%1,%2,%3}, {%4,%5,%6,%7}, {%8,%9}, {%0,%1,%2,%3};"
        : "+f"(c[0]), "+f"(c[1]), "+f"(c[2]), "+f"(c[3])
        : "r"(a0), "r"(a1), "r"(a2), "r"(a3), "r"(b0), "r"(b1));
}

__device__ __forceinline__ void ldsm4(uint32_t addr, uint32_t& r0, uint32_t& r1,
                                      uint32_t& r2, uint32_t& r3)
{
    asm volatile("ldmatrix.sync.aligned.m8n8.x4.shared.b16 {%0,%1,%2,%3}, [%4];"
                 : "=r"(r0), "=r"(r1), "=r"(r2), "=r"(r3) : "r"(addr));
}

template <int EPI>
__global__ __launch_bounds__(256, 2) void gemm_h16(
    const __half* __restrict__ A, const __half* __restrict__ B,
    float* __restrict__ D,
    const float* __restrict__ G, const float* __restrict__ R1, const float* __restrict__ R2,
    int M, int N, int Kpack, int Kchunk, int Kplane)
{
    extern __shared__ __half smem[];

    const int tid  = threadIdx.x;
    const int wid  = tid >> 5, lane = tid & 31;
    const int wm   = wid & 1, wn = wid >> 1;
    const int g    = lane >> 2, tg = lane & 3;
    const int m0   = blockIdx.y * 128;
    const int n0   = blockIdx.x * 128;
    const int z    = blockIdx.z;

    D += (size_t)z * M * N;

    float acc[4][4][4];
#pragma unroll
    for (int mt = 0; mt < 4; mt++)
#pragma unroll
        for (int nt = 0; nt < 4; nt++)
#pragma unroll
            for (int e = 0; e < 4; e++) acc[mt][nt][e] = 0.f;

    const int KT  = Kchunk >> 6;
    const int KT1 = Kplane >> 6;
    const int zKT = z * KT;
    const int rowStride = 2 * Kplane;

    uint32_t base;
    asm("{ .reg .u64 t; cvta.to.shared.u64 t, %1; cvt.u32.u64 %0, t; }" : "=r"(base) : "l"(smem));

    uint32_t swOff[4];
    const __half* aG[4];
    const __half* bG[4];
#pragma unroll
    for (int l = 0; l < 4; l++) {
        int idx = tid + l * 256;
        int r = idx >> 3, c = idx & 7;
        uint32_t off = r * 128 + c * 16;
        swOff[l] = SWZ(off);
        aG[l] = A + (size_t)(m0 + r) * rowStride + c * 8;
        bG[l] = B + (size_t)(n0 + r) * rowStride + c * 8;
    }

    const int lmRow = ((lane >> 3) & 1) * 8 + (lane & 7);
    const int lmCB  = ((lane >> 4) & 1) * 16;

    // per-chunk plane mapping: seg 0:(hi,hi) 1:(lo,hi) 2:(hi,lo)
#define LOADG(buf, kt)                                                                     \
    {                                                                                      \
        int ktg_ = zKT + (kt);                                                             \
        int s_ = (ktg_ >= KT1) + (ktg_ >= 2 * KT1);                                        \
        int rr_ = ktg_ - s_ * KT1;                                                         \
        size_t aO_ = (size_t)(((s_ == 1) ? KT1 : 0) + rr_) * 64;                           \
        size_t bO_ = (size_t)(((s_ == 2) ? KT1 : 0) + rr_) * 64;                           \
        uint32_t aB_ = base + (buf) * STAGE_B;                                             \
        uint32_t bB_ = aB_ + TILE_B;                                                       \
        _Pragma("unroll")                                                                  \
        for (int l = 0; l < 4; l++) {                                                      \
            asm volatile("cp.async.ca.shared.global [%0], [%1], 16;"                       \
                         :: "r"(aB_ + swOff[l]), "l"(aG[l] + aO_));                        \
            asm volatile("cp.async.ca.shared.global [%0], [%1], 16;"                       \
                         :: "r"(bB_ + swOff[l]), "l"(bG[l] + bO_));                        \
        }                                                                                  \
    }

    LOADG(0, 0);
    asm volatile("cp.async.commit_group;");
    if (KT > 1) LOADG(1, 1);
    asm volatile("cp.async.commit_group;");

    int buf = 0;
    for (int kt = 0; kt < KT; kt++) {
        asm volatile("cp.async.wait_group 1;");
        __syncthreads();

        if (kt + 2 < KT) {
            int nb = buf + 2; if (nb >= 3) nb -= 3;
            LOADG(nb, kt + 2);
        }
        asm volatile("cp.async.commit_group;");

        const uint32_t aBuf = base + buf * STAGE_B;
        const uint32_t bBuf = aBuf + TILE_B;

#pragma unroll
        for (int ks = 0; ks < 4; ks++) {
            const int kbB = ks * 32;
            uint32_t bf[4][2];
#pragma unroll
            for (int h = 0; h < 2; h++) {
                uint32_t off = (uint32_t)(wn * 32 + h * 16 + lmRow) * 128 + kbB + lmCB;
                ldsm4(bBuf + SWZ(off), bf[2 * h][0], bf[2 * h + 1][0], bf[2 * h][1], bf[2 * h + 1][1]);
            }
            uint32_t af[4][4];
#pragma unroll
            for (int mt = 0; mt < 4; mt++) {
                uint32_t off = (uint32_t)(wm * 64 + mt * 16 + lmRow) * 128 + kbB + lmCB;
                ldsm4(aBuf + SWZ(off), af[mt][0], af[mt][1], af[mt][2], af[mt][3]);
            }
#pragma unroll
            for (int mt = 0; mt < 4; mt++)
#pragma unroll
                for (int nt = 0; nt < 4; nt++)
                    mma16(acc[mt][nt], af[mt][0], af[mt][1], af[mt][2], af[mt][3],
                          bf[nt][0], bf[nt][1]);
        }
        if (++buf >= 3) buf = 0;
    }
#undef LOADG

#pragma unroll
    for (int mt = 0; mt < 4; mt++) {
        int r0 = m0 + wm * 64 + mt * 16 + g;
#pragma unroll
        for (int nt = 0; nt < 4; nt++) {
            int col = n0 + wn * 32 + nt * 8 + tg * 2;
            size_t i0 = (size_t)r0 * N + col;
            size_t i1 = i0 + (size_t)8 * N;
            float2 o0, o1;
            o0.x = epi_apply<EPI>(acc[mt][nt][0], i0,     G, R1, R2);
            o0.y = epi_apply<EPI>(acc[mt][nt][1], i0 + 1, G, R1, R2);
            o1.x = epi_apply<EPI>(acc[mt][nt][2], i1,     G, R1, R2);
            o1.y = epi_apply<EPI>(acc[mt][nt][3], i1 + 1, G, R1, R2);
            *(float2*)&D[i0] = o0;
            *(float2*)&D[i1] = o1;
        }
    }
}

// ---------------- legacy FFMA GEMM (tiny-N cases: N=64) ----------------
#define BM 128
#define BN 128
#define BKK 16

template <int EPI>
__global__ __launch_bounds__(256) void gemm_tn(
    const float* __restrict__ A, const float* __restrict__ B, float* __restrict__ D,
    const float* __restrict__ G, const float* __restrict__ R1, const float* __restrict__ R2,
    int M, int N, int K)
{
    __shared__ float As[BKK][BM + 4];
    __shared__ float Bs[BKK][BN + 4];

    const int tid = threadIdx.x;
    const int m0 = blockIdx.y * BM;
    const int n0 = blockIdx.x * BN;
    const int tx = tid & 15;
    const int ty = tid >> 4;

    float acc[8][8];
#pragma unroll
    for (int i = 0; i < 8; i++)
#pragma unroll
        for (int j = 0; j < 8; j++) acc[i][j] = 0.f;

    for (int k0 = 0; k0 < K; k0 += BKK) {
#pragma unroll
        for (int l = 0; l < 2; l++) {
            int qi  = tid + l * 256;
            int row = qi >> 2;
            int kk  = (qi & 3) * 4;
            float4 av = *(const float4*)&A[(size_t)(m0 + row) * K + k0 + kk];
            As[kk + 0][row] = av.x; As[kk + 1][row] = av.y;
            As[kk + 2][row] = av.z; As[kk + 3][row] = av.w;
        }
#pragma unroll
        for (int l = 0; l < 2; l++) {
            int qi  = tid + l * 256;
            int row = qi >> 2;
            int kk  = (qi & 3) * 4;
            float4 bv = make_float4(0.f, 0.f, 0.f, 0.f);
            if (n0 + row < N) bv = *(const float4*)&B[(size_t)(n0 + row) * K + k0 + kk];
            Bs[kk + 0][row] = bv.x; Bs[kk + 1][row] = bv.y;
            Bs[kk + 2][row] = bv.z; Bs[kk + 3][row] = bv.w;
        }
        __syncthreads();

#pragma unroll
        for (int kk = 0; kk < BKK; kk++) {
            float a[8], b[8];
#pragma unroll
            for (int i = 0; i < 8; i++) a[i] = As[kk][ty * 8 + i];
#pragma unroll
            for (int j = 0; j < 8; j++) b[j] = Bs[kk][tx * 8 + j];
#pragma unroll
            for (int i = 0; i < 8; i++)
#pragma unroll
                for (int j = 0; j < 8; j++) acc[i][j] += a[i] * b[j];
        }
        __syncthreads();
    }

#pragma unroll
    for (int i = 0; i < 8; i++) {
        int row = m0 + ty * 8 + i;
#pragma unroll
        for (int j = 0; j < 8; j++) {
            int col = n0 + tx * 8 + j;
            if (col < N) {
                size_t idx = (size_t)row * N + col;
                D[idx] = epi_apply<EPI>(acc[i][j], idx, G, R1, R2);
            }
        }
    }
}

// ---------------- scale_norm with fused 2-plane split ----------------
__global__ __launch_bounds__(256) void scale_norm_split(
    const float* __restrict__ x, float* __restrict__ o,
    __half* __restrict__ o2, const float* __restrict__ g)
{
    int t = blockIdx.x;
    const float4* xr = (const float4*)(x + (size_t)t * XD);
    float4 v0 = xr[threadIdx.x];
    float4 v1 = xr[threadIdx.x + 256];
    float s = v0.x*v0.x + v0.y*v0.y + v0.z*v0.z + v0.w*v0.w
            + v1.x*v1.x + v1.y*v1.y + v1.z*v1.z + v1.w*v1.w;
    for (int off = 16; off; off >>= 1) s += __shfl_xor_sync(0xffffffffu, s, off);
    __shared__ float red[8];
    int w = threadIdx.x >> 5, lane = threadIdx.x & 31;
    if (lane == 0) red[w] = s;
    __syncthreads();
    float tot = red[0] + red[1] + red[2] + red[3] + red[4] + red[5] + red[6] + red[7];
    float sc = g[0] / (sqrtf(tot) + 1e-8f);
    v0.x *= sc; v0.y *= sc; v0.z *= sc; v0.w *= sc;
    v1.x *= sc; v1.y *= sc; v1.z *= sc; v1.w *= sc;
    float4* orow = (float4*)(o + (size_t)t * XD);
    orow[threadIdx.x] = v0;
    orow[threadIdx.x + 256] = v1;
    __half* r2 = o2 + (size_t)t * 2 * XD;
    uint32_t h, l;
    int c0 = threadIdx.x * 4;
    split2h(v0.x, v0.y, h, l);
    *(uint32_t*)(r2 + c0) = h; *(uint32_t*)(r2 + XD + c0) = l;
    split2h(v0.z, v0.w, h, l);
    *(uint32_t*)(r2 + c0 + 2) = h; *(uint32_t*)(r2 + XD + c0 + 2) = l;
    int c1 = c0 + 1024;
    split2h(v1.x, v1.y, h, l);
    *(uint32_t*)(r2 + c1) = h; *(uint32_t*)(r2 + XD + c1) = l;
    split2h(v1.z, v1.w, h, l);
    *(uint32_t*)(r2 + c1 + 2) = h; *(uint32_t*)(r2 + XD + c1 + 2) = l;
}

// ---------------- RoPE ----------------
__global__ __launch_bounds__(128) void rope_all(
    const float* __restrict__ q, const float* __restrict__ k,
    float* __restrict__ qhi, float* __restrict__ klo, float* __restrict__ khi)
{
    int t = blockIdx.x, j = threadIdx.x;
    int r = t & 63;
    float freq = powf(10000.f, -(float)j / 128.f);
    float slo, clo, shi, chi;
    sincosf((float)r * freq, &slo, &clo);
    sincosf((float)(64 + r) * freq, &shi, &chi);
    size_t base = (size_t)t * QD + 2 * j;
    float qe = q[base], qo = q[base + 1];
    qhi[base]     = qe * chi - qo * shi;
    qhi[base + 1] = qo * chi + qe * shi;
    float ke = k[base], ko = k[base + 1];
    klo[base]     = ke * clo - ko * slo;
    klo[base + 1] = ko * clo + ke * slo;
    khi[base]     = ke * chi - ko * shi;
    khi[base + 1] = ko * chi + ke * shi;
}

// ---------------- attention scores + softmax ----------------
__global__ __launch_bounds__(256) void attn_score(
    const float* __restrict__ qr, const float* __restrict__ klo,
    const float* __restrict__ khi, float* __restrict__ Aout)
{
    int w = threadIdx.x >> 5, lane = threadIdx.x & 31;
    int t = blockIdx.x * 8 + w;
    int c = t >> 6, r = t & 63;
    float qreg[8];
#pragma unroll
    for (int i = 0; i < 8; i++) qreg[i] = qr[(size_t)t * QD + i * 32 + lane];

    __shared__ float s_s[8][128];
    for (int m = 0; m < 128; m++) {
        float sc;
        if (c == 0 && m < 64) {
            sc = 0.f;
        } else {
            const float* kp = (m < 64)
                ? &klo[(size_t)((c - 1) * 64 + m) * QD]
                : &khi[(size_t)(c * 64 + (m - 64)) * QD];
            float d = 0.f;
#pragma unroll
            for (int i = 0; i < 8; i++) d += qreg[i] * kp[i * 32 + lane];
            for (int off = 16; off; off >>= 1) d += __shfl_xor_sync(0xffffffffu, d, off);
            sc = d * (1.f / 16.f);
        }
        if (m > r + 64) sc = -1e30f;
        if (lane == 0) s_s[w][m] = sc;
    }
    __syncwarp();
    float a0 = s_s[w][lane], a1 = s_s[w][lane + 32], a2 = s_s[w][lane + 64], a3 = s_s[w][lane + 96];
    float mx = fmaxf(fmaxf(a0, a1), fmaxf(a2, a3));
    for (int off = 16; off; off >>= 1) mx = fmaxf(mx, __shfl_xor_sync(0xffffffffu, mx, off));
    float e0 = expf(a0 - mx), e1 = expf(a1 - mx), e2 = expf(a2 - mx), e3 = expf(a3 - mx);
    float sm = e0 + e1 + e2 + e3;
    for (int off = 16; off; off >>= 1) sm += __shfl_xor_sync(0xffffffffu, sm, off);
    float inv = 1.f / sm;
    size_t ob = (size_t)t * 128;
    Aout[ob + lane]      = e0 * inv;
    Aout[ob + lane + 32] = e1 * inv;
    Aout[ob + lane + 64] = e2 * inv;
    Aout[ob + lane + 96] = e3 * inv;
}

// ---------------- y = A @ v2, fused 2-plane split into y2 ----------------
__global__ __launch_bounds__(256) void attn_av(
    const float* __restrict__ Aat, const float* __restrict__ v,
    __half* __restrict__ y2)
{
    int c = blockIdx.z, rg = blockIdx.y, ct = blockIdx.x;
    int col = ct * 256 + threadIdx.x;
    __shared__ float As[16][128];
    for (int idx = threadIdx.x; idx < 16 * 128; idx += 256) {
        int rr = idx >> 7, mm = idx & 127;
        As[rr][mm] = Aat[(size_t)(c * 64 + rg * 16 + rr) * 128 + mm];
    }
    __syncthreads();
    float acc[16];
#pragma unroll
    for (int r = 0; r < 16; r++) acc[r] = 0.f;
    int mstart = (c == 0) ? 64 : 0;
    for (int m = mstart; m < 128; m++) {
        float vv = v[(size_t)((c - 1) * 64 + m) * XD + col];
#pragma unroll
        for (int r = 0; r < 16; r++) acc[r] += As[r][m] * vv;
    }
#pragma unroll
    for (int r = 0; r < 16; r++) {
        float val = acc[r];
        __half hb = __float2half_rn(val);
        __half lb = __float2half_rn(val - __half2float(hb));
        __half* yr = y2 + (size_t)(c * 64 + rg * 16 + r) * 2 * XD;
        yr[col] = hb; yr[XD + col] = lb;
    }
}

// ---------------- mem prep ----------------
__global__ void mem_prep(const float* __restrict__ beta, const float* __restrict__ decay,
                         float* __restrict__ gam, float* __restrict__ bg)
{
    int n = blockIdx.x, d = threadIdx.x;
    float g = (d < MD - DCD) ? 1.f : sigf(decay[n * DCD + (d - (MD - DCD))]);
    gam[n * MD + d] = g;
    bg[n * MD + d] = g * sigf(beta[n * MD + d]);
}

// ---------------- mem scan ----------------
__global__ __launch_bounds__(256) void mem_scan(
    const float* __restrict__ F, const float* __restrict__ V,
    const float* __restrict__ gam, const float* __restrict__ bg, float* __restrict__ mems)
{
    int n = blockIdx.x, d = threadIdx.x;
    float ga = gam[n * MD + d], b = bg[n * MD + d];
    float m = 0.f;
    float fn = F[n], vn = V[d];
    for (int t = 0; t < T; t++) {
        float f = fn, vv = vn;
        if (t + 1 < T) { fn = F[(t + 1) * MN + n]; vn = V[(size_t)(t + 1) * MD + d]; }
        m = (ga - f * b) * m + f * vv;
        mems[((size_t)t * MN + n) * MD + d] = m;
    }
}

// ---------------- transpose 256x256 ----------------
__global__ void transpose256(const float* __restrict__ W, float* __restrict__ WT)
{
    int rk = blockIdx.x, cd = threadIdx.x;
    WT[cd * MD + rk] = W[rk * MD + cd];
}

// ---------------- mem readout (smem-staged) ----------------
__global__ __launch_bounds__(256) void mem_readout2(
    const float* __restrict__ mems, const float* __restrict__ qk2,
    const float* __restrict__ lq, float* __restrict__ yout)
{
    extern __shared__ float ms[];
    __shared__ float qs[MD];
    __shared__ float as[MN];
    int t = blockIdx.x;
    int tid = threadIdx.x, w = tid >> 5, lane = tid & 31;
    qs[tid] = qk2[(size_t)t * MD + tid];
    const float4* mb4 = (const float4*)(mems + (size_t)t * MN * MD);
    float4* ms4 = (float4*)ms;
#pragma unroll
    for (int i = 0; i < 16; i++) ms4[tid + i * 256] = mb4[tid + i * 256];
    __syncthreads();
#pragma unroll
    for (int mi = 0; mi < 8; mi++) {
        int m = w * 8 + mi;
        float d = 0.f;
#pragma unroll
        for (int i = 0; i < 8; i++) d += ms[m * MD + i * 32 + lane] * qs[i * 32 + lane];
        for (int off = 16; off; off >>= 1) d += __shfl_xor_sync(0xffffffffu, d, off);
        if (lane == 0) as[m] = (d + lq[t * MN + m]) * (1.f / 16.f);
    }
    __syncthreads();
    if (w == 0) {
        float a0 = as[lane], a1 = as[lane + 32];
        float mx = fmaxf(a0, a1);
        for (int off = 16; off; off >>= 1) mx = fmaxf(mx, __shfl_xor_sync(0xffffffffu, mx, off));
        float e0 = expf(a0 - mx), e1 = expf(a1 - mx);
        float sm = e0 + e1;
        for (int off = 16; off; off >>= 1) sm += __shfl_xor_sync(0xffffffffu, sm, off);
        float inv = 1.f / sm;
        as[lane] = e0 * inv;
        as[lane + 32] = e1 * inv;
    }
    __syncthreads();
    float acc = 0.f;
    for (int m = 0; m < MN; m++) acc += as[m] * ms[m * MD + tid];
    yout[(size_t)t * MD + tid] = acc;
}

// ---------------- launcher ----------------
static float* sym(const void* s) { void* p = nullptr; cudaGetSymbolAddress(&p, s); return (float*)p; }
static __half* symh(const void* s) { void* p = nullptr; cudaGetSymbolAddress(&p, s); return (__half*)p; }

extern "C" void kernel_launch(void* const* d_in, const int* in_sizes, int n_in,
                              void* d_out, int out_size)
{
    const float* xs      = (const float*)d_in[0];
    const float* attn_q  = (const float*)d_in[1];
    const float* attn_k  = (const float*)d_in[2];
    const float* attn_v  = (const float*)d_in[3];
    const float* attn_o  = (const float*)d_in[4];
    const float* attn_r  = (const float*)d_in[5];
    const float* mem_f   = (const float*)d_in[6];
    const float* mem_q   = (const float*)d_in[7];
    const float* mem_k   = (const float*)d_in[8];
    const float* mem_v   = (const float*)d_in[9];
    const float* mem_o   = (const float*)d_in[10];
    const float* mem_r   = (const float*)d_in[11];
    const float* mem_beta= (const float*)d_in[12];
    const float* mem_dec = (const float*)d_in[13];
    const float* mem_l   = (const float*)d_in[14];
    const float* ff_in1  = (const float*)d_in[15];
    const float* ff_in2  = (const float*)d_in[16];
    const float* ff_out  = (const float*)d_in[17];
    const float* sn1     = (const float*)d_in[18];
    const float* sn2     = (const float*)d_in[19];
    float* out = (float*)d_out;

    float* xn   = sym(B_xn);   float* q_   = sym(B_q);    float* k_   = sym(B_k);
    float* qhi  = sym(B_qhi);  float* klo  = sym(B_klo);  float* khi  = sym(B_khi);
    float* v_   = sym(B_v);    float* A_   = sym(B_A);
    float* gate = sym(B_gate); float* accb = sym(B_acc);
    float* memF = sym(B_memF); float* memV = sym(B_memV); float* memQ = sym(B_memQ);
    float* gam  = sym(B_gam);  float* bg   = sym(B_bg);   float* wkT  = sym(B_wkT);
    float* qk2  = sym(B_qk2);  float* lq   = sym(B_lq);   float* mems = sym(B_mems);
    float* memY = sym(B_memY); float* x1   = sym(B_x1);   float* x2n  = sym(B_x2n);
    float* h1   = sym(B_h1);   float* part = sym(B_part); float* partF= sym(B_partF);

    __half* xn2  = symh(C_xn2);  __half* q2   = symh(C_q2);
    __half* y2   = symh(C_y2);   __half* memQ2= symh(C_memQ2);
    __half* memY2= symh(C_memY2);__half* x2n2 = symh(C_x2n2);
    __half* h22  = symh(C_h22);
    __half* aq2  = symh(W_aq2);  __half* ak2  = symh(W_ak2);
    __half* av2  = symh(W_av2);  __half* ao2  = symh(W_ao2);
    __half* ar2  = symh(W_ar2);  __half* mv2  = symh(W_mv2);
    __half* mq2  = symh(W_mq2);  __half* mr2  = symh(W_mr2);
    __half* wk2  = symh(W_wk2);  __half* mo2  = symh(W_mo2);
    __half* f12  = symh(W_f12);  __half* f22  = symh(W_f22);
    __half* fo2  = symh(W_fo2);

    cudaFuncSetAttribute(gemm_h16<EPI_NONE>,      cudaFuncAttributeMaxDynamicSharedMemorySize, GB_SMEM);
    cudaFuncSetAttribute(gemm_h16<EPI_GATE>,      cudaFuncAttributeMaxDynamicSharedMemorySize, GB_SMEM);
    cudaFuncSetAttribute(gemm_h16<EPI_GATE_ADD2>, cudaFuncAttributeMaxDynamicSharedMemorySize, GB_SMEM);
    cudaFuncSetAttribute(gemm_h16<EPI_ADD>,       cudaFuncAttributeMaxDynamicSharedMemorySize, GB_SMEM);
    cudaFuncSetAttribute(mem_readout2, cudaFuncAttributeMaxDynamicSharedMemorySize, MN * MD * 4);

    const dim3 blk256(256);
#define GB(EPI_, gx, gy, Aa, Bb, Dd, Gg, Rr1, Rr2, Mm, Nn, Kpk, Kpl)                            \
    gemm_h16<EPI_><<<dim3(gx, gy, 1), blk256, GB_SMEM>>>(Aa, Bb, Dd, Gg, Rr1, Rr2, Mm, Nn, Kpk, Kpk, Kpl)
#define GBSK4(Aa, Bb, Dd, Kpk, Kpl)                                                              \
    do {                                                                                         \
        gemm_h16<EPI_NONE><<<dim3(2, 16, 4), blk256, GB_SMEM>>>(                                 \
            Aa, Bb, part, nullptr, nullptr, nullptr, T, QD, Kpk, (Kpk) / 4, Kpl);                \
        redk<<<T * QD / 1024, blk256>>>(part, Dd, T * QD / 4);                                   \
    } while (0)

    // -------- launch order: #5 (0-based) = grid-256 v gemm for ncu -s 5 ----
    transpose256<<<MD, MD>>>(mem_k, wkT);                                   // 0
    cvt_weights_all<<<CVTW_BLOCKS, blk256>>>(                               // 1
        attn_q, attn_k, attn_v, attn_o, attn_r, mem_v, mem_q, mem_r, wkT, mem_o,
        ff_in1, ff_in2, ff_out,
        aq2, ak2, av2, ao2, ar2, mv2, mq2, mr2, wk2, mo2, f12, f22, fo2);
    scale_norm_split<<<T, blk256>>>(xs, xn, xn2, sn1);                      // 2
    gemm_h16<EPI_NONE><<<dim3(2, 16, 4), blk256, GB_SMEM>>>(                // 3: q proj 2-term split-K
        xn2, aq2, part, nullptr, nullptr, nullptr, T, QD, 2 * XD, 2 * XD / 4, XD);
    redk<<<T * QD / 1024, blk256>>>(part, q_, T * QD / 4);                  // 4
    GB(EPI_NONE, 16, 16, xn2, av2, v_, nullptr, nullptr, nullptr, T, XD, 2 * XD, XD);  // 5: v 2-term, PROFILED
    cvtA_t<QD / 4><<<T * QD / 1024, blk256>>>(q_, q2);
    GBSK4(q2, ak2, k_, 3 * QD, QD);                                          // k: 3-term (tiny)
    GB(EPI_NONE, 16, 16, xn2, ar2, gate, nullptr, nullptr, nullptr, T, XD, XD, XD);   // gate: 1-term
    // attention core
    rope_all<<<T, 128>>>(q_, k_, qhi, klo, khi);
    attn_score<<<T / 8, blk256>>>(qhi, klo, khi, A_);
    attn_av<<<dim3(8, 4, 32), blk256>>>(A_, v_, y2);
    GB(EPI_GATE, 16, 16, y2, ao2, accb, gate, nullptr, nullptr, T, XD, 2 * XD, XD);   // ao: 2-term
    // mem projections + gate
    gemm_tn<EPI_SIGMOID><<<dim3(1, 16), blk256>>>(xn, mem_f, memF, nullptr, nullptr, nullptr, T, MN, XD);
    GBSK4(xn2, mv2, memV, 2 * XD, XD);                                       // mv: 2-term
    GBSK4(xn2, mq2, memQ, 2 * XD, XD);                                       // mq: 2-term
    GB(EPI_NONE, 16, 16, xn2, mr2, gate, nullptr, nullptr, nullptr, T, XD, XD, XD);   // gate: 1-term
    // scan
    mem_prep<<<MN, MD>>>(mem_beta, mem_dec, gam, bg);
    mem_scan<<<MN, MD>>>(memF, memV, gam, bg, mems);
    // readout
    cvtA_t<MD / 4><<<T * MD / 1024, blk256>>>(memQ, memQ2);
    GBSK4(memQ2, wk2, qk2, 3 * MD, MD);                                      // wk: 3-term (tiny)
    gemm_tn<EPI_NONE><<<dim3(1, 16), blk256>>>(memQ, mem_l, lq, nullptr, nullptr, nullptr, T, MN, MD);
    mem_readout2<<<T, blk256, MN * MD * 4>>>(mems, qk2, lq, memY);
    // x1 = (memY @ mem_o^T)*sigmoid(gate) + attn_out + xs
    cvtA_t<MD / 4><<<T * MD / 1024, blk256>>>(memY, memY2);
    GB(EPI_GATE_ADD2, 16, 16, memY2, mo2, x1, gate, accb, xs, T, XD, 2 * MD, MD);     // mo: 2-term
    // FF block: f1/f2 1-term with split-K x2; fo 1-term
    scale_norm_split<<<T, blk256>>>(x1, x2n, x2n2, sn2);
    gemm_h16<EPI_NONE><<<dim3(22, 16, 2), blk256, GB_SMEM>>>(
        x2n2, f12, partF, nullptr, nullptr, nullptr, T, FFD, XD, XD / 2, XD);
    redk2<<<T * FFD / 1024, blk256>>>(partF, h1, T * FFD / 4);
    gemm_h16<EPI_NONE><<<dim3(22, 16, 2), blk256, GB_SMEM>>>(
        x2n2, f22, partF, nullptr, nullptr, nullptr, T, FFD, XD, XD / 2, XD);
    red2_silu_split<<<T * FFD / 1024, blk256>>>(partF, h1, h22);
    GB(EPI_ADD, 16, 16, h22, fo2, out, nullptr, x1, nullptr, T, XD, FFD, FFD);        // fo: 1-term
#undef GB
#undef GBSK4
}

// round 16
// speedup vs baseline: 3.7854x; 1.1044x over previous
#include <cuda_runtime.h>
#include <cuda_fp16.h>
#include <math.h>
#include <stdint.h>

// ---------------- problem dims ----------------
#define T    2048
#define XD   2048
#define QD   256
#define MN   64
#define MD   256
#define DCD  64
#define FFD  2816
#define CH   64

// ---------------- fp32 scratch ----------------
__device__ float B_xn  [(size_t)T*XD];
__device__ float B_q   [(size_t)T*QD];
__device__ float B_k   [(size_t)T*QD];
__device__ float B_qhi [(size_t)T*QD];
__device__ float B_klo [(size_t)T*QD];
__device__ float B_khi [(size_t)T*QD];
__device__ float B_v   [(size_t)T*XD];
__device__ float B_A   [(size_t)T*2*CH];
__device__ float B_gate[(size_t)T*XD];
__device__ float B_acc [(size_t)T*XD];
__device__ float B_memF[(size_t)T*MN];
__device__ float B_memV[(size_t)T*MD];
__device__ float B_memQ[(size_t)T*MD];
__device__ float B_gam [(size_t)MN*MD];
__device__ float B_bg  [(size_t)MN*MD];
__device__ float B_wkT [(size_t)MD*MD];
__device__ float B_qk2 [(size_t)T*MD];
__device__ float B_lq  [(size_t)T*MN];
__device__ float B_memY[(size_t)T*MD];
__device__ float B_x1  [(size_t)T*XD];
__device__ float B_x2n [(size_t)T*XD];
__device__ float B_h1  [(size_t)T*FFD];
__device__ float B_part[(size_t)4*T*MD];    // split-K x4 partials (N=256 GEMMs)
__device__ float B_partF[(size_t)2*T*FFD];  // split-K x2 partials (FF GEMMs)

// mems in fp16 storage (recurrence accumulates fp32; storage rounds only)
__device__ __half H_mems[(size_t)T*MN*MD];  // 67 MB

// ---------------- fp16 2-plane scratch: row = [hi(K) | lo(K)] ----------------
__device__ __half C_xn2  [(size_t)T*2*XD];
__device__ __half C_q2   [(size_t)T*2*QD];
__device__ __half C_y2   [(size_t)T*2*XD];
__device__ __half C_memQ2[(size_t)T*2*MD];
__device__ __half C_memY2[(size_t)T*2*MD];
__device__ __half C_x2n2 [(size_t)T*2*XD];
__device__ __half C_h22  [(size_t)T*2*FFD];
__device__ __half W_aq2  [(size_t)QD*2*XD];
__device__ __half W_ak2  [(size_t)QD*2*QD];
__device__ __half W_av2  [(size_t)XD*2*XD];
__device__ __half W_ao2  [(size_t)XD*2*XD];
__device__ __half W_ar2  [(size_t)XD*2*XD];
__device__ __half W_mv2  [(size_t)MD*2*XD];
__device__ __half W_mq2  [(size_t)MD*2*XD];
__device__ __half W_mr2  [(size_t)XD*2*XD];
__device__ __half W_wk2  [(size_t)MD*2*MD];
__device__ __half W_mo2  [(size_t)XD*2*MD];
__device__ __half W_f12  [(size_t)FFD*2*XD];
__device__ __half W_f22  [(size_t)FFD*2*XD];
__device__ __half W_fo2  [(size_t)XD*2*FFD];

__device__ __forceinline__ float sigf(float x) { return 1.f / (1.f + expf(-x)); }

enum { EPI_NONE = 0, EPI_SIGMOID, EPI_GATE, EPI_GATE_ADD2, EPI_ADD };

// fp16 hi/lo split: hi = f16x2(v0,v1) (v0 low), lo = f16x2 of residuals
__device__ __forceinline__ void split2h(float v0, float v1, uint32_t& hi, uint32_t& lo)
{
    asm("cvt.rn.f16x2.f32 %0, %1, %2;" : "=r"(hi) : "f"(v1), "f"(v0));
    __half2 hh = *(__half2*)&hi;
    float h0 = __half2float(__low2half(hh));
    float h1 = __half2float(__high2half(hh));
    asm("cvt.rn.f16x2.f32 %0, %1, %2;" : "=r"(lo) : "f"(v1 - h1), "f"(v0 - h0));
}

// ---------------- split conversion: 4 elems/thread -> 2-plane row [hi|lo] ----------------
template <int KQ>
__device__ __forceinline__ void cvt_one(const float* __restrict__ src,
                                        __half* __restrict__ dst, int b, int tid)
{
    int idx4 = b * 256 + tid;
    int row = idx4 / KQ;
    int cq  = idx4 - row * KQ;
    const int K = KQ * 4;
    float4 v = ((const float4*)src)[idx4];
    uint32_t h0, l0, h1, l1;
    split2h(v.x, v.y, h0, l0);
    split2h(v.z, v.w, h1, l1);
    __half* dr = dst + (size_t)row * 2 * K + cq * 4;
    *(uint2*)dr       = make_uint2(h0, h1);
    *(uint2*)(dr + K) = make_uint2(l0, l1);
}

// one launch converts all 13 weight matrices (shapes compile-time)
__global__ __launch_bounds__(256) void cvt_weights_all(
    const float* aq, const float* ak, const float* av, const float* ao, const float* ar,
    const float* mv, const float* mq, const float* mr, const float* wk, const float* mo,
    const float* f1, const float* f2, const float* fo,
    __half* aq2, __half* ak2, __half* av2, __half* ao2,
    __half* ar2, __half* mv2, __half* mq2, __half* mr2,
    __half* wk2, __half* mo2, __half* f12, __half* f22,
    __half* fo2)
{
    int b = blockIdx.x, tid = threadIdx.x;
    if (b < 512)  { cvt_one<512>(aq, aq2, b, tid); return; }  b -= 512;   // 256x2048
    if (b < 64)   { cvt_one<64 >(ak, ak2, b, tid); return; }  b -= 64;    // 256x256
    if (b < 4096) { cvt_one<512>(av, av2, b, tid); return; }  b -= 4096;  // 2048x2048
    if (b < 4096) { cvt_one<512>(ao, ao2, b, tid); return; }  b -= 4096;
    if (b < 4096) { cvt_one<512>(ar, ar2, b, tid); return; }  b -= 4096;
    if (b < 512)  { cvt_one<512>(mv, mv2, b, tid); return; }  b -= 512;
    if (b < 512)  { cvt_one<512>(mq, mq2, b, tid); return; }  b -= 512;
    if (b < 4096) { cvt_one<512>(mr, mr2, b, tid); return; }  b -= 4096;
    if (b < 64)   { cvt_one<64 >(wk, wk2, b, tid); return; }  b -= 64;
    if (b < 512)  { cvt_one<64 >(mo, mo2, b, tid); return; }  b -= 512;   // 2048x256
    if (b < 5632) { cvt_one<512>(f1, f12, b, tid); return; }  b -= 5632;  // 2816x2048
    if (b < 5632) { cvt_one<512>(f2, f22, b, tid); return; }  b -= 5632;
    cvt_one<704>(fo, fo2, b, tid);                                        // 2048x2816
}
#define CVTW_BLOCKS 35456

template <int KQ>
__global__ __launch_bounds__(256) void cvtA_t(const float* __restrict__ src,
                                              __half* __restrict__ dst)
{
    cvt_one<KQ>(src, dst, blockIdx.x, threadIdx.x);
}

// ---------------- split-K reduces ----------------
__global__ __launch_bounds__(256) void redk(const float* __restrict__ p,
                                            float* __restrict__ o, int n4)
{
    int i = blockIdx.x * 256 + threadIdx.x;
    const float4* p4 = (const float4*)p;
    float4 a = p4[i], b = p4[i + n4], c = p4[i + 2 * n4], d = p4[i + 3 * n4];
    ((float4*)o)[i] = make_float4(a.x + b.x + c.x + d.x, a.y + b.y + c.y + d.y,
                                  a.z + b.z + c.z + d.z, a.w + b.w + c.w + d.w);
}

__global__ __launch_bounds__(256) void redk2(const float* __restrict__ p,
                                             float* __restrict__ o, int n4)
{
    int i = blockIdx.x * 256 + threadIdx.x;
    const float4* p4 = (const float4*)p;
    float4 a = p4[i], b = p4[i + n4];
    ((float4*)o)[i] = make_float4(a.x + b.x, a.y + b.y, a.z + b.z, a.w + b.w);
}

// reduce 2 planes + silu gate + 2-plane fp16 split (for FF h2)
__global__ __launch_bounds__(256) void red2_silu_split(
    const float* __restrict__ p, const float* __restrict__ h1,
    __half* __restrict__ o2)
{
    int idx4 = blockIdx.x * 256 + threadIdx.x;
    const int KQ = FFD / 4;
    int row = idx4 / KQ;
    int cq  = idx4 - row * KQ;
    const float4* p4 = (const float4*)p;
    float4 a = p4[idx4], b = p4[idx4 + (size_t)T * FFD / 4];
    float4 g = ((const float4*)h1)[idx4];
    float c0 = (a.x + b.x) * (g.x * sigf(g.x));
    float c1 = (a.y + b.y) * (g.y * sigf(g.y));
    float c2 = (a.z + b.z) * (g.z * sigf(g.z));
    float c3 = (a.w + b.w) * (g.w * sigf(g.w));
    uint32_t h0, l0, h1b, l1;
    split2h(c0, c1, h0, l0);
    split2h(c2, c3, h1b, l1);
    __half* dr = o2 + (size_t)row * 2 * FFD + cq * 4;
    *(uint2*)dr         = make_uint2(h0, h1b);
    *(uint2*)(dr + FFD) = make_uint2(l0, l1);
}

// =====================================================================
//  fp16 mma.sync GEMM over 2-plane [hi|lo] operands.
//  Segment pairs per K-chunk: 0:(hi,hi) 1:(lo,hi) 2:(hi,lo)
//  Kpack = Kplane (1-term) / 2*Kplane (2-term) / 3*Kplane (full compensation)
//  tile 128x128, BK=64, 3-stage cp.async, one barrier per K-iter; split-K by z.
// =====================================================================
#define SWZ(off) ((off) ^ (((off) >> 3) & 0x70))
#define TILE_B   16384
#define STAGE_B  (2 * TILE_B)
#define GB_SMEM  (3 * STAGE_B)   // 96 KB

template <int EPI>
__device__ __forceinline__ float epi_apply(float c, size_t idx,
                                           const float* __restrict__ G,
                                           const float* __restrict__ R1,
                                           const float* __restrict__ R2)
{
    if (EPI == EPI_SIGMOID)        c = sigf(c);
    else if (EPI == EPI_GATE)      c = c * sigf(G[idx]);
    else if (EPI == EPI_GATE_ADD2) c = c * sigf(G[idx]) + R1[idx] + R2[idx];
    else if (EPI == EPI_ADD)       c = c + R1[idx];
    return c;
}

__device__ __forceinline__ void mma16(float* c, uint32_t a0, uint32_t a1, uint32_t a2, uint32_t a3,
                                      uint32_t b0, uint32_t b1)
{
    asm volatile(
        "mma.sync.aligned.m16n8k16.row.col.f32.f16.f16.f32 "
        "{%0,%1,%2,%3}, {%4,%5,%6,%7}, {%8,%9}, {%0,%1,%2,%3};"
        : "+f"(c[0]), "+f"(c[1]), "+f"(c[2]), "+f"(c[3])
        : "r"(a0), "r"(a1), "r"(a2), "r"(a3), "r"(b0), "r"(b1));
}

__device__ __forceinline__ void ldsm4(uint32_t addr, uint32_t& r0, uint32_t& r1,
                                      uint32_t& r2, uint32_t& r3)
{
    asm volatile("ldmatrix.sync.aligned.m8n8.x4.shared.b16 {%0,%1,%2,%3}, [%4];"
                 : "=r"(r0), "=r"(r1), "=r"(r2), "=r"(r3) : "r"(addr));
}

template <int EPI>
__global__ __launch_bounds__(256, 2) void gemm_h16(
    const __half* __restrict__ A, const __half* __restrict__ B,
    float* __restrict__ D,
    const float* __restrict__ G, const float* __restrict__ R1, const float* __restrict__ R2,
    int M, int N, int Kpack, int Kchunk, int Kplane)
{
    extern __shared__ __half smem[];

    const int tid  = threadIdx.x;
    const int wid  = tid >> 5, lane = tid & 31;
    const int wm   = wid & 1, wn = wid >> 1;
    const int g    = lane >> 2, tg = lane & 3;
    const int m0   = blockIdx.y * 128;
    const int n0   = blockIdx.x * 128;
    const int z    = blockIdx.z;

    D += (size_t)z * M * N;

    float acc[4][4][4];
#pragma unroll
    for (int mt = 0; mt < 4; mt++)
#pragma unroll
        for (int nt = 0; nt < 4; nt++)
#pragma unroll
            for (int e = 0; e < 4; e++) acc[mt][nt][e] = 0.f;

    const int KT  = Kchunk >> 6;
    const int KT1 = Kplane >> 6;
    const int zKT = z * KT;
    const int rowStride = 2 * Kplane;

    uint32_t base;
    asm("{ .reg .u64 t; cvta.to.shared.u64 t, %1; cvt.u32.u64 %0, t; }" : "=r"(base) : "l"(smem));

    uint32_t swOff[4];
    const __half* aG[4];
    const __half* bG[4];
#pragma unroll
    for (int l = 0; l < 4; l++) {
        int idx = tid + l * 256;
        int r = idx >> 3, c = idx & 7;
        uint32_t off = r * 128 + c * 16;
        swOff[l] = SWZ(off);
        aG[l] = A + (size_t)(m0 + r) * rowStride + c * 8;
        bG[l] = B + (size_t)(n0 + r) * rowStride + c * 8;
    }

    const int lmRow = ((lane >> 3) & 1) * 8 + (lane & 7);
    const int lmCB  = ((lane >> 4) & 1) * 16;

    // per-chunk plane mapping: seg 0:(hi,hi) 1:(lo,hi) 2:(hi,lo)
#define LOADG(buf, kt)                                                                     \
    {                                                                                      \
        int ktg_ = zKT + (kt);                                                             \
        int s_ = (ktg_ >= KT1) + (ktg_ >= 2 * KT1);                                        \
        int rr_ = ktg_ - s_ * KT1;                                                         \
        size_t aO_ = (size_t)(((s_ == 1) ? KT1 : 0) + rr_) * 64;                           \
        size_t bO_ = (size_t)(((s_ == 2) ? KT1 : 0) + rr_) * 64;                           \
        uint32_t aB_ = base + (buf) * STAGE_B;                                             \
        uint32_t bB_ = aB_ + TILE_B;                                                       \
        _Pragma("unroll")                                                                  \
        for (int l = 0; l < 4; l++) {                                                      \
            asm volatile("cp.async.ca.shared.global [%0], [%1], 16;"                       \
                         :: "r"(aB_ + swOff[l]), "l"(aG[l] + aO_));                        \
            asm volatile("cp.async.ca.shared.global [%0], [%1], 16;"                       \
                         :: "r"(bB_ + swOff[l]), "l"(bG[l] + bO_));                        \
        }                                                                                  \
    }

    LOADG(0, 0);
    asm volatile("cp.async.commit_group;");
    if (KT > 1) LOADG(1, 1);
    asm volatile("cp.async.commit_group;");

    int buf = 0;
    for (int kt = 0; kt < KT; kt++) {
        asm volatile("cp.async.wait_group 1;");
        __syncthreads();

        if (kt + 2 < KT) {
            int nb = buf + 2; if (nb >= 3) nb -= 3;
            LOADG(nb, kt + 2);
        }
        asm volatile("cp.async.commit_group;");

        const uint32_t aBuf = base + buf * STAGE_B;
        const uint32_t bBuf = aBuf + TILE_B;

#pragma unroll
        for (int ks = 0; ks < 4; ks++) {
            const int kbB = ks * 32;
            uint32_t bf[4][2];
#pragma unroll
            for (int h = 0; h < 2; h++) {
                uint32_t off = (uint32_t)(wn * 32 + h * 16 + lmRow) * 128 + kbB + lmCB;
                ldsm4(bBuf + SWZ(off), bf[2 * h][0], bf[2 * h + 1][0], bf[2 * h][1], bf[2 * h + 1][1]);
            }
            uint32_t af[4][4];
#pragma unroll
            for (int mt = 0; mt < 4; mt++) {
                uint32_t off = (uint32_t)(wm * 64 + mt * 16 + lmRow) * 128 + kbB + lmCB;
                ldsm4(aBuf + SWZ(off), af[mt][0], af[mt][1], af[mt][2], af[mt][3]);
            }
#pragma unroll
            for (int mt = 0; mt < 4; mt++)
#pragma unroll
                for (int nt = 0; nt < 4; nt++)
                    mma16(acc[mt][nt], af[mt][0], af[mt][1], af[mt][2], af[mt][3],
                          bf[nt][0], bf[nt][1]);
        }
        if (++buf >= 3) buf = 0;
    }
#undef LOADG

#pragma unroll
    for (int mt = 0; mt < 4; mt++) {
        int r0 = m0 + wm * 64 + mt * 16 + g;
#pragma unroll
        for (int nt = 0; nt < 4; nt++) {
            int col = n0 + wn * 32 + nt * 8 + tg * 2;
            size_t i0 = (size_t)r0 * N + col;
            size_t i1 = i0 + (size_t)8 * N;
            float2 o0, o1;
            o0.x = epi_apply<EPI>(acc[mt][nt][0], i0,     G, R1, R2);
            o0.y = epi_apply<EPI>(acc[mt][nt][1], i0 + 1, G, R1, R2);
            o1.x = epi_apply<EPI>(acc[mt][nt][2], i1,     G, R1, R2);
            o1.y = epi_apply<EPI>(acc[mt][nt][3], i1 + 1, G, R1, R2);
            *(float2*)&D[i0] = o0;
            *(float2*)&D[i1] = o1;
        }
    }
}

// ---------------- legacy FFMA GEMM (tiny-N cases: N=64) ----------------
#define BM 128
#define BN 128
#define BKK 16

template <int EPI>
__global__ __launch_bounds__(256) void gemm_tn(
    const float* __restrict__ A, const float* __restrict__ B, float* __restrict__ D,
    const float* __restrict__ G, const float* __restrict__ R1, const float* __restrict__ R2,
    int M, int N, int K)
{
    __shared__ float As[BKK][BM + 4];
    __shared__ float Bs[BKK][BN + 4];

    const int tid = threadIdx.x;
    const int m0 = blockIdx.y * BM;
    const int n0 = blockIdx.x * BN;
    const int tx = tid & 15;
    const int ty = tid >> 4;

    float acc[8][8];
#pragma unroll
    for (int i = 0; i < 8; i++)
#pragma unroll
        for (int j = 0; j < 8; j++) acc[i][j] = 0.f;

    for (int k0 = 0; k0 < K; k0 += BKK) {
#pragma unroll
        for (int l = 0; l < 2; l++) {
            int qi  = tid + l * 256;
            int row = qi >> 2;
            int kk  = (qi & 3) * 4;
            float4 av = *(const float4*)&A[(size_t)(m0 + row) * K + k0 + kk];
            As[kk + 0][row] = av.x; As[kk + 1][row] = av.y;
            As[kk + 2][row] = av.z; As[kk + 3][row] = av.w;
        }
#pragma unroll
        for (int l = 0; l < 2; l++) {
            int qi  = tid + l * 256;
            int row = qi >> 2;
            int kk  = (qi & 3) * 4;
            float4 bv = make_float4(0.f, 0.f, 0.f, 0.f);
            if (n0 + row < N) bv = *(const float4*)&B[(size_t)(n0 + row) * K + k0 + kk];
            Bs[kk + 0][row] = bv.x; Bs[kk + 1][row] = bv.y;
            Bs[kk + 2][row] = bv.z; Bs[kk + 3][row] = bv.w;
        }
        __syncthreads();

#pragma unroll
        for (int kk = 0; kk < BKK; kk++) {
            float a[8], b[8];
#pragma unroll
            for (int i = 0; i < 8; i++) a[i] = As[kk][ty * 8 + i];
#pragma unroll
            for (int j = 0; j < 8; j++) b[j] = Bs[kk][tx * 8 + j];
#pragma unroll
            for (int i = 0; i < 8; i++)
#pragma unroll
                for (int j = 0; j < 8; j++) acc[i][j] += a[i] * b[j];
        }
        __syncthreads();
    }

#pragma unroll
    for (int i = 0; i < 8; i++) {
        int row = m0 + ty * 8 + i;
#pragma unroll
        for (int j = 0; j < 8; j++) {
            int col = n0 + tx * 8 + j;
            if (col < N) {
                size_t idx = (size_t)row * N + col;
                D[idx] = epi_apply<EPI>(acc[i][j], idx, G, R1, R2);
            }
        }
    }
}

// ---------------- scale_norm with fused 2-plane split ----------------
__global__ __launch_bounds__(256) void scale_norm_split(
    const float* __restrict__ x, float* __restrict__ o,
    __half* __restrict__ o2, const float* __restrict__ g)
{
    int t = blockIdx.x;
    const float4* xr = (const float4*)(x + (size_t)t * XD);
    float4 v0 = xr[threadIdx.x];
    float4 v1 = xr[threadIdx.x + 256];
    float s = v0.x*v0.x + v0.y*v0.y + v0.z*v0.z + v0.w*v0.w
            + v1.x*v1.x + v1.y*v1.y + v1.z*v1.z + v1.w*v1.w;
    for (int off = 16; off; off >>= 1) s += __shfl_xor_sync(0xffffffffu, s, off);
    __shared__ float red[8];
    int w = threadIdx.x >> 5, lane = threadIdx.x & 31;
    if (lane == 0) red[w] = s;
    __syncthreads();
    float tot = red[0] + red[1] + red[2] + red[3] + red[4] + red[5] + red[6] + red[7];
    float sc = g[0] / (sqrtf(tot) + 1e-8f);
    v0.x *= sc; v0.y *= sc; v0.z *= sc; v0.w *= sc;
    v1.x *= sc; v1.y *= sc; v1.z *= sc; v1.w *= sc;
    float4* orow = (float4*)(o + (size_t)t * XD);
    orow[threadIdx.x] = v0;
    orow[threadIdx.x + 256] = v1;
    __half* r2 = o2 + (size_t)t * 2 * XD;
    uint32_t h, l;
    int c0 = threadIdx.x * 4;
    split2h(v0.x, v0.y, h, l);
    *(uint32_t*)(r2 + c0) = h; *(uint32_t*)(r2 + XD + c0) = l;
    split2h(v0.z, v0.w, h, l);
    *(uint32_t*)(r2 + c0 + 2) = h; *(uint32_t*)(r2 + XD + c0 + 2) = l;
    int c1 = c0 + 1024;
    split2h(v1.x, v1.y, h, l);
    *(uint32_t*)(r2 + c1) = h; *(uint32_t*)(r2 + XD + c1) = l;
    split2h(v1.z, v1.w, h, l);
    *(uint32_t*)(r2 + c1 + 2) = h; *(uint32_t*)(r2 + XD + c1 + 2) = l;
}

// ---------------- RoPE ----------------
__global__ __launch_bounds__(128) void rope_all(
    const float* __restrict__ q, const float* __restrict__ k,
    float* __restrict__ qhi, float* __restrict__ klo, float* __restrict__ khi)
{
    int t = blockIdx.x, j = threadIdx.x;
    int r = t & 63;
    float freq = powf(10000.f, -(float)j / 128.f);
    float slo, clo, shi, chi;
    sincosf((float)r * freq, &slo, &clo);
    sincosf((float)(64 + r) * freq, &shi, &chi);
    size_t base = (size_t)t * QD + 2 * j;
    float qe = q[base], qo = q[base + 1];
    qhi[base]     = qe * chi - qo * shi;
    qhi[base + 1] = qo * chi + qe * shi;
    float ke = k[base], ko = k[base + 1];
    klo[base]     = ke * clo - ko * slo;
    klo[base + 1] = ko * clo + ke * slo;
    khi[base]     = ke * chi - ko * shi;
    khi[base + 1] = ko * chi + ke * shi;
}

// ---------------- attention scores + softmax ----------------
__global__ __launch_bounds__(256) void attn_score(
    const float* __restrict__ qr, const float* __restrict__ klo,
    const float* __restrict__ khi, float* __restrict__ Aout)
{
    int w = threadIdx.x >> 5, lane = threadIdx.x & 31;
    int t = blockIdx.x * 8 + w;
    int c = t >> 6, r = t & 63;
    float qreg[8];
#pragma unroll
    for (int i = 0; i < 8; i++) qreg[i] = qr[(size_t)t * QD + i * 32 + lane];

    __shared__ float s_s[8][128];
    for (int m = 0; m < 128; m++) {
        float sc;
        if (c == 0 && m < 64) {
            sc = 0.f;
        } else {
            const float* kp = (m < 64)
                ? &klo[(size_t)((c - 1) * 64 + m) * QD]
                : &khi[(size_t)(c * 64 + (m - 64)) * QD];
            float d = 0.f;
#pragma unroll
            for (int i = 0; i < 8; i++) d += qreg[i] * kp[i * 32 + lane];
            for (int off = 16; off; off >>= 1) d += __shfl_xor_sync(0xffffffffu, d, off);
            sc = d * (1.f / 16.f);
        }
        if (m > r + 64) sc = -1e30f;
        if (lane == 0) s_s[w][m] = sc;
    }
    __syncwarp();
    float a0 = s_s[w][lane], a1 = s_s[w][lane + 32], a2 = s_s[w][lane + 64], a3 = s_s[w][lane + 96];
    float mx = fmaxf(fmaxf(a0, a1), fmaxf(a2, a3));
    for (int off = 16; off; off >>= 1) mx = fmaxf(mx, __shfl_xor_sync(0xffffffffu, mx, off));
    float e0 = expf(a0 - mx), e1 = expf(a1 - mx), e2 = expf(a2 - mx), e3 = expf(a3 - mx);
    float sm = e0 + e1 + e2 + e3;
    for (int off = 16; off; off >>= 1) sm += __shfl_xor_sync(0xffffffffu, sm, off);
    float inv = 1.f / sm;
    size_t ob = (size_t)t * 128;
    Aout[ob + lane]      = e0 * inv;
    Aout[ob + lane + 32] = e1 * inv;
    Aout[ob + lane + 64] = e2 * inv;
    Aout[ob + lane + 96] = e3 * inv;
}

// ---------------- y = A @ v2, fused 2-plane split into y2 ----------------
__global__ __launch_bounds__(256) void attn_av(
    const float* __restrict__ Aat, const float* __restrict__ v,
    __half* __restrict__ y2)
{
    int c = blockIdx.z, rg = blockIdx.y, ct = blockIdx.x;
    int col = ct * 256 + threadIdx.x;
    __shared__ float As[16][128];
    for (int idx = threadIdx.x; idx < 16 * 128; idx += 256) {
        int rr = idx >> 7, mm = idx & 127;
        As[rr][mm] = Aat[(size_t)(c * 64 + rg * 16 + rr) * 128 + mm];
    }
    __syncthreads();
    float acc[16];
#pragma unroll
    for (int r = 0; r < 16; r++) acc[r] = 0.f;
    int mstart = (c == 0) ? 64 : 0;
    for (int m = mstart; m < 128; m++) {
        float vv = v[(size_t)((c - 1) * 64 + m) * XD + col];
#pragma unroll
        for (int r = 0; r < 16; r++) acc[r] += As[r][m] * vv;
    }
#pragma unroll
    for (int r = 0; r < 16; r++) {
        float val = acc[r];
        __half hb = __float2half_rn(val);
        __half lb = __float2half_rn(val - __half2float(hb));
        __half* yr = y2 + (size_t)(c * 64 + rg * 16 + r) * 2 * XD;
        yr[col] = hb; yr[XD + col] = lb;
    }
}

// ---------------- mem prep ----------------
__global__ void mem_prep(const float* __restrict__ beta, const float* __restrict__ decay,
                         float* __restrict__ gam, float* __restrict__ bg)
{
    int n = blockIdx.x, d = threadIdx.x;
    float g = (d < MD - DCD) ? 1.f : sigf(decay[n * DCD + (d - (MD - DCD))]);
    gam[n * MD + d] = g;
    bg[n * MD + d] = g * sigf(beta[n * MD + d]);
}

// ---------------- mem scan (fp32 recurrence, fp16 storage) ----------------
__global__ __launch_bounds__(256) void mem_scan(
    const float* __restrict__ F, const float* __restrict__ V,
    const float* __restrict__ gam, const float* __restrict__ bg,
    __half* __restrict__ mems)
{
    int n = blockIdx.x, d = threadIdx.x;
    float ga = gam[n * MD + d], b = bg[n * MD + d];
    float m = 0.f;
    float fn = F[n], vn = V[d];
    for (int t = 0; t < T; t++) {
        float f = fn, vv = vn;
        if (t + 1 < T) { fn = F[(t + 1) * MN + n]; vn = V[(size_t)(t + 1) * MD + d]; }
        m = (ga - f * b) * m + f * vv;
        mems[((size_t)t * MN + n) * MD + d] = __float2half_rn(m);
    }
}

// ---------------- transpose 256x256 ----------------
__global__ void transpose256(const float* __restrict__ W, float* __restrict__ WT)
{
    int rk = blockIdx.x, cd = threadIdx.x;
    WT[cd * MD + rk] = W[rk * MD + cd];
}

// ---------------- mem readout (fp16 mems, smem-staged as fp32) ----------------
__global__ __launch_bounds__(256) void mem_readout2(
    const __half* __restrict__ mems, const float* __restrict__ qk2,
    const float* __restrict__ lq, float* __restrict__ yout)
{
    extern __shared__ float ms[];
    __shared__ float qs[MD];
    __shared__ float as[MN];
    int t = blockIdx.x;
    int tid = threadIdx.x, w = tid >> 5, lane = tid & 31;
    qs[tid] = qk2[(size_t)t * MD + tid];
    const __half2* mb2 = (const __half2*)(mems + (size_t)t * MN * MD);
#pragma unroll
    for (int i = 0; i < 32; i++) {
        __half2 hv = mb2[tid + i * 256];
        ((float2*)ms)[tid + i * 256] = __half22float2(hv);
    }
    __syncthreads();
#pragma unroll
    for (int mi = 0; mi < 8; mi++) {
        int m = w * 8 + mi;
        float d = 0.f;
#pragma unroll
        for (int i = 0; i < 8; i++) d += ms[m * MD + i * 32 + lane] * qs[i * 32 + lane];
        for (int off = 16; off; off >>= 1) d += __shfl_xor_sync(0xffffffffu, d, off);
        if (lane == 0) as[m] = (d + lq[t * MN + m]) * (1.f / 16.f);
    }
    __syncthreads();
    if (w == 0) {
        float a0 = as[lane], a1 = as[lane + 32];
        float mx = fmaxf(a0, a1);
        for (int off = 16; off; off >>= 1) mx = fmaxf(mx, __shfl_xor_sync(0xffffffffu, mx, off));
        float e0 = expf(a0 - mx), e1 = expf(a1 - mx);
        float sm = e0 + e1;
        for (int off = 16; off; off >>= 1) sm += __shfl_xor_sync(0xffffffffu, sm, off);
        float inv = 1.f / sm;
        as[lane] = e0 * inv;
        as[lane + 32] = e1 * inv;
    }
    __syncthreads();
    float acc = 0.f;
    for (int m = 0; m < MN; m++) acc += as[m] * ms[m * MD + tid];
    yout[(size_t)t * MD + tid] = acc;
}

// ---------------- launcher ----------------
static float* sym(const void* s) { void* p = nullptr; cudaGetSymbolAddress(&p, s); return (float*)p; }
static __half* symh(const void* s) { void* p = nullptr; cudaGetSymbolAddress(&p, s); return (__half*)p; }

extern "C" void kernel_launch(void* const* d_in, const int* in_sizes, int n_in,
                              void* d_out, int out_size)
{
    const float* xs      = (const float*)d_in[0];
    const float* attn_q  = (const float*)d_in[1];
    const float* attn_k  = (const float*)d_in[2];
    const float* attn_v  = (const float*)d_in[3];
    const float* attn_o  = (const float*)d_in[4];
    const float* attn_r  = (const float*)d_in[5];
    const float* mem_f   = (const float*)d_in[6];
    const float* mem_q   = (const float*)d_in[7];
    const float* mem_k   = (const float*)d_in[8];
    const float* mem_v   = (const float*)d_in[9];
    const float* mem_o   = (const float*)d_in[10];
    const float* mem_r   = (const float*)d_in[11];
    const float* mem_beta= (const float*)d_in[12];
    const float* mem_dec = (const float*)d_in[13];
    const float* mem_l   = (const float*)d_in[14];
    const float* ff_in1  = (const float*)d_in[15];
    const float* ff_in2  = (const float*)d_in[16];
    const float* ff_out  = (const float*)d_in[17];
    const float* sn1     = (const float*)d_in[18];
    const float* sn2     = (const float*)d_in[19];
    float* out = (float*)d_out;

    float* xn   = sym(B_xn);   float* q_   = sym(B_q);    float* k_   = sym(B_k);
    float* qhi  = sym(B_qhi);  float* klo  = sym(B_klo);  float* khi  = sym(B_khi);
    float* v_   = sym(B_v);    float* A_   = sym(B_A);
    float* gate = sym(B_gate); float* accb = sym(B_acc);
    float* memF = sym(B_memF); float* memV = sym(B_memV); float* memQ = sym(B_memQ);
    float* gam  = sym(B_gam);  float* bg   = sym(B_bg);   float* wkT  = sym(B_wkT);
    float* qk2  = sym(B_qk2);  float* lq   = sym(B_lq);
    float* memY = sym(B_memY); float* x1   = sym(B_x1);   float* x2n  = sym(B_x2n);
    float* h1   = sym(B_h1);   float* part = sym(B_part); float* partF= sym(B_partF);
    __half* mems = symh(H_mems);

    __half* xn2  = symh(C_xn2);  __half* q2   = symh(C_q2);
    __half* y2   = symh(C_y2);   __half* memQ2= symh(C_memQ2);
    __half* memY2= symh(C_memY2);__half* x2n2 = symh(C_x2n2);
    __half* h22  = symh(C_h22);
    __half* aq2  = symh(W_aq2);  __half* ak2  = symh(W_ak2);
    __half* av2  = symh(W_av2);  __half* ao2  = symh(W_ao2);
    __half* ar2  = symh(W_ar2);  __half* mv2  = symh(W_mv2);
    __half* mq2  = symh(W_mq2);  __half* mr2  = symh(W_mr2);
    __half* wk2  = symh(W_wk2);  __half* mo2  = symh(W_mo2);
    __half* f12  = symh(W_f12);  __half* f22  = symh(W_f22);
    __half* fo2  = symh(W_fo2);

    cudaFuncSetAttribute(gemm_h16<EPI_NONE>,      cudaFuncAttributeMaxDynamicSharedMemorySize, GB_SMEM);
    cudaFuncSetAttribute(gemm_h16<EPI_GATE>,      cudaFuncAttributeMaxDynamicSharedMemorySize, GB_SMEM);
    cudaFuncSetAttribute(gemm_h16<EPI_GATE_ADD2>, cudaFuncAttributeMaxDynamicSharedMemorySize, GB_SMEM);
    cudaFuncSetAttribute(gemm_h16<EPI_ADD>,       cudaFuncAttributeMaxDynamicSharedMemorySize, GB_SMEM);
    cudaFuncSetAttribute(mem_readout2, cudaFuncAttributeMaxDynamicSharedMemorySize, MN * MD * 4);

    const dim3 blk256(256);
#define GB(EPI_, gx, gy, Aa, Bb, Dd, Gg, Rr1, Rr2, Mm, Nn, Kpk, Kpl)                            \
    gemm_h16<EPI_><<<dim3(gx, gy, 1), blk256, GB_SMEM>>>(Aa, Bb, Dd, Gg, Rr1, Rr2, Mm, Nn, Kpk, Kpk, Kpl)
#define GBSK4(Aa, Bb, Dd, Kpk, Kpl)                                                              \
    do {                                                                                         \
        gemm_h16<EPI_NONE><<<dim3(2, 16, 4), blk256, GB_SMEM>>>(                                 \
            Aa, Bb, part, nullptr, nullptr, nullptr, T, QD, Kpk, (Kpk) / 4, Kpl);                \
        redk<<<T * QD / 1024, blk256>>>(part, Dd, T * QD / 4);                                   \
    } while (0)

    // -------- launch order: #5 (0-based) = grid-256 v gemm for ncu -s 5 ----
    transpose256<<<MD, MD>>>(mem_k, wkT);                                   // 0
    cvt_weights_all<<<CVTW_BLOCKS, blk256>>>(                               // 1
        attn_q, attn_k, attn_v, attn_o, attn_r, mem_v, mem_q, mem_r, wkT, mem_o,
        ff_in1, ff_in2, ff_out,
        aq2, ak2, av2, ao2, ar2, mv2, mq2, mr2, wk2, mo2, f12, f22, fo2);
    scale_norm_split<<<T, blk256>>>(xs, xn, xn2, sn1);                      // 2
    gemm_h16<EPI_NONE><<<dim3(2, 16, 4), blk256, GB_SMEM>>>(                // 3: q proj 2-term split-K
        xn2, aq2, part, nullptr, nullptr, nullptr, T, QD, 2 * XD, 2 * XD / 4, XD);
    redk<<<T * QD / 1024, blk256>>>(part, q_, T * QD / 4);                  // 4
    GB(EPI_NONE, 16, 16, xn2, av2, v_, nullptr, nullptr, nullptr, T, XD, XD, XD);     // 5: v 1-term, PROFILED
    cvtA_t<QD / 4><<<T * QD / 1024, blk256>>>(q_, q2);
    GBSK4(q2, ak2, k_, 3 * QD, QD);                                          // k: 3-term (tiny)
    GB(EPI_NONE, 16, 16, xn2, ar2, gate, nullptr, nullptr, nullptr, T, XD, XD, XD);   // gate: 1-term
    // attention core
    rope_all<<<T, 128>>>(q_, k_, qhi, klo, khi);
    attn_score<<<T / 8, blk256>>>(qhi, klo, khi, A_);
    attn_av<<<dim3(8, 4, 32), blk256>>>(A_, v_, y2);
    GB(EPI_GATE, 16, 16, y2, ao2, accb, gate, nullptr, nullptr, T, XD, XD, XD);       // ao: 1-term
    // mem projections + gate
    gemm_tn<EPI_SIGMOID><<<dim3(1, 16), blk256>>>(xn, mem_f, memF, nullptr, nullptr, nullptr, T, MN, XD);
    GBSK4(xn2, mv2, memV, 2 * XD, XD);                                       // mv: 2-term
    GBSK4(xn2, mq2, memQ, 2 * XD, XD);                                       // mq: 2-term
    GB(EPI_NONE, 16, 16, xn2, mr2, gate, nullptr, nullptr, nullptr, T, XD, XD, XD);   // gate: 1-term
    // scan (fp16 storage)
    mem_prep<<<MN, MD>>>(mem_beta, mem_dec, gam, bg);
    mem_scan<<<MN, MD>>>(memF, memV, gam, bg, mems);
    // readout
    cvtA_t<MD / 4><<<T * MD / 1024, blk256>>>(memQ, memQ2);
    GBSK4(memQ2, wk2, qk2, 3 * MD, MD);                                      // wk: 3-term (tiny)
    gemm_tn<EPI_NONE><<<dim3(1, 16), blk256>>>(memQ, mem_l, lq, nullptr, nullptr, nullptr, T, MN, MD);
    mem_readout2<<<T, blk256, MN * MD * 4>>>(mems, qk2, lq, memY);
    // x1 = (memY @ mem_o^T)*sigmoid(gate) + attn_out + xs
    cvtA_t<MD / 4><<<T * MD / 1024, blk256>>>(memY, memY2);
    GB(EPI_GATE_ADD2, 16, 16, memY2, mo2, x1, gate, accb, xs, T, XD, 2 * MD, MD);     // mo: 2-term
    // FF block: f1/f2 1-term with split-K x2; fo 1-term
    scale_norm_split<<<T, blk256>>>(x1, x2n, x2n2, sn2);
    gemm_h16<EPI_NONE><<<dim3(22, 16, 2), blk256, GB_SMEM>>>(
        x2n2, f12, partF, nullptr, nullptr, nullptr, T, FFD, XD, XD / 2, XD);
    redk2<<<T * FFD / 1024, blk256>>>(partF, h1, T * FFD / 4);
    gemm_h16<EPI_NONE><<<dim3(22, 16, 2), blk256, GB_SMEM>>>(
        x2n2, f22, partF, nullptr, nullptr, nullptr, T, FFD, XD, XD / 2, XD);
    red2_silu_split<<<T * FFD / 1024, blk256>>>(partF, h1, h22);
    GB(EPI_ADD, 16, 16, h22, fo2, out, nullptr, x1, nullptr, T, XD, FFD, FFD);        // fo: 1-term
#undef GB
#undef GBSK4
}